// round 3
// baseline (speedup 1.0000x reference)
#include <cuda_runtime.h>

#define M_TOK 200704
#define QKV_N 288

__device__ float g_qkv[(size_t)M_TOK * QKV_N];   // 231 MB scratch
__device__ float g_att[(size_t)M_TOK * 96];      //  77 MB scratch

typedef unsigned long long u64;

__device__ __forceinline__ void ffma2(u64& d, u64 a, u64 b) {
    asm("fma.rn.f32x2 %0,%1,%2,%0;" : "+l"(d) : "l"(a), "l"(b));
}
__device__ __forceinline__ float red2(u64 v) {
    float lo, hi; asm("mov.b64 {%0,%1},%2;" : "=f"(lo), "=f"(hi) : "l"(v));
    return lo + hi;
}

// ---------------------------------------------------------------------------
// GEMM: out[M,N] = A[M,96] @ Bw[96,N] + bias.  Tile 128(M) x 48(N), K=96.
// K-paired FFMA2: both operands loaded with LDS.64 from k-contiguous smem,
// zero pack instructions.  256 threads, thread tile 8 rows x 3 cols.
// smem: sA[128][96] (natural) + sBT[48][98] (B transposed, padded) = 66.4 KB
// ---------------------------------------------------------------------------
#define GEMM_SMEM ((128*96 + 48*98) * 4)

__global__ __launch_bounds__(256, 3) void gemm_kpair(
    const float* __restrict__ A, const float* __restrict__ Bw,
    const float* __restrict__ bias, float* __restrict__ out, int N)
{
    extern __shared__ float smem[];
    float* sA  = smem;              // [m][k], row stride 96 (16B aligned rows)
    float* sBT = smem + 128 * 96;   // [n][k], row stride 98 (bank-spread)
    const int m0 = blockIdx.x * 128;
    const int n0 = blockIdx.y * 48;
    const int tid = threadIdx.x;

    // A tile 128x96 coalesced float4 (natural layout: k contiguous)
    for (int i = tid; i < 128 * 24; i += 256) {
        int row = i / 24, k4 = (i % 24) * 4;
        *(float4*)(sA + row * 96 + k4) = *(const float4*)(A + (size_t)(m0 + row) * 96 + k4);
    }
    // B tile 96x48, transposed into sBT[n][k]
    for (int i = tid; i < 96 * 12; i += 256) {
        int k = i / 12, c4 = (i % 12) * 4;
        float4 v = *(const float4*)(Bw + (size_t)k * N + n0 + c4);
        sBT[(c4 + 0) * 98 + k] = v.x;
        sBT[(c4 + 1) * 98 + k] = v.y;
        sBT[(c4 + 2) * 98 + k] = v.z;
        sBT[(c4 + 3) * 98 + k] = v.w;
    }
    __syncthreads();

    const int tx = tid & 15;        // cols n0 + tx + 16c, c<3
    const int ty = tid >> 4;        // rows m0 + ty*8 + r, r<8
    u64 acc[8][3];
    #pragma unroll
    for (int r = 0; r < 8; r++)
        #pragma unroll
        for (int c = 0; c < 3; c++) acc[r][c] = 0ull;

    const float* aB = sA + ty * 8 * 96;
    const float* bB = sBT + tx * 98;

    #pragma unroll 4
    for (int kp = 0; kp < 48; kp++) {
        u64 a[8], b[3];
        #pragma unroll
        for (int r = 0; r < 8; r++) a[r] = *(const u64*)(aB + r * 96 + 2 * kp);
        #pragma unroll
        for (int c = 0; c < 3; c++) b[c] = *(const u64*)(bB + c * 16 * 98 + 2 * kp);
        #pragma unroll
        for (int r = 0; r < 8; r++)
            #pragma unroll
            for (int c = 0; c < 3; c++) ffma2(acc[r][c], a[r], b[c]);
    }

    #pragma unroll
    for (int c = 0; c < 3; c++) {
        int col = n0 + tx + 16 * c;
        float bb = bias[col];
        #pragma unroll
        for (int r = 0; r < 8; r++)
            out[(size_t)(m0 + ty * 8 + r) * N + col] = red2(acc[r][c]) + bb;
    }
}

// ---------------------------------------------------------------------------
// Attention: one block per window, 192 threads, all 3 heads.
// sim: d-paired FFMA2 (q,k d-contiguous, stride 36).  AV: j-paired FFMA2
// (att j-contiguous in ssim stride 50; V stored TRANSPOSED [d][j] stride 50,
// col 49 zero-padded -> 25 clean j-pairs).  Zero pack instructions.
// smem floats: sq 3*49*36 + sk 3*49*36 + svT 3*32*50 + ssim 3*49*50 + rel 507
// ---------------------------------------------------------------------------
#define ATTN_SMEM ((2*3*49*36 + 3*32*50 + 3*49*50 + 507) * 4)

__global__ __launch_bounds__(192) void attn3(const float* __restrict__ rel_pos)
{
    extern __shared__ float sm[];
    float* sq   = sm;                       // [h][49][36]
    float* sk   = sq + 3 * 49 * 36;
    float* svT  = sk + 3 * 49 * 36;         // [h][32][50]  (d-major, j contiguous)
    float* ssim = svT + 3 * 32 * 50;        // [h][49][50]
    float* srel = ssim + 3 * 49 * 50;       // 507
    __shared__ int sg[49];

    const int tid = threadIdx.x;
    const int win = blockIdx.x;             // ((b*8)+hi)*8+wi
    const int wi = win & 7, hi = (win >> 3) & 7, b = win >> 6;

    if (tid < 49) {
        int p = tid / 7, q = tid - (tid / 7) * 7;
        sg[tid] = (b * 56 + p * 8 + hi) * 56 + q * 8 + wi;
    }
    for (int i = tid; i < 507; i += 192) srel[i] = rel_pos[i];
    if (tid < 96) svT[tid * 50 + 49] = 0.f;   // zero pad col 49 of vT
    __syncthreads();

    const float scale = 0.17677669529663687f;  // 32^-0.5
    // Gather: per token 288 contiguous floats = [q96|k96|v96], each = 3h x 32d
    for (int i = tid; i < 49 * 72; i += 192) {
        int t = i / 72, r = i % 72;
        int which = r / 24, h = (r % 24) / 8, d4 = (r % 8) * 4;
        float4 v = *(const float4*)(g_qkv + (size_t)sg[t] * 288 + which * 96 + h * 32 + d4);
        if (which == 0) {
            float4 s = make_float4(v.x * scale, v.y * scale, v.z * scale, v.w * scale);
            *(float4*)(sq + (h * 49 + t) * 36 + d4) = s;
        } else if (which == 1) {
            *(float4*)(sk + (h * 49 + t) * 36 + d4) = v;
        } else {
            float* dst = svT + (h * 32 + d4) * 50 + t;
            dst[0] = v.x; dst[50] = v.y; dst[100] = v.z; dst[150] = v.w;
        }
    }
    __syncthreads();

    // sim = q k^T + bias : thread (h, 7x7 tile), d-paired FFMA2
    if (tid < 147) {
        int h = tid / 49, s = tid % 49, ti = s / 7, tj = s % 7;
        const float* qb = sq + (h * 49 + ti * 7) * 36;
        const float* kb = sk + (h * 49 + tj * 7) * 36;
        u64 acc[7][7];
        #pragma unroll
        for (int r = 0; r < 7; r++)
            #pragma unroll
            for (int c = 0; c < 7; c++) acc[r][c] = 0ull;
        #pragma unroll 4
        for (int dp = 0; dp < 16; dp++) {
            u64 qr[7], kc[7];
            #pragma unroll
            for (int r = 0; r < 7; r++) qr[r] = *(const u64*)(qb + r * 36 + 2 * dp);
            #pragma unroll
            for (int c = 0; c < 7; c++) kc[c] = *(const u64*)(kb + c * 36 + 2 * dp);
            #pragma unroll
            for (int r = 0; r < 7; r++)
                #pragma unroll
                for (int c = 0; c < 7; c++) ffma2(acc[r][c], qr[r], kc[c]);
        }
        const float* relh = srel + h * 169;
        float* simb = ssim + (h * 49 + ti * 7) * 50 + tj * 7;
        #pragma unroll
        for (int r = 0; r < 7; r++)
            #pragma unroll
            for (int c = 0; c < 7; c++)
                simb[r * 50 + c] = red2(acc[r][c]) + relh[(ti - tj + 6) * 13 + (r - c + 6)];
    }
    __syncthreads();

    // softmax: one row per thread; also zero pad col 49 for j-pairing
    if (tid < 147) {
        int h = tid / 49, i = tid % 49;
        float* row = ssim + (h * 49 + i) * 50;
        float mx = -1e30f;
        #pragma unroll
        for (int j = 0; j < 49; j++) mx = fmaxf(mx, row[j]);
        float sum = 0.f;
        #pragma unroll
        for (int j = 0; j < 49; j++) { float e = __expf(row[j] - mx); row[j] = e; sum += e; }
        float inv = 1.f / sum;
        #pragma unroll
        for (int j = 0; j < 49; j++) row[j] *= inv;
        row[49] = 0.f;
    }
    __syncthreads();

    // out = att @ v : thread (h, 7-row tile, 4-d chunk), j-paired FFMA2
    if (tid < 168) {
        int h = tid / 56, s = tid % 56, ti = s / 8, td = s % 8;
        const float* attb = ssim + (h * 49 + ti * 7) * 50;
        const float* vb   = svT + (h * 32 + td * 4) * 50;
        u64 acc[7][4];
        #pragma unroll
        for (int r = 0; r < 7; r++)
            #pragma unroll
            for (int c = 0; c < 4; c++) acc[r][c] = 0ull;
        #pragma unroll 5
        for (int jp = 0; jp < 25; jp++) {
            u64 av[7], vv[4];
            #pragma unroll
            for (int r = 0; r < 7; r++) av[r] = *(const u64*)(attb + r * 50 + 2 * jp);
            #pragma unroll
            for (int c = 0; c < 4; c++) vv[c] = *(const u64*)(vb + c * 50 + 2 * jp);
            #pragma unroll
            for (int r = 0; r < 7; r++)
                #pragma unroll
                for (int c = 0; c < 4; c++) ffma2(acc[r][c], av[r], vv[c]);
        }
        #pragma unroll
        for (int r = 0; r < 7; r++) {
            int i = ti * 7 + r;
            float4 o = make_float4(red2(acc[r][0]), red2(acc[r][1]),
                                   red2(acc[r][2]), red2(acc[r][3]));
            *(float4*)(g_att + (size_t)sg[i] * 96 + h * 32 + td * 4) = o;
        }
    }
}

extern "C" void kernel_launch(void* const* d_in, const int* in_sizes, int n_in,
                              void* d_out, int out_size)
{
    (void)in_sizes; (void)n_in; (void)out_size;
    const float* x     = (const float*)d_in[0];
    const float* w_qkv = (const float*)d_in[1];
    const float* b_qkv = (const float*)d_in[2];
    const float* rel   = (const float*)d_in[3];
    const float* w_out = (const float*)d_in[4];
    const float* b_out = (const float*)d_in[5];
    float* out = (float*)d_out;

    float *qkv_p = nullptr, *att_p = nullptr;
    cudaGetSymbolAddress((void**)&qkv_p, g_qkv);
    cudaGetSymbolAddress((void**)&att_p, g_att);

    cudaFuncSetAttribute(gemm_kpair, cudaFuncAttributeMaxDynamicSharedMemorySize, GEMM_SMEM);
    cudaFuncSetAttribute(attn3,      cudaFuncAttributeMaxDynamicSharedMemorySize, ATTN_SMEM);

    // 1) qkv = x @ w_qkv + b_qkv   (M=200704, N=288, K=96)
    gemm_kpair<<<dim3(M_TOK / 128, QKV_N / 48), 256, GEMM_SMEM>>>(x, w_qkv, b_qkv, qkv_p, QKV_N);

    // 2) windowed attention (all heads per block), scatter to spatial layout
    attn3<<<4096, 192, ATTN_SMEM>>>(rel);

    // 3) out = att @ w_out + b_out  (N=96)
    gemm_kpair<<<dim3(M_TOK / 128, 2), 256, GEMM_SMEM>>>(att_p, w_out, b_out, out, 96);
}

// round 6
// speedup vs baseline: 1.4526x; 1.4526x over previous
#include <cuda_runtime.h>
#include <cuda_bf16.h>
#include <cstdint>

#define M_TOK 200704
#define QKV_N 288

// ---------------- scratch (__device__ globals; no allocs allowed) ----------
__device__ float         g_qkv[(size_t)M_TOK * QKV_N];        // 231 MB
__device__ __nv_bfloat16 g_xh[(size_t)M_TOK * 96], g_xl[(size_t)M_TOK * 96];
__device__ __nv_bfloat16 g_ah[(size_t)M_TOK * 96], g_al[(size_t)M_TOK * 96];
__device__ __nv_bfloat16 g_wqh[QKV_N * 96], g_wql[QKV_N * 96]; // w_qkv^T [n][k]
__device__ __nv_bfloat16 g_woh[96 * 96],    g_wol[96 * 96];    // w_out^T [n][k]

typedef unsigned long long u64;

__device__ __forceinline__ void ffma2(u64& d, u64 a, u64 b) {
    asm("fma.rn.f32x2 %0,%1,%2,%0;" : "+l"(d) : "l"(a), "l"(b));
}
__device__ __forceinline__ float red2(u64 v) {
    float lo, hi; asm("mov.b64 {%0,%1},%2;" : "=f"(lo), "=f"(hi) : "l"(v));
    return lo + hi;
}
__device__ __forceinline__ void mma_bf16(float* c, const uint32_t* a, const uint32_t* b) {
    asm("mma.sync.aligned.m16n8k16.row.col.f32.bf16.bf16.f32 "
        "{%0,%1,%2,%3}, {%4,%5,%6,%7}, {%8,%9}, {%0,%1,%2,%3};"
        : "+f"(c[0]), "+f"(c[1]), "+f"(c[2]), "+f"(c[3])
        : "r"(a[0]), "r"(a[1]), "r"(a[2]), "r"(a[3]), "r"(b[0]), "r"(b[1]));
}

// ---------------- prep: split fp32 -> bf16 hi/lo ---------------------------
__global__ void split_x(const float* __restrict__ x) {
    size_t i4 = ((size_t)blockIdx.x * 256 + threadIdx.x) * 4;
    if (i4 >= (size_t)M_TOK * 96) return;
    float4 v = *(const float4*)(x + i4);
    float vv[4] = {v.x, v.y, v.z, v.w};
    __nv_bfloat16 h[4], l[4];
    #pragma unroll
    for (int e = 0; e < 4; e++) {
        h[e] = __float2bfloat16(vv[e]);
        l[e] = __float2bfloat16(vv[e] - __bfloat162float(h[e]));
    }
    *(__nv_bfloat162*)(g_xh + i4)     = __halves2bfloat162(h[0], h[1]);
    *(__nv_bfloat162*)(g_xh + i4 + 2) = __halves2bfloat162(h[2], h[3]);
    *(__nv_bfloat162*)(g_xl + i4)     = __halves2bfloat162(l[0], l[1]);
    *(__nv_bfloat162*)(g_xl + i4 + 2) = __halves2bfloat162(l[2], l[3]);
}

__global__ void split_w(const float* __restrict__ wqkv, const float* __restrict__ wout) {
    int idx = blockIdx.x * 256 + threadIdx.x;
    if (idx < QKV_N * 96) {                 // g_wqh[n][k] = wqkv[k][n]
        int n = idx / 96, k = idx % 96;
        float v = wqkv[k * QKV_N + n];
        __nv_bfloat16 h = __float2bfloat16(v);
        g_wqh[idx] = h;
        g_wql[idx] = __float2bfloat16(v - __bfloat162float(h));
    } else if (idx < QKV_N * 96 + 96 * 96) { // g_woh[n][k] = wout[k][n]
        int j = idx - QKV_N * 96;
        int n = j / 96, k = j % 96;
        float v = wout[k * 96 + n];
        __nv_bfloat16 h = __float2bfloat16(v);
        g_woh[j] = h;
        g_wol[j] = __float2bfloat16(v - __bfloat162float(h));
    }
}

// ---------------- HMMA GEMM ------------------------------------------------
// out[M,N] = (Ah+Al)@(Bh+Bl)^T + bias via Ah·Bh + Ah·Bl + Al·Bh.
// Block 128M x 96N, 8 warps (4Mx2N), warp 32x48, mma m16n8k16, K=96.
// smem [row][k] stride 104 bf16 -> conflict-free 32-bit fragment loads.
#define ASTR 104
#define S_AH 0
#define S_AL (128 * ASTR)
#define S_BH (2 * 128 * ASTR)
#define S_BL (2 * 128 * ASTR + 96 * ASTR)
#define GEMM_SMEM ((2 * 128 * ASTR + 2 * 96 * ASTR) * 2)   // 93184 B

__global__ __launch_bounds__(256) void gemm_hmma(
    const __nv_bfloat16* __restrict__ Ah, const __nv_bfloat16* __restrict__ Al,
    const __nv_bfloat16* __restrict__ Bh, const __nv_bfloat16* __restrict__ Bl,
    const float* __restrict__ bias, float* __restrict__ out, int N)
{
    extern __shared__ __nv_bfloat16 s[];
    const int tid = threadIdx.x, wid = tid >> 5, lane = tid & 31;
    const int g = lane >> 2, tg = lane & 3;
    const size_t m0 = (size_t)blockIdx.x * 128;
    const int n0 = blockIdx.y * 96;

    // A tiles 128x96 (hi & lo), coalesced uint4 (8 bf16)
    for (int i = tid; i < 128 * 12; i += 256) {
        int row = i / 12, k8 = (i % 12) * 8;
        *(uint4*)(s + S_AH + row * ASTR + k8) = *(const uint4*)(Ah + (m0 + row) * 96 + k8);
        *(uint4*)(s + S_AL + row * ASTR + k8) = *(const uint4*)(Al + (m0 + row) * 96 + k8);
    }
    // B tiles 96x96
    for (int i = tid; i < 96 * 12; i += 256) {
        int row = i / 12, k8 = (i % 12) * 8;
        *(uint4*)(s + S_BH + row * ASTR + k8) = *(const uint4*)(Bh + (size_t)(n0 + row) * 96 + k8);
        *(uint4*)(s + S_BL + row * ASTR + k8) = *(const uint4*)(Bl + (size_t)(n0 + row) * 96 + k8);
    }
    __syncthreads();

    const int wm = (wid >> 1) * 32, wn = (wid & 1) * 48;
    float acc[2][6][4];
    #pragma unroll
    for (int mt = 0; mt < 2; mt++)
        #pragma unroll
        for (int nt = 0; nt < 6; nt++)
            #pragma unroll
            for (int e = 0; e < 4; e++) acc[mt][nt][e] = 0.f;

    for (int k16 = 0; k16 < 96; k16 += 16) {
        const int cb = k16 + tg * 2;
        uint32_t ah[2][4], al[2][4], bh[6][2], bl[6][2];
        #pragma unroll
        for (int mt = 0; mt < 2; mt++) {
            int r = wm + mt * 16 + g;
            ah[mt][0] = *(const uint32_t*)(s + S_AH + r * ASTR + cb);
            ah[mt][1] = *(const uint32_t*)(s + S_AH + (r + 8) * ASTR + cb);
            ah[mt][2] = *(const uint32_t*)(s + S_AH + r * ASTR + cb + 8);
            ah[mt][3] = *(const uint32_t*)(s + S_AH + (r + 8) * ASTR + cb + 8);
            al[mt][0] = *(const uint32_t*)(s + S_AL + r * ASTR + cb);
            al[mt][1] = *(const uint32_t*)(s + S_AL + (r + 8) * ASTR + cb);
            al[mt][2] = *(const uint32_t*)(s + S_AL + r * ASTR + cb + 8);
            al[mt][3] = *(const uint32_t*)(s + S_AL + (r + 8) * ASTR + cb + 8);
        }
        #pragma unroll
        for (int nt = 0; nt < 6; nt++) {
            int rn = wn + nt * 8 + g;
            bh[nt][0] = *(const uint32_t*)(s + S_BH + rn * ASTR + cb);
            bh[nt][1] = *(const uint32_t*)(s + S_BH + rn * ASTR + cb + 8);
            bl[nt][0] = *(const uint32_t*)(s + S_BL + rn * ASTR + cb);
            bl[nt][1] = *(const uint32_t*)(s + S_BL + rn * ASTR + cb + 8);
        }
        #pragma unroll
        for (int mt = 0; mt < 2; mt++)
            #pragma unroll
            for (int nt = 0; nt < 6; nt++) {
                mma_bf16(acc[mt][nt], ah[mt], bh[nt]);   // hi*hi
                mma_bf16(acc[mt][nt], ah[mt], bl[nt]);   // hi*lo
                mma_bf16(acc[mt][nt], al[mt], bh[nt]);   // lo*hi
            }
    }

    // epilogue: direct float2 stores + bias
    #pragma unroll
    for (int nt = 0; nt < 6; nt++) {
        int col = n0 + wn + nt * 8 + tg * 2;
        float2 bb = *(const float2*)(bias + col);
        #pragma unroll
        for (int mt = 0; mt < 2; mt++) {
            size_t r0 = m0 + wm + mt * 16 + g;
            float2 v0 = make_float2(acc[mt][nt][0] + bb.x, acc[mt][nt][1] + bb.y);
            float2 v1 = make_float2(acc[mt][nt][2] + bb.x, acc[mt][nt][3] + bb.y);
            *(float2*)(out + r0 * N + col)       = v0;
            *(float2*)(out + (r0 + 8) * N + col) = v1;
        }
    }
}

// ---------------- attention (FFMA2 path; writes bf16 hi/lo att) ------------
#define ATTN_SMEM ((2*3*49*36 + 3*32*50 + 3*49*50 + 507) * 4)

__global__ __launch_bounds__(192) void attn3(const float* __restrict__ rel_pos)
{
    extern __shared__ float sm[];
    float* sq   = sm;                       // [h][49][36]
    float* sk   = sq + 3 * 49 * 36;
    float* svT  = sk + 3 * 49 * 36;         // [h][32][50]
    float* ssim = svT + 3 * 32 * 50;        // [h][49][50]
    float* srel = ssim + 3 * 49 * 50;
    __shared__ int sg[49];

    const int tid = threadIdx.x;
    const int win = blockIdx.x;
    const int wi = win & 7, hi = (win >> 3) & 7, b = win >> 6;

    if (tid < 49) {
        int p = tid / 7, q = tid - (tid / 7) * 7;
        sg[tid] = (b * 56 + p * 8 + hi) * 56 + q * 8 + wi;
    }
    for (int i = tid; i < 507; i += 192) srel[i] = rel_pos[i];
    if (tid < 96) svT[tid * 50 + 49] = 0.f;
    __syncthreads();

    const float scale = 0.17677669529663687f;  // 32^-0.5
    for (int i = tid; i < 49 * 72; i += 192) {
        int t = i / 72, r = i % 72;
        int which = r / 24, h = (r % 24) / 8, d4 = (r % 8) * 4;
        float4 v = *(const float4*)(g_qkv + (size_t)sg[t] * 288 + which * 96 + h * 32 + d4);
        if (which == 0) {
            float4 sc = make_float4(v.x * scale, v.y * scale, v.z * scale, v.w * scale);
            *(float4*)(sq + (h * 49 + t) * 36 + d4) = sc;
        } else if (which == 1) {
            *(float4*)(sk + (h * 49 + t) * 36 + d4) = v;
        } else {
            float* dst = svT + (h * 32 + d4) * 50 + t;
            dst[0] = v.x; dst[50] = v.y; dst[100] = v.z; dst[150] = v.w;
        }
    }
    __syncthreads();

    if (tid < 147) {
        int h = tid / 49, sdx = tid % 49, ti = sdx / 7, tj = sdx % 7;
        const float* qb = sq + (h * 49 + ti * 7) * 36;
        const float* kb = sk + (h * 49 + tj * 7) * 36;
        u64 acc[7][7];
        #pragma unroll
        for (int r = 0; r < 7; r++)
            #pragma unroll
            for (int c = 0; c < 7; c++) acc[r][c] = 0ull;
        #pragma unroll 4
        for (int dp = 0; dp < 16; dp++) {
            u64 qr[7], kc[7];
            #pragma unroll
            for (int r = 0; r < 7; r++) qr[r] = *(const u64*)(qb + r * 36 + 2 * dp);
            #pragma unroll
            for (int c = 0; c < 7; c++) kc[c] = *(const u64*)(kb + c * 36 + 2 * dp);
            #pragma unroll
            for (int r = 0; r < 7; r++)
                #pragma unroll
                for (int c = 0; c < 7; c++) ffma2(acc[r][c], qr[r], kc[c]);
        }
        const float* relh = srel + h * 169;
        float* simb = ssim + (h * 49 + ti * 7) * 50 + tj * 7;
        #pragma unroll
        for (int r = 0; r < 7; r++)
            #pragma unroll
            for (int c = 0; c < 7; c++)
                simb[r * 50 + c] = red2(acc[r][c]) + relh[(ti - tj + 6) * 13 + (r - c + 6)];
    }
    __syncthreads();

    if (tid < 147) {
        int h = tid / 49, i = tid % 49;
        float* row = ssim + (h * 49 + i) * 50;
        float mx = -1e30f;
        #pragma unroll
        for (int j = 0; j < 49; j++) mx = fmaxf(mx, row[j]);
        float sum = 0.f;
        #pragma unroll
        for (int j = 0; j < 49; j++) { float e = __expf(row[j] - mx); row[j] = e; sum += e; }
        float inv = 1.f / sum;
        #pragma unroll
        for (int j = 0; j < 49; j++) row[j] *= inv;
        row[49] = 0.f;
    }
    __syncthreads();

    if (tid < 168) {
        int h = tid / 56, sdx = tid % 56, ti = sdx / 8, td = sdx % 8;
        const float* attb = ssim + (h * 49 + ti * 7) * 50;
        const float* vb   = svT + (h * 32 + td * 4) * 50;
        u64 acc[7][4];
        #pragma unroll
        for (int r = 0; r < 7; r++)
            #pragma unroll
            for (int c = 0; c < 4; c++) acc[r][c] = 0ull;
        #pragma unroll 5
        for (int jp = 0; jp < 25; jp++) {
            u64 av[7], vv[4];
            #pragma unroll
            for (int r = 0; r < 7; r++) av[r] = *(const u64*)(attb + r * 50 + 2 * jp);
            #pragma unroll
            for (int c = 0; c < 4; c++) vv[c] = *(const u64*)(vb + c * 50 + 2 * jp);
            #pragma unroll
            for (int r = 0; r < 7; r++)
                #pragma unroll
                for (int c = 0; c < 4; c++) ffma2(acc[r][c], av[r], vv[c]);
        }
        #pragma unroll
        for (int r = 0; r < 7; r++) {
            int i = ti * 7 + r;
            size_t base = (size_t)sg[i] * 96 + h * 32 + td * 4;
            float v[4] = {red2(acc[r][0]), red2(acc[r][1]), red2(acc[r][2]), red2(acc[r][3])};
            __nv_bfloat16 hh[4], ll[4];
            #pragma unroll
            for (int e = 0; e < 4; e++) {
                hh[e] = __float2bfloat16(v[e]);
                ll[e] = __float2bfloat16(v[e] - __bfloat162float(hh[e]));
            }
            *(__nv_bfloat162*)(g_ah + base)     = __halves2bfloat162(hh[0], hh[1]);
            *(__nv_bfloat162*)(g_ah + base + 2) = __halves2bfloat162(hh[2], hh[3]);
            *(__nv_bfloat162*)(g_al + base)     = __halves2bfloat162(ll[0], ll[1]);
            *(__nv_bfloat162*)(g_al + base + 2) = __halves2bfloat162(ll[2], ll[3]);
        }
    }
}

// ---------------- launch ----------------------------------------------------
extern "C" void kernel_launch(void* const* d_in, const int* in_sizes, int n_in,
                              void* d_out, int out_size)
{
    (void)in_sizes; (void)n_in; (void)out_size;
    const float* x     = (const float*)d_in[0];
    const float* w_qkv = (const float*)d_in[1];
    const float* b_qkv = (const float*)d_in[2];
    const float* rel   = (const float*)d_in[3];
    const float* w_out = (const float*)d_in[4];
    const float* b_out = (const float*)d_in[5];
    float* out = (float*)d_out;

    float* qkv_p = nullptr;
    __nv_bfloat16 *xh, *xl, *ah, *al, *wqh, *wql, *woh, *wol;
    cudaGetSymbolAddress((void**)&qkv_p, g_qkv);
    cudaGetSymbolAddress((void**)&xh, g_xh);   cudaGetSymbolAddress((void**)&xl, g_xl);
    cudaGetSymbolAddress((void**)&ah, g_ah);   cudaGetSymbolAddress((void**)&al, g_al);
    cudaGetSymbolAddress((void**)&wqh, g_wqh); cudaGetSymbolAddress((void**)&wql, g_wql);
    cudaGetSymbolAddress((void**)&woh, g_woh); cudaGetSymbolAddress((void**)&wol, g_wol);

    cudaFuncSetAttribute(gemm_hmma, cudaFuncAttributeMaxDynamicSharedMemorySize, GEMM_SMEM);
    cudaFuncSetAttribute(attn3,     cudaFuncAttributeMaxDynamicSharedMemorySize, ATTN_SMEM);

    // 0) split inputs/weights into bf16 hi/lo (weights transposed to [n][k])
    split_x<<<(int)(((size_t)M_TOK * 96 / 4 + 255) / 256), 256>>>(x);
    split_w<<<((QKV_N + 96) * 96 + 255) / 256, 256>>>(w_qkv, w_out);

    // 1) qkv = x @ w_qkv + b_qkv   (HMMA, 3-product bf16 split)
    gemm_hmma<<<dim3(M_TOK / 128, 3), 256, GEMM_SMEM>>>(xh, xl, wqh, wql, b_qkv, qkv_p, QKV_N);

    // 2) windowed attention; writes bf16 hi/lo att directly
    attn3<<<4096, 192, ATTN_SMEM>>>(rel);

    // 3) out = att @ w_out + b_out
    gemm_hmma<<<dim3(M_TOK / 128, 1), 256, GEMM_SMEM>>>(ah, al, woh, wol, b_out, out, 96);
}

// round 7
// speedup vs baseline: 1.5721x; 1.0823x over previous
#include <cuda_runtime.h>
#include <cuda_bf16.h>
#include <cstdint>

#define M_TOK 200704
#define QKV_N 288

// ---------------- scratch (__device__ globals; no allocs allowed) ----------
__device__ float         g_qkv[(size_t)M_TOK * QKV_N];        // 231 MB
__device__ __nv_bfloat16 g_xh[(size_t)M_TOK * 96], g_xl[(size_t)M_TOK * 96];
__device__ __nv_bfloat16 g_ah[(size_t)M_TOK * 96], g_al[(size_t)M_TOK * 96];
__device__ __nv_bfloat16 g_wqh[QKV_N * 96], g_wql[QKV_N * 96]; // w_qkv^T [n][k]
__device__ __nv_bfloat16 g_woh[96 * 96],    g_wol[96 * 96];    // w_out^T [n][k]

__device__ __forceinline__ void mma_bf16(float* c, const uint32_t* a, const uint32_t* b) {
    asm("mma.sync.aligned.m16n8k16.row.col.f32.bf16.bf16.f32 "
        "{%0,%1,%2,%3}, {%4,%5,%6,%7}, {%8,%9}, {%0,%1,%2,%3};"
        : "+f"(c[0]), "+f"(c[1]), "+f"(c[2]), "+f"(c[3])
        : "r"(a[0]), "r"(a[1]), "r"(a[2]), "r"(a[3]), "r"(b[0]), "r"(b[1]));
}
// pack two fp32 -> bf16x2 (lo = first element, hi = second)
__device__ __forceinline__ uint32_t pack_bf16x2(float lo, float hi) {
    uint32_t r;
    asm("cvt.rn.bf16x2.f32 %0, %1, %2;" : "=r"(r) : "f"(hi), "f"(lo));
    return r;
}
__device__ __forceinline__ float bf16rt(float x) {   // round-trip through bf16
    return __bfloat162float(__float2bfloat16(x));
}

// ---------------- prep: split fp32 -> bf16 hi/lo ---------------------------
__global__ void split_x(const float* __restrict__ x) {
    size_t i4 = ((size_t)blockIdx.x * 256 + threadIdx.x) * 4;
    if (i4 >= (size_t)M_TOK * 96) return;
    float4 v = *(const float4*)(x + i4);
    float vv[4] = {v.x, v.y, v.z, v.w};
    float rt[4];
    #pragma unroll
    for (int e = 0; e < 4; e++) rt[e] = bf16rt(vv[e]);
    *(uint32_t*)(g_xh + i4)     = pack_bf16x2(vv[0], vv[1]);
    *(uint32_t*)(g_xh + i4 + 2) = pack_bf16x2(vv[2], vv[3]);
    *(uint32_t*)(g_xl + i4)     = pack_bf16x2(vv[0] - rt[0], vv[1] - rt[1]);
    *(uint32_t*)(g_xl + i4 + 2) = pack_bf16x2(vv[2] - rt[2], vv[3] - rt[3]);
}

__global__ void split_w(const float* __restrict__ wqkv, const float* __restrict__ wout) {
    int idx = blockIdx.x * 256 + threadIdx.x;
    if (idx < QKV_N * 96) {                 // g_wqh[n][k] = wqkv[k][n]
        int n = idx / 96, k = idx % 96;
        float v = wqkv[k * QKV_N + n];
        __nv_bfloat16 h = __float2bfloat16(v);
        g_wqh[idx] = h;
        g_wql[idx] = __float2bfloat16(v - __bfloat162float(h));
    } else if (idx < QKV_N * 96 + 96 * 96) { // g_woh[n][k] = wout[k][n]
        int j = idx - QKV_N * 96;
        int n = j / 96, k = j % 96;
        float v = wout[k * 96 + n];
        __nv_bfloat16 h = __float2bfloat16(v);
        g_woh[j] = h;
        g_wol[j] = __float2bfloat16(v - __bfloat162float(h));
    }
}

// ---------------- HMMA GEMM (unchanged from R6) ----------------------------
#define ASTR 104
#define S_AH 0
#define S_AL (128 * ASTR)
#define S_BH (2 * 128 * ASTR)
#define S_BL (2 * 128 * ASTR + 96 * ASTR)
#define GEMM_SMEM ((2 * 128 * ASTR + 2 * 96 * ASTR) * 2)   // 93184 B

__global__ __launch_bounds__(256) void gemm_hmma(
    const __nv_bfloat16* __restrict__ Ah, const __nv_bfloat16* __restrict__ Al,
    const __nv_bfloat16* __restrict__ Bh, const __nv_bfloat16* __restrict__ Bl,
    const float* __restrict__ bias, float* __restrict__ out, int N)
{
    extern __shared__ __nv_bfloat16 s[];
    const int tid = threadIdx.x, wid = tid >> 5, lane = tid & 31;
    const int g = lane >> 2, tg = lane & 3;
    const size_t m0 = (size_t)blockIdx.x * 128;
    const int n0 = blockIdx.y * 96;

    for (int i = tid; i < 128 * 12; i += 256) {
        int row = i / 12, k8 = (i % 12) * 8;
        *(uint4*)(s + S_AH + row * ASTR + k8) = *(const uint4*)(Ah + (m0 + row) * 96 + k8);
        *(uint4*)(s + S_AL + row * ASTR + k8) = *(const uint4*)(Al + (m0 + row) * 96 + k8);
    }
    for (int i = tid; i < 96 * 12; i += 256) {
        int row = i / 12, k8 = (i % 12) * 8;
        *(uint4*)(s + S_BH + row * ASTR + k8) = *(const uint4*)(Bh + (size_t)(n0 + row) * 96 + k8);
        *(uint4*)(s + S_BL + row * ASTR + k8) = *(const uint4*)(Bl + (size_t)(n0 + row) * 96 + k8);
    }
    __syncthreads();

    const int wm = (wid >> 1) * 32, wn = (wid & 1) * 48;
    float acc[2][6][4];
    #pragma unroll
    for (int mt = 0; mt < 2; mt++)
        #pragma unroll
        for (int nt = 0; nt < 6; nt++)
            #pragma unroll
            for (int e = 0; e < 4; e++) acc[mt][nt][e] = 0.f;

    for (int k16 = 0; k16 < 96; k16 += 16) {
        const int cb = k16 + tg * 2;
        uint32_t ah[2][4], al[2][4], bh[6][2], bl[6][2];
        #pragma unroll
        for (int mt = 0; mt < 2; mt++) {
            int r = wm + mt * 16 + g;
            ah[mt][0] = *(const uint32_t*)(s + S_AH + r * ASTR + cb);
            ah[mt][1] = *(const uint32_t*)(s + S_AH + (r + 8) * ASTR + cb);
            ah[mt][2] = *(const uint32_t*)(s + S_AH + r * ASTR + cb + 8);
            ah[mt][3] = *(const uint32_t*)(s + S_AH + (r + 8) * ASTR + cb + 8);
            al[mt][0] = *(const uint32_t*)(s + S_AL + r * ASTR + cb);
            al[mt][1] = *(const uint32_t*)(s + S_AL + (r + 8) * ASTR + cb);
            al[mt][2] = *(const uint32_t*)(s + S_AL + r * ASTR + cb + 8);
            al[mt][3] = *(const uint32_t*)(s + S_AL + (r + 8) * ASTR + cb + 8);
        }
        #pragma unroll
        for (int nt = 0; nt < 6; nt++) {
            int rn = wn + nt * 8 + g;
            bh[nt][0] = *(const uint32_t*)(s + S_BH + rn * ASTR + cb);
            bh[nt][1] = *(const uint32_t*)(s + S_BH + rn * ASTR + cb + 8);
            bl[nt][0] = *(const uint32_t*)(s + S_BL + rn * ASTR + cb);
            bl[nt][1] = *(const uint32_t*)(s + S_BL + rn * ASTR + cb + 8);
        }
        #pragma unroll
        for (int mt = 0; mt < 2; mt++)
            #pragma unroll
            for (int nt = 0; nt < 6; nt++) {
                mma_bf16(acc[mt][nt], ah[mt], bh[nt]);
                mma_bf16(acc[mt][nt], ah[mt], bl[nt]);
                mma_bf16(acc[mt][nt], al[mt], bh[nt]);
            }
    }

    #pragma unroll
    for (int nt = 0; nt < 6; nt++) {
        int col = n0 + wn + nt * 8 + tg * 2;
        float2 bb = *(const float2*)(bias + col);
        #pragma unroll
        for (int mt = 0; mt < 2; mt++) {
            size_t r0 = m0 + wm + mt * 16 + g;
            *(float2*)(out + r0 * N + col)       = make_float2(acc[mt][nt][0] + bb.x, acc[mt][nt][1] + bb.y);
            *(float2*)(out + (r0 + 8) * N + col) = make_float2(acc[mt][nt][2] + bb.x, acc[mt][nt][3] + bb.y);
        }
    }
}

// ---------------- HMMA attention -------------------------------------------
// One block per window, 128 threads = 4 warps, warp = one m-tile (rows
// {0,16,32,33}+0..15, overlap rows computed twice -> identical stores).
// n-tiles {0,8,...,40,41} cover j=0..48 exactly (overlap cols deduped in
// softmax sum).  sim/att never leave registers: softmaxed QK accumulators are
// repacked in-register as bf16 hi/lo A-fragments for AV (k-steps {0,16,32};
// j=48 via shfl + scalar FMA).  V stored transposed [d][j] as B operand.
#define QSTR 40
#define VSTR 56
#define SQH 0
#define SQL (3*49*QSTR)
#define SKH (2*3*49*QSTR)
#define SKL (3*3*49*QSTR)
#define SVH (4*3*49*QSTR)
#define SVL (4*3*49*QSTR + 3*32*VSTR)
#define SREL_OFF (4*3*49*QSTR + 2*3*32*VSTR)            // in bf16 units (even)
#define ATTN_SMEM (SREL_OFF*2 + 507*4)                  // 70572 B

__global__ __launch_bounds__(128, 3) void attn_mma(const float* __restrict__ rel_pos)
{
    extern __shared__ __nv_bfloat16 sb[];
    __nv_bfloat16* sqh = sb + SQH;
    __nv_bfloat16* sql = sb + SQL;
    __nv_bfloat16* skh = sb + SKH;
    __nv_bfloat16* skl = sb + SKL;
    __nv_bfloat16* vth = sb + SVH;
    __nv_bfloat16* vtl = sb + SVL;
    float* srel = (float*)(sb + SREL_OFF);
    __shared__ int sg[49];

    const int tid = threadIdx.x;
    const int win = blockIdx.x;                 // ((b*8)+hi)*8+wi
    const int wi = win & 7, hi2 = (win >> 3) & 7, bb = win >> 6;

    if (tid < 49) {
        int p = tid / 7, q = tid - (tid / 7) * 7;
        sg[tid] = (bb * 56 + p * 8 + hi2) * 56 + q * 8 + wi;
    }
    for (int i = tid; i < 507; i += 128) srel[i] = rel_pos[i];
    __syncthreads();

    const float scale = 0.17677669529663687f;   // 32^-0.5
    // gather: 49 tokens x [q96|k96|v96]; q,k -> [h][t][d] hi/lo; v -> [h][d][t]
    for (int i = tid; i < 49 * 72; i += 128) {
        int t = i / 72, r = i % 72;
        int which = r / 24, h = (r % 24) / 8, d4 = (r % 8) * 4;
        float4 v = *(const float4*)(g_qkv + (size_t)sg[t] * 288 + which * 96 + h * 32 + d4);
        if (which == 0) { v.x *= scale; v.y *= scale; v.z *= scale; v.w *= scale; }
        if (which < 2) {
            float rx = bf16rt(v.x), ry = bf16rt(v.y), rz = bf16rt(v.z), rw = bf16rt(v.w);
            __nv_bfloat16* dh = (which ? skh : sqh) + (h * 49 + t) * QSTR + d4;
            __nv_bfloat16* dl = (which ? skl : sql) + (h * 49 + t) * QSTR + d4;
            *(uint32_t*)dh       = pack_bf16x2(v.x, v.y);
            *(uint32_t*)(dh + 2) = pack_bf16x2(v.z, v.w);
            *(uint32_t*)dl       = pack_bf16x2(v.x - rx, v.y - ry);
            *(uint32_t*)(dl + 2) = pack_bf16x2(v.z - rz, v.w - rw);
        } else {
            float vv[4] = {v.x, v.y, v.z, v.w};
            #pragma unroll
            for (int e = 0; e < 4; e++) {
                float rt = bf16rt(vv[e]);
                vth[(h * 32 + d4 + e) * VSTR + t] = __float2bfloat16(vv[e]);
                vtl[(h * 32 + d4 + e) * VSTR + t] = __float2bfloat16(vv[e] - rt);
            }
        }
    }
    __syncthreads();

    const int lane = tid & 31, warp = tid >> 5;
    const int g = lane >> 2, tg = lane & 3;
    const int m0 = (warp == 3) ? 33 : warp * 16;
    const int r0 = m0 + g, r1 = m0 + 8 + g;
    const int n0tab[7] = {0, 8, 16, 24, 32, 40, 41};

    // rel-pos indices (head-invariant): 7 n-tiles x {(r0,j0),(r0,j1),(r1,j0),(r1,j1)}
    int bidx[7][4];
    {
        int pi0 = r0 / 7, qi0 = r0 % 7, pi1 = r1 / 7, qi1 = r1 % 7;
        #pragma unroll
        for (int nt = 0; nt < 7; nt++) {
            int j0 = n0tab[nt] + 2 * tg, j1 = j0 + 1;
            int pj0 = j0 / 7, qj0 = j0 % 7, pj1 = j1 / 7, qj1 = j1 % 7;
            bidx[nt][0] = (pi0 - pj0 + 6) * 13 + (qi0 - qj0 + 6);
            bidx[nt][1] = (pi0 - pj1 + 6) * 13 + (qi0 - qj1 + 6);
            bidx[nt][2] = (pi1 - pj0 + 6) * 13 + (qi1 - qj0 + 6);
            bidx[nt][3] = (pi1 - pj1 + 6) * 13 + (qi1 - qj1 + 6);
        }
    }

    const int tok0 = sg[r0], tok1 = sg[r1];

    for (int h = 0; h < 3; h++) {
        const __nv_bfloat16* qh = sqh + h * 49 * QSTR;
        const __nv_bfloat16* ql = sql + h * 49 * QSTR;
        const __nv_bfloat16* kh = skh + h * 49 * QSTR;
        const __nv_bfloat16* kl = skl + h * 49 * QSTR;

        // ---- sim = q k^T (3-product bf16 split) ----
        float acc[7][4];
        #pragma unroll
        for (int nt = 0; nt < 7; nt++)
            #pragma unroll
            for (int e = 0; e < 4; e++) acc[nt][e] = 0.f;

        #pragma unroll
        for (int ks = 0; ks < 2; ks++) {
            const int kb = ks * 16 + 2 * tg;
            uint32_t aH[4], aL[4];
            aH[0] = *(const uint32_t*)(qh + r0 * QSTR + kb);
            aH[1] = *(const uint32_t*)(qh + r1 * QSTR + kb);
            aH[2] = *(const uint32_t*)(qh + r0 * QSTR + kb + 8);
            aH[3] = *(const uint32_t*)(qh + r1 * QSTR + kb + 8);
            aL[0] = *(const uint32_t*)(ql + r0 * QSTR + kb);
            aL[1] = *(const uint32_t*)(ql + r1 * QSTR + kb);
            aL[2] = *(const uint32_t*)(ql + r0 * QSTR + kb + 8);
            aL[3] = *(const uint32_t*)(ql + r1 * QSTR + kb + 8);
            #pragma unroll
            for (int nt = 0; nt < 7; nt++) {
                int rn = n0tab[nt] + g;
                uint32_t bH[2] = {*(const uint32_t*)(kh + rn * QSTR + kb),
                                  *(const uint32_t*)(kh + rn * QSTR + kb + 8)};
                uint32_t bL[2] = {*(const uint32_t*)(kl + rn * QSTR + kb),
                                  *(const uint32_t*)(kl + rn * QSTR + kb + 8)};
                mma_bf16(acc[nt], aH, bH);
                mma_bf16(acc[nt], aH, bL);
                mma_bf16(acc[nt], aL, bH);
            }
        }

        // ---- + rel-pos bias ----
        const float* relh = srel + h * 169;
        #pragma unroll
        for (int nt = 0; nt < 7; nt++)
            #pragma unroll
            for (int e = 0; e < 4; e++) acc[nt][e] += relh[bidx[nt][e]];

        // ---- softmax (rows r0: c0/c1, r1: c2/c3); dup cols excluded from sum ----
        float mx0 = -1e30f, mx1 = -1e30f;
        #pragma unroll
        for (int nt = 0; nt < 7; nt++) {
            mx0 = fmaxf(mx0, fmaxf(acc[nt][0], acc[nt][1]));
            mx1 = fmaxf(mx1, fmaxf(acc[nt][2], acc[nt][3]));
        }
        mx0 = fmaxf(mx0, __shfl_xor_sync(0xffffffffu, mx0, 1));
        mx0 = fmaxf(mx0, __shfl_xor_sync(0xffffffffu, mx0, 2));
        mx1 = fmaxf(mx1, __shfl_xor_sync(0xffffffffu, mx1, 1));
        mx1 = fmaxf(mx1, __shfl_xor_sync(0xffffffffu, mx1, 2));
        float s0 = 0.f, s1 = 0.f;
        #pragma unroll
        for (int nt = 0; nt < 6; nt++) {          // tiles 0..5 = cols 0..47, unique
            acc[nt][0] = __expf(acc[nt][0] - mx0); s0 += acc[nt][0];
            acc[nt][1] = __expf(acc[nt][1] - mx0); s0 += acc[nt][1];
            acc[nt][2] = __expf(acc[nt][2] - mx1); s1 += acc[nt][2];
            acc[nt][3] = __expf(acc[nt][3] - mx1); s1 += acc[nt][3];
        }
        acc[6][0] = __expf(acc[6][0] - mx0);      // overlap tile: only col 48 unique
        acc[6][1] = __expf(acc[6][1] - mx0);
        acc[6][2] = __expf(acc[6][2] - mx1);
        acc[6][3] = __expf(acc[6][3] - mx1);
        if (tg == 3) { s0 += acc[6][1]; s1 += acc[6][3]; }   // col 48
        s0 += __shfl_xor_sync(0xffffffffu, s0, 1);
        s0 += __shfl_xor_sync(0xffffffffu, s0, 2);
        s1 += __shfl_xor_sync(0xffffffffu, s1, 1);
        s1 += __shfl_xor_sync(0xffffffffu, s1, 2);
        float inv0 = 1.f / s0, inv1 = 1.f / s1;
        #pragma unroll
        for (int nt = 0; nt < 7; nt++) {
            acc[nt][0] *= inv0; acc[nt][1] *= inv0;
            acc[nt][2] *= inv1; acc[nt][3] *= inv1;
        }

        // ---- out = att @ v : att repacked in-register as A frags ----
        float accv[4][4];
        #pragma unroll
        for (int dn = 0; dn < 4; dn++)
            #pragma unroll
            for (int e = 0; e < 4; e++) accv[dn][e] = 0.f;

        #pragma unroll
        for (int ks = 0; ks < 3; ks++) {          // j 0..47 via tiles (2ks, 2ks+1)
            uint32_t aH[4], aL[4];
            #pragma unroll
            for (int half = 0; half < 2; half++) {
                float* t = acc[2 * ks + half];
                float h0 = bf16rt(t[0]), h1 = bf16rt(t[1]);
                float h2 = bf16rt(t[2]), h3 = bf16rt(t[3]);
                aH[half ? 2 : 0] = pack_bf16x2(t[0], t[1]);
                aH[half ? 3 : 1] = pack_bf16x2(t[2], t[3]);
                aL[half ? 2 : 0] = pack_bf16x2(t[0] - h0, t[1] - h1);
                aL[half ? 3 : 1] = pack_bf16x2(t[2] - h2, t[3] - h3);
            }
            #pragma unroll
            for (int dn = 0; dn < 4; dn++) {
                const __nv_bfloat16* bh = vth + (h * 32 + dn * 8 + g) * VSTR + ks * 16 + 2 * tg;
                const __nv_bfloat16* bl = vtl + (h * 32 + dn * 8 + g) * VSTR + ks * 16 + 2 * tg;
                uint32_t bH[2] = {*(const uint32_t*)bh, *(const uint32_t*)(bh + 8)};
                uint32_t bL[2] = {*(const uint32_t*)bl, *(const uint32_t*)(bl + 8)};
                mma_bf16(accv[dn], aH, bH);
                mma_bf16(accv[dn], aH, bL);
                mma_bf16(accv[dn], aL, bH);
            }
        }
        // j = 48: att col 48 lives in tile6 c1/c3 of tg==3 lane; fp32 FMA
        float a48a = __shfl_sync(0xffffffffu, acc[6][1], lane | 3);
        float a48b = __shfl_sync(0xffffffffu, acc[6][3], lane | 3);
        #pragma unroll
        for (int dn = 0; dn < 4; dn++) {
            int d0 = dn * 8 + 2 * tg;
            float v0 = __bfloat162float(vth[(h * 32 + d0) * VSTR + 48])
                     + __bfloat162float(vtl[(h * 32 + d0) * VSTR + 48]);
            float v1 = __bfloat162float(vth[(h * 32 + d0 + 1) * VSTR + 48])
                     + __bfloat162float(vtl[(h * 32 + d0 + 1) * VSTR + 48]);
            accv[dn][0] += a48a * v0; accv[dn][1] += a48a * v1;
            accv[dn][2] += a48b * v0; accv[dn][3] += a48b * v1;
        }

        // ---- store bf16 hi/lo att-output (overlap rows: identical dup stores) ----
        #pragma unroll
        for (int dn = 0; dn < 4; dn++) {
            int d0 = dn * 8 + 2 * tg;
            size_t o0 = (size_t)tok0 * 96 + h * 32 + d0;
            size_t o1 = (size_t)tok1 * 96 + h * 32 + d0;
            float e0 = bf16rt(accv[dn][0]), e1 = bf16rt(accv[dn][1]);
            float e2 = bf16rt(accv[dn][2]), e3 = bf16rt(accv[dn][3]);
            *(uint32_t*)(g_ah + o0) = pack_bf16x2(accv[dn][0], accv[dn][1]);
            *(uint32_t*)(g_al + o0) = pack_bf16x2(accv[dn][0] - e0, accv[dn][1] - e1);
            *(uint32_t*)(g_ah + o1) = pack_bf16x2(accv[dn][2], accv[dn][3]);
            *(uint32_t*)(g_al + o1) = pack_bf16x2(accv[dn][2] - e2, accv[dn][3] - e3);
        }
    }
}

// ---------------- launch ----------------------------------------------------
extern "C" void kernel_launch(void* const* d_in, const int* in_sizes, int n_in,
                              void* d_out, int out_size)
{
    (void)in_sizes; (void)n_in; (void)out_size;
    const float* x     = (const float*)d_in[0];
    const float* w_qkv = (const float*)d_in[1];
    const float* b_qkv = (const float*)d_in[2];
    const float* rel   = (const float*)d_in[3];
    const float* w_out = (const float*)d_in[4];
    const float* b_out = (const float*)d_in[5];
    float* out = (float*)d_out;

    float* qkv_p = nullptr;
    __nv_bfloat16 *xh, *xl, *ah, *al, *wqh, *wql, *woh, *wol;
    cudaGetSymbolAddress((void**)&qkv_p, g_qkv);
    cudaGetSymbolAddress((void**)&xh, g_xh);   cudaGetSymbolAddress((void**)&xl, g_xl);
    cudaGetSymbolAddress((void**)&ah, g_ah);   cudaGetSymbolAddress((void**)&al, g_al);
    cudaGetSymbolAddress((void**)&wqh, g_wqh); cudaGetSymbolAddress((void**)&wql, g_wql);
    cudaGetSymbolAddress((void**)&woh, g_woh); cudaGetSymbolAddress((void**)&wol, g_wol);

    cudaFuncSetAttribute(gemm_hmma, cudaFuncAttributeMaxDynamicSharedMemorySize, GEMM_SMEM);
    cudaFuncSetAttribute(attn_mma,  cudaFuncAttributeMaxDynamicSharedMemorySize, ATTN_SMEM);

    // 0) split inputs/weights into bf16 hi/lo (weights transposed to [n][k])
    split_x<<<(int)(((size_t)M_TOK * 96 / 4 + 255) / 256), 256>>>(x);
    split_w<<<((QKV_N + 96) * 96 + 255) / 256, 256>>>(w_qkv, w_out);

    // 1) qkv = x @ w_qkv + b_qkv   (HMMA, 3-product bf16 split)
    gemm_hmma<<<dim3(M_TOK / 128, 3), 256, GEMM_SMEM>>>(xh, xl, wqh, wql, b_qkv, qkv_p, QKV_N);

    // 2) windowed attention (HMMA, register-resident sim/att)
    attn_mma<<<4096, 128, ATTN_SMEM>>>(rel);

    // 3) out = att @ w_out + b_out
    gemm_hmma<<<dim3(M_TOK / 128, 1), 256, GEMM_SMEM>>>(ah, al, woh, wol, b_out, out, 96);
}

// round 10
// speedup vs baseline: 1.6823x; 1.0701x over previous
#include <cuda_runtime.h>
#include <cuda_bf16.h>
#include <cstdint>

#define M_TOK 200704
#define QKV_N 288

// ---------------- scratch (__device__ globals; no allocs allowed) ----------
// qkv in WINDOW-MAJOR layout: row = win*49 + t, 288 cols = [q96|k96|v96]
__device__ __nv_bfloat16 g_qh[(size_t)M_TOK * 288], g_ql[(size_t)M_TOK * 288];
__device__ __nv_bfloat16 g_ah[(size_t)M_TOK * 96],  g_al[(size_t)M_TOK * 96];
__device__ __nv_bfloat16 g_wqh[QKV_N * 96], g_wql[QKV_N * 96]; // w_qkv^T [n][k]
__device__ __nv_bfloat16 g_woh[96 * 96],    g_wol[96 * 96];    // w_out^T [n][k]

__device__ __forceinline__ void mma_bf16(float* c, const uint32_t* a, const uint32_t* b) {
    asm("mma.sync.aligned.m16n8k16.row.col.f32.bf16.bf16.f32 "
        "{%0,%1,%2,%3}, {%4,%5,%6,%7}, {%8,%9}, {%0,%1,%2,%3};"
        : "+f"(c[0]), "+f"(c[1]), "+f"(c[2]), "+f"(c[3])
        : "r"(a[0]), "r"(a[1]), "r"(a[2]), "r"(a[3]), "r"(b[0]), "r"(b[1]));
}
__device__ __forceinline__ uint32_t pack_bf16x2(float lo, float hi) {
    uint32_t r;
    asm("cvt.rn.bf16x2.f32 %0, %1, %2;" : "=r"(r) : "f"(hi), "f"(lo));
    return r;
}
__device__ __forceinline__ float bf16rt(float x) {
    return __bfloat162float(__float2bfloat16(x));
}
// spatial row m -> window-major row
__device__ __forceinline__ size_t winmap(size_t m) {
    int b = (int)(m / 3136), rem = (int)(m % 3136);
    int H = rem / 56, W = rem % 56;
    return ((size_t)(b * 64 + (H & 7) * 8 + (W & 7))) * 49 + (H >> 3) * 7 + (W >> 3);
}

// ---------------- prep: split weights -> bf16 hi/lo (transposed) -----------
__global__ void split_w(const float* __restrict__ wqkv, const float* __restrict__ wout) {
    int idx = blockIdx.x * 256 + threadIdx.x;
    if (idx < QKV_N * 96) {
        int n = idx / 96, k = idx % 96;
        float v = wqkv[k * QKV_N + n];
        __nv_bfloat16 h = __float2bfloat16(v);
        g_wqh[idx] = h;
        g_wql[idx] = __float2bfloat16(v - __bfloat162float(h));
    } else if (idx < QKV_N * 96 + 96 * 96) {
        int j = idx - QKV_N * 96;
        int n = j / 96, k = j % 96;
        float v = wout[k * 96 + n];
        __nv_bfloat16 h = __float2bfloat16(v);
        g_woh[j] = h;
        g_wol[j] = __float2bfloat16(v - __bfloat162float(h));
    }
}

// ---------------- HMMA GEMM ------------------------------------------------
// A32:   A operand is fp32, split to bf16 hi/lo while staging to smem.
// WINOUT: write bf16 hi/lo qkv into window-major g_qh/g_ql (+bias);
//         else write fp32 spatial out (+bias).
#define ASTR 104
#define S_AH 0
#define S_AL (128 * ASTR)
#define S_BH (2 * 128 * ASTR)
#define S_BL (2 * 128 * ASTR + 96 * ASTR)
#define GEMM_SMEM ((2 * 128 * ASTR + 2 * 96 * ASTR) * 2)   // 93184 B

template<bool A32, bool WINOUT>
__global__ __launch_bounds__(256) void gemm_hmma(
    const float* __restrict__ Af,
    const __nv_bfloat16* __restrict__ Ah, const __nv_bfloat16* __restrict__ Al,
    const __nv_bfloat16* __restrict__ Bh, const __nv_bfloat16* __restrict__ Bl,
    const float* __restrict__ bias, float* __restrict__ out, int N)
{
    extern __shared__ __nv_bfloat16 s[];
    const int tid = threadIdx.x, wid = tid >> 5, lane = tid & 31;
    const int g = lane >> 2, tg = lane & 3;
    const size_t m0 = (size_t)blockIdx.x * 128;
    const int n0 = blockIdx.y * 96;

    // A tiles 128x96 hi/lo
    for (int i = tid; i < 128 * 12; i += 256) {
        int row = i / 12, k8 = (i % 12) * 8;
        if (A32) {
            float4 v0 = *(const float4*)(Af + (m0 + row) * 96 + k8);
            float4 v1 = *(const float4*)(Af + (m0 + row) * 96 + k8 + 4);
            float vv[8] = {v0.x, v0.y, v0.z, v0.w, v1.x, v1.y, v1.z, v1.w};
            uint32_t hh[4], ll[4];
            #pragma unroll
            for (int e = 0; e < 4; e++) {
                float a = vv[2 * e], b = vv[2 * e + 1];
                hh[e] = pack_bf16x2(a, b);
                ll[e] = pack_bf16x2(a - bf16rt(a), b - bf16rt(b));
            }
            *(uint4*)(s + S_AH + row * ASTR + k8) = make_uint4(hh[0], hh[1], hh[2], hh[3]);
            *(uint4*)(s + S_AL + row * ASTR + k8) = make_uint4(ll[0], ll[1], ll[2], ll[3]);
        } else {
            *(uint4*)(s + S_AH + row * ASTR + k8) = *(const uint4*)(Ah + (m0 + row) * 96 + k8);
            *(uint4*)(s + S_AL + row * ASTR + k8) = *(const uint4*)(Al + (m0 + row) * 96 + k8);
        }
    }
    // B tiles 96x96 hi/lo
    for (int i = tid; i < 96 * 12; i += 256) {
        int row = i / 12, k8 = (i % 12) * 8;
        *(uint4*)(s + S_BH + row * ASTR + k8) = *(const uint4*)(Bh + (size_t)(n0 + row) * 96 + k8);
        *(uint4*)(s + S_BL + row * ASTR + k8) = *(const uint4*)(Bl + (size_t)(n0 + row) * 96 + k8);
    }
    __syncthreads();

    const int wm = (wid >> 1) * 32, wn = (wid & 1) * 48;
    float acc[2][6][4];
    #pragma unroll
    for (int mt = 0; mt < 2; mt++)
        #pragma unroll
        for (int nt = 0; nt < 6; nt++)
            #pragma unroll
            for (int e = 0; e < 4; e++) acc[mt][nt][e] = 0.f;

    for (int k16 = 0; k16 < 96; k16 += 16) {
        const int cb = k16 + tg * 2;
        uint32_t ah[2][4], al[2][4], bh[6][2], bl[6][2];
        #pragma unroll
        for (int mt = 0; mt < 2; mt++) {
            int r = wm + mt * 16 + g;
            ah[mt][0] = *(const uint32_t*)(s + S_AH + r * ASTR + cb);
            ah[mt][1] = *(const uint32_t*)(s + S_AH + (r + 8) * ASTR + cb);
            ah[mt][2] = *(const uint32_t*)(s + S_AH + r * ASTR + cb + 8);
            ah[mt][3] = *(const uint32_t*)(s + S_AH + (r + 8) * ASTR + cb + 8);
            al[mt][0] = *(const uint32_t*)(s + S_AL + r * ASTR + cb);
            al[mt][1] = *(const uint32_t*)(s + S_AL + (r + 8) * ASTR + cb);
            al[mt][2] = *(const uint32_t*)(s + S_AL + r * ASTR + cb + 8);
            al[mt][3] = *(const uint32_t*)(s + S_AL + (r + 8) * ASTR + cb + 8);
        }
        #pragma unroll
        for (int nt = 0; nt < 6; nt++) {
            int rn = wn + nt * 8 + g;
            bh[nt][0] = *(const uint32_t*)(s + S_BH + rn * ASTR + cb);
            bh[nt][1] = *(const uint32_t*)(s + S_BH + rn * ASTR + cb + 8);
            bl[nt][0] = *(const uint32_t*)(s + S_BL + rn * ASTR + cb);
            bl[nt][1] = *(const uint32_t*)(s + S_BL + rn * ASTR + cb + 8);
        }
        #pragma unroll
        for (int mt = 0; mt < 2; mt++)
            #pragma unroll
            for (int nt = 0; nt < 6; nt++) {
                mma_bf16(acc[mt][nt], ah[mt], bh[nt]);
                mma_bf16(acc[mt][nt], ah[mt], bl[nt]);
                mma_bf16(acc[mt][nt], al[mt], bh[nt]);
            }
    }

    if (WINOUT) {
        #pragma unroll
        for (int mt = 0; mt < 2; mt++) {
            size_t ra = m0 + wm + mt * 16 + g;
            size_t dA = winmap(ra) * 288, dB = winmap(ra + 8) * 288;
            #pragma unroll
            for (int nt = 0; nt < 6; nt++) {
                int col = n0 + wn + nt * 8 + tg * 2;
                float2 bb = *(const float2*)(bias + col);
                float v0 = acc[mt][nt][0] + bb.x, v1 = acc[mt][nt][1] + bb.y;
                float v2 = acc[mt][nt][2] + bb.x, v3 = acc[mt][nt][3] + bb.y;
                *(uint32_t*)(g_qh + dA + col) = pack_bf16x2(v0, v1);
                *(uint32_t*)(g_ql + dA + col) = pack_bf16x2(v0 - bf16rt(v0), v1 - bf16rt(v1));
                *(uint32_t*)(g_qh + dB + col) = pack_bf16x2(v2, v3);
                *(uint32_t*)(g_ql + dB + col) = pack_bf16x2(v2 - bf16rt(v2), v3 - bf16rt(v3));
            }
        }
    } else {
        #pragma unroll
        for (int nt = 0; nt < 6; nt++) {
            int col = n0 + wn + nt * 8 + tg * 2;
            float2 bb = *(const float2*)(bias + col);
            #pragma unroll
            for (int mt = 0; mt < 2; mt++) {
                size_t r0 = m0 + wm + mt * 16 + g;
                *(float2*)(out + r0 * N + col)       = make_float2(acc[mt][nt][0] + bb.x, acc[mt][nt][1] + bb.y);
                *(float2*)(out + (r0 + 8) * N + col) = make_float2(acc[mt][nt][2] + bb.x, acc[mt][nt][3] + bb.y);
            }
        }
    }
}

// ---------------- HMMA attention -------------------------------------------
// 384 threads = 12 warps; warp = (m-tile 0..3, head 0..2).  qkv already bf16
// hi/lo in window-major layout -> fully coalesced gather, zero conversions.
// Scale folded into post-MMA bias FMA.  sim/att register-resident as in R7.
#define QSTR 40
#define VSTR 56
#define SQH 0
#define SQL (3*49*QSTR)
#define SKH (2*3*49*QSTR)
#define SKL (3*3*49*QSTR)
#define SVH (4*3*49*QSTR)
#define SVL (4*3*49*QSTR + 3*32*VSTR)
#define SREL_OFF (4*3*49*QSTR + 2*3*32*VSTR)            // bf16 units (even)
#define ATTN_SMEM (SREL_OFF*2 + 507*4)                  // 70572 B

__global__ __launch_bounds__(384, 2) void attn_mma(const float* __restrict__ rel_pos)
{
    extern __shared__ __nv_bfloat16 sb[];
    __nv_bfloat16* sqh = sb + SQH;
    __nv_bfloat16* sql = sb + SQL;
    __nv_bfloat16* skh = sb + SKH;
    __nv_bfloat16* skl = sb + SKL;
    __nv_bfloat16* vth = sb + SVH;
    __nv_bfloat16* vtl = sb + SVL;
    float* srel = (float*)(sb + SREL_OFF);
    __shared__ int sg[49];

    const int tid = threadIdx.x;
    const int win = blockIdx.x;                 // ((b*8)+hi)*8+wi
    const int wi = win & 7, hi2 = (win >> 3) & 7, bb2 = win >> 6;

    if (tid < 49) {
        int p = tid / 7, q = tid - (tid / 7) * 7;
        sg[tid] = (bb2 * 56 + p * 8 + hi2) * 56 + q * 8 + wi;
    }
    for (int i = tid; i < 507; i += 384) srel[i] = rel_pos[i];

    // coalesced gather: 49 tokens x 36 uint4 (hi & lo)
    const __nv_bfloat16* srcH = g_qh + (size_t)win * 49 * 288;
    const __nv_bfloat16* srcL = g_ql + (size_t)win * 49 * 288;
    for (int i = tid; i < 49 * 36; i += 384) {
        int t = i / 36, r = i % 36;
        int which = r / 12, h = (r % 12) >> 2, d8 = (r & 3) * 8;
        uint4 H = *(const uint4*)(srcH + t * 288 + r * 8);
        uint4 L = *(const uint4*)(srcL + t * 288 + r * 8);
        if (which == 0) {
            *(uint4*)(sqh + (h * 49 + t) * QSTR + d8) = H;
            *(uint4*)(sql + (h * 49 + t) * QSTR + d8) = L;
        } else if (which == 1) {
            *(uint4*)(skh + (h * 49 + t) * QSTR + d8) = H;
            *(uint4*)(skl + (h * 49 + t) * QSTR + d8) = L;
        } else {
            const __nv_bfloat16* he = (const __nv_bfloat16*)&H;
            const __nv_bfloat16* le = (const __nv_bfloat16*)&L;
            #pragma unroll
            for (int e = 0; e < 8; e++) {
                vth[(h * 32 + d8 + e) * VSTR + t] = he[e];
                vtl[(h * 32 + d8 + e) * VSTR + t] = le[e];
            }
        }
    }
    __syncthreads();

    const int lane = tid & 31, warp = tid >> 5;
    const int mtile = warp & 3, h = warp >> 2;
    const int g = lane >> 2, tg = lane & 3;
    const int m0 = (mtile == 3) ? 33 : mtile * 16;
    const int r0 = m0 + g, r1 = m0 + 8 + g;
    const int n0tab[7] = {0, 8, 16, 24, 32, 40, 41};
    const float scale = 0.17677669529663687f;   // 32^-0.5

    const __nv_bfloat16* qh = sqh + h * 49 * QSTR;
    const __nv_bfloat16* ql = sql + h * 49 * QSTR;
    const __nv_bfloat16* kh = skh + h * 49 * QSTR;
    const __nv_bfloat16* kl = skl + h * 49 * QSTR;

    // ---- sim = q k^T (3-product bf16 split) ----
    float acc[7][4];
    #pragma unroll
    for (int nt = 0; nt < 7; nt++)
        #pragma unroll
        for (int e = 0; e < 4; e++) acc[nt][e] = 0.f;

    #pragma unroll
    for (int ks = 0; ks < 2; ks++) {
        const int kb = ks * 16 + 2 * tg;
        uint32_t aH[4], aL[4];
        aH[0] = *(const uint32_t*)(qh + r0 * QSTR + kb);
        aH[1] = *(const uint32_t*)(qh + r1 * QSTR + kb);
        aH[2] = *(const uint32_t*)(qh + r0 * QSTR + kb + 8);
        aH[3] = *(const uint32_t*)(qh + r1 * QSTR + kb + 8);
        aL[0] = *(const uint32_t*)(ql + r0 * QSTR + kb);
        aL[1] = *(const uint32_t*)(ql + r1 * QSTR + kb);
        aL[2] = *(const uint32_t*)(ql + r0 * QSTR + kb + 8);
        aL[3] = *(const uint32_t*)(ql + r1 * QSTR + kb + 8);
        #pragma unroll
        for (int nt = 0; nt < 7; nt++) {
            int rn = n0tab[nt] + g;
            uint32_t bH[2] = {*(const uint32_t*)(kh + rn * QSTR + kb),
                              *(const uint32_t*)(kh + rn * QSTR + kb + 8)};
            uint32_t bL[2] = {*(const uint32_t*)(kl + rn * QSTR + kb),
                              *(const uint32_t*)(kl + rn * QSTR + kb + 8)};
            mma_bf16(acc[nt], aH, bH);
            mma_bf16(acc[nt], aH, bL);
            mma_bf16(acc[nt], aL, bH);
        }
    }

    // ---- acc*scale + rel-pos bias ----
    {
        const float* relh = srel + h * 169;
        int pi0 = r0 / 7, qi0 = r0 % 7, pi1 = r1 / 7, qi1 = r1 % 7;
        #pragma unroll
        for (int nt = 0; nt < 7; nt++) {
            int j0 = n0tab[nt] + 2 * tg, j1 = j0 + 1;
            int pj0 = j0 / 7, qj0 = j0 % 7, pj1 = j1 / 7, qj1 = j1 % 7;
            acc[nt][0] = fmaf(acc[nt][0], scale, relh[(pi0 - pj0 + 6) * 13 + (qi0 - qj0 + 6)]);
            acc[nt][1] = fmaf(acc[nt][1], scale, relh[(pi0 - pj1 + 6) * 13 + (qi0 - qj1 + 6)]);
            acc[nt][2] = fmaf(acc[nt][2], scale, relh[(pi1 - pj0 + 6) * 13 + (qi1 - qj0 + 6)]);
            acc[nt][3] = fmaf(acc[nt][3], scale, relh[(pi1 - pj1 + 6) * 13 + (qi1 - qj1 + 6)]);
        }
    }

    // ---- softmax (rows r0: c0/c1, r1: c2/c3); dup cols excluded from sum ----
    float mx0 = -1e30f, mx1 = -1e30f;
    #pragma unroll
    for (int nt = 0; nt < 7; nt++) {
        mx0 = fmaxf(mx0, fmaxf(acc[nt][0], acc[nt][1]));
        mx1 = fmaxf(mx1, fmaxf(acc[nt][2], acc[nt][3]));
    }
    mx0 = fmaxf(mx0, __shfl_xor_sync(0xffffffffu, mx0, 1));
    mx0 = fmaxf(mx0, __shfl_xor_sync(0xffffffffu, mx0, 2));
    mx1 = fmaxf(mx1, __shfl_xor_sync(0xffffffffu, mx1, 1));
    mx1 = fmaxf(mx1, __shfl_xor_sync(0xffffffffu, mx1, 2));
    float s0 = 0.f, s1 = 0.f;
    #pragma unroll
    for (int nt = 0; nt < 6; nt++) {
        acc[nt][0] = __expf(acc[nt][0] - mx0); s0 += acc[nt][0];
        acc[nt][1] = __expf(acc[nt][1] - mx0); s0 += acc[nt][1];
        acc[nt][2] = __expf(acc[nt][2] - mx1); s1 += acc[nt][2];
        acc[nt][3] = __expf(acc[nt][3] - mx1); s1 += acc[nt][3];
    }
    acc[6][0] = __expf(acc[6][0] - mx0);
    acc[6][1] = __expf(acc[6][1] - mx0);
    acc[6][2] = __expf(acc[6][2] - mx1);
    acc[6][3] = __expf(acc[6][3] - mx1);
    if (tg == 3) { s0 += acc[6][1]; s1 += acc[6][3]; }   // col 48 only
    s0 += __shfl_xor_sync(0xffffffffu, s0, 1);
    s0 += __shfl_xor_sync(0xffffffffu, s0, 2);
    s1 += __shfl_xor_sync(0xffffffffu, s1, 1);
    s1 += __shfl_xor_sync(0xffffffffu, s1, 2);
    float inv0 = 1.f / s0, inv1 = 1.f / s1;
    #pragma unroll
    for (int nt = 0; nt < 7; nt++) {
        acc[nt][0] *= inv0; acc[nt][1] *= inv0;
        acc[nt][2] *= inv1; acc[nt][3] *= inv1;
    }

    // ---- out = att @ v : att repacked in-register as A frags ----
    float accv[4][4];
    #pragma unroll
    for (int dn = 0; dn < 4; dn++)
        #pragma unroll
        for (int e = 0; e < 4; e++) accv[dn][e] = 0.f;

    #pragma unroll
    for (int ks = 0; ks < 3; ks++) {
        uint32_t aH[4], aL[4];
        #pragma unroll
        for (int half = 0; half < 2; half++) {
            float* t = acc[2 * ks + half];
            float h0 = bf16rt(t[0]), h1 = bf16rt(t[1]);
            float h2 = bf16rt(t[2]), h3 = bf16rt(t[3]);
            aH[half ? 2 : 0] = pack_bf16x2(t[0], t[1]);
            aH[half ? 3 : 1] = pack_bf16x2(t[2], t[3]);
            aL[half ? 2 : 0] = pack_bf16x2(t[0] - h0, t[1] - h1);
            aL[half ? 3 : 1] = pack_bf16x2(t[2] - h2, t[3] - h3);
        }
        #pragma unroll
        for (int dn = 0; dn < 4; dn++) {
            const __nv_bfloat16* bh = vth + (h * 32 + dn * 8 + g) * VSTR + ks * 16 + 2 * tg;
            const __nv_bfloat16* bl = vtl + (h * 32 + dn * 8 + g) * VSTR + ks * 16 + 2 * tg;
            uint32_t bH[2] = {*(const uint32_t*)bh, *(const uint32_t*)(bh + 8)};
            uint32_t bL[2] = {*(const uint32_t*)bl, *(const uint32_t*)(bl + 8)};
            mma_bf16(accv[dn], aH, bH);
            mma_bf16(accv[dn], aH, bL);
            mma_bf16(accv[dn], aL, bH);
        }
    }
    // j = 48 via shfl + scalar FMA
    float a48a = __shfl_sync(0xffffffffu, acc[6][1], lane | 3);
    float a48b = __shfl_sync(0xffffffffu, acc[6][3], lane | 3);
    #pragma unroll
    for (int dn = 0; dn < 4; dn++) {
        int d0 = dn * 8 + 2 * tg;
        float v0 = __bfloat162float(vth[(h * 32 + d0) * VSTR + 48])
                 + __bfloat162float(vtl[(h * 32 + d0) * VSTR + 48]);
        float v1 = __bfloat162float(vth[(h * 32 + d0 + 1) * VSTR + 48])
                 + __bfloat162float(vtl[(h * 32 + d0 + 1) * VSTR + 48]);
        accv[dn][0] += a48a * v0; accv[dn][1] += a48a * v1;
        accv[dn][2] += a48b * v0; accv[dn][3] += a48b * v1;
    }

    // ---- store bf16 hi/lo att-output (spatial layout for gemm2) ----
    const int tok0 = sg[r0], tok1 = sg[r1];
    #pragma unroll
    for (int dn = 0; dn < 4; dn++) {
        int d0 = dn * 8 + 2 * tg;
        size_t o0 = (size_t)tok0 * 96 + h * 32 + d0;
        size_t o1 = (size_t)tok1 * 96 + h * 32 + d0;
        float e0 = bf16rt(accv[dn][0]), e1 = bf16rt(accv[dn][1]);
        float e2 = bf16rt(accv[dn][2]), e3 = bf16rt(accv[dn][3]);
        *(uint32_t*)(g_ah + o0) = pack_bf16x2(accv[dn][0], accv[dn][1]);
        *(uint32_t*)(g_al + o0) = pack_bf16x2(accv[dn][0] - e0, accv[dn][1] - e1);
        *(uint32_t*)(g_ah + o1) = pack_bf16x2(accv[dn][2], accv[dn][3]);
        *(uint32_t*)(g_al + o1) = pack_bf16x2(accv[dn][2] - e2, accv[dn][3] - e3);
    }
}

// ---------------- launch ----------------------------------------------------
extern "C" void kernel_launch(void* const* d_in, const int* in_sizes, int n_in,
                              void* d_out, int out_size)
{
    (void)in_sizes; (void)n_in; (void)out_size;
    const float* x     = (const float*)d_in[0];
    const float* w_qkv = (const float*)d_in[1];
    const float* b_qkv = (const float*)d_in[2];
    const float* rel   = (const float*)d_in[3];
    const float* w_out = (const float*)d_in[4];
    const float* b_out = (const float*)d_in[5];
    float* out = (float*)d_out;

    __nv_bfloat16 *ah, *al, *wqh, *wql, *woh, *wol;
    cudaGetSymbolAddress((void**)&ah, g_ah);   cudaGetSymbolAddress((void**)&al, g_al);
    cudaGetSymbolAddress((void**)&wqh, g_wqh); cudaGetSymbolAddress((void**)&wql, g_wql);
    cudaGetSymbolAddress((void**)&woh, g_woh); cudaGetSymbolAddress((void**)&wol, g_wol);

    cudaFuncSetAttribute(gemm_hmma<true, true>,   cudaFuncAttributeMaxDynamicSharedMemorySize, GEMM_SMEM);
    cudaFuncSetAttribute(gemm_hmma<false, false>, cudaFuncAttributeMaxDynamicSharedMemorySize, GEMM_SMEM);
    cudaFuncSetAttribute(attn_mma, cudaFuncAttributeMaxDynamicSharedMemorySize, ATTN_SMEM);

    // 0) split weights (tiny)
    split_w<<<((QKV_N + 96) * 96 + 255) / 256, 256>>>(w_qkv, w_out);

    // 1) qkv = x @ w_qkv + b_qkv -> bf16 hi/lo window-major (fused x split)
    gemm_hmma<true, true><<<dim3(M_TOK / 128, 3), 256, GEMM_SMEM>>>(
        x, nullptr, nullptr, wqh, wql, b_qkv, nullptr, QKV_N);

    // 2) windowed attention (12 warps: 4 m-tiles x 3 heads)
    attn_mma<<<4096, 384, ATTN_SMEM>>>(rel);

    // 3) out = att @ w_out + b_out (fp32 spatial)
    gemm_hmma<false, false><<<dim3(M_TOK / 128, 1), 256, GEMM_SMEM>>>(
        nullptr, ah, al, woh, wol, b_out, out, 96);
}

// round 11
// speedup vs baseline: 1.7948x; 1.0669x over previous
#include <cuda_runtime.h>
#include <cuda_bf16.h>
#include <cstdint>

#define M_TOK 200704
#define QKV_N 288

// ---------------- scratch (__device__ globals; no allocs allowed) ----------
// qkv AND att in WINDOW-MAJOR layout: row = win*49 + t
__device__ __nv_bfloat16 g_qh[(size_t)M_TOK * 288], g_ql[(size_t)M_TOK * 288];
__device__ __nv_bfloat16 g_ah[(size_t)M_TOK * 96],  g_al[(size_t)M_TOK * 96];
__device__ __nv_bfloat16 g_wqh[QKV_N * 96], g_wql[QKV_N * 96]; // w_qkv^T [n][k]
__device__ __nv_bfloat16 g_woh[96 * 96],    g_wol[96 * 96];    // w_out^T [n][k]

__device__ __forceinline__ void mma_bf16(float* c, const uint32_t* a, const uint32_t* b) {
    asm("mma.sync.aligned.m16n8k16.row.col.f32.bf16.bf16.f32 "
        "{%0,%1,%2,%3}, {%4,%5,%6,%7}, {%8,%9}, {%0,%1,%2,%3};"
        : "+f"(c[0]), "+f"(c[1]), "+f"(c[2]), "+f"(c[3])
        : "r"(a[0]), "r"(a[1]), "r"(a[2]), "r"(a[3]), "r"(b[0]), "r"(b[1]));
}
__device__ __forceinline__ uint32_t pack_bf16x2(float lo, float hi) {
    uint32_t r;
    asm("cvt.rn.bf16x2.f32 %0, %1, %2;" : "=r"(r) : "f"(hi), "f"(lo));
    return r;
}
__device__ __forceinline__ float bf16rt(float x) {
    return __bfloat162float(__float2bfloat16(x));
}
// spatial row m -> window-major row
__device__ __forceinline__ size_t winmap(size_t m) {
    int b = (int)(m / 3136), rem = (int)(m % 3136);
    int H = rem / 56, W = rem % 56;
    return ((size_t)(b * 64 + (H & 7) * 8 + (W & 7))) * 49 + (H >> 3) * 7 + (W >> 3);
}
// window-major row -> spatial row
__device__ __forceinline__ size_t invwinmap(size_t wr) {
    int win = (int)(wr / 49), t = (int)(wr % 49);
    int b = win >> 6, hi = (win >> 3) & 7, wi = win & 7;
    int p = t / 7, q = t % 7;
    return (size_t)(b * 56 + p * 8 + hi) * 56 + q * 8 + wi;
}

// ---------------- prep: split weights -> bf16 hi/lo (transposed) -----------
__global__ void split_w(const float* __restrict__ wqkv, const float* __restrict__ wout) {
    int idx = blockIdx.x * 256 + threadIdx.x;
    if (idx < QKV_N * 96) {
        int n = idx / 96, k = idx % 96;
        float v = wqkv[k * QKV_N + n];
        __nv_bfloat16 h = __float2bfloat16(v);
        g_wqh[idx] = h;
        g_wql[idx] = __float2bfloat16(v - __bfloat162float(h));
    } else if (idx < QKV_N * 96 + 96 * 96) {
        int j = idx - QKV_N * 96;
        int n = j / 96, k = j % 96;
        float v = wout[k * 96 + n];
        __nv_bfloat16 h = __float2bfloat16(v);
        g_woh[j] = h;
        g_wol[j] = __float2bfloat16(v - __bfloat162float(h));
    }
}

// ---------------- shared GEMM core macros ----------------------------------
#define ASTR 104
#define S_AH 0
#define S_AL (128 * ASTR)
#define S_BH (2 * 128 * ASTR)
#define S_BL (2 * 128 * ASTR + 96 * ASTR)
#define GEMM_SMEM ((2 * 128 * ASTR + 2 * 96 * ASTR) * 2)   // 93184 B
#define STG 104                                            // staging row stride

#define GEMM_MAINLOOP()                                                         \
    const int wm = (wid >> 1) * 32, wn = (wid & 1) * 48;                        \
    float acc[2][6][4];                                                         \
    _Pragma("unroll")                                                           \
    for (int mt = 0; mt < 2; mt++)                                              \
        _Pragma("unroll")                                                       \
        for (int nt = 0; nt < 6; nt++)                                          \
            _Pragma("unroll")                                                   \
            for (int e = 0; e < 4; e++) acc[mt][nt][e] = 0.f;                   \
    for (int k16 = 0; k16 < 96; k16 += 16) {                                    \
        const int cb = k16 + tg * 2;                                            \
        uint32_t ah[2][4], al[2][4], bh[6][2], bl[6][2];                        \
        _Pragma("unroll")                                                       \
        for (int mt = 0; mt < 2; mt++) {                                        \
            int r = wm + mt * 16 + g;                                           \
            ah[mt][0] = *(const uint32_t*)(s + S_AH + r * ASTR + cb);           \
            ah[mt][1] = *(const uint32_t*)(s + S_AH + (r + 8) * ASTR + cb);     \
            ah[mt][2] = *(const uint32_t*)(s + S_AH + r * ASTR + cb + 8);       \
            ah[mt][3] = *(const uint32_t*)(s + S_AH + (r + 8) * ASTR + cb + 8); \
            al[mt][0] = *(const uint32_t*)(s + S_AL + r * ASTR + cb);           \
            al[mt][1] = *(const uint32_t*)(s + S_AL + (r + 8) * ASTR + cb);     \
            al[mt][2] = *(const uint32_t*)(s + S_AL + r * ASTR + cb + 8);       \
            al[mt][3] = *(const uint32_t*)(s + S_AL + (r + 8) * ASTR + cb + 8); \
        }                                                                       \
        _Pragma("unroll")                                                       \
        for (int nt = 0; nt < 6; nt++) {                                        \
            int rn = wn + nt * 8 + g;                                           \
            bh[nt][0] = *(const uint32_t*)(s + S_BH + rn * ASTR + cb);          \
            bh[nt][1] = *(const uint32_t*)(s + S_BH + rn * ASTR + cb + 8);      \
            bl[nt][0] = *(const uint32_t*)(s + S_BL + rn * ASTR + cb);          \
            bl[nt][1] = *(const uint32_t*)(s + S_BL + rn * ASTR + cb + 8);      \
        }                                                                       \
        _Pragma("unroll")                                                       \
        for (int mt = 0; mt < 2; mt++)                                          \
            _Pragma("unroll")                                                   \
            for (int nt = 0; nt < 6; nt++) {                                    \
                mma_bf16(acc[mt][nt], ah[mt], bh[nt]);                          \
                mma_bf16(acc[mt][nt], ah[mt], bl[nt]);                          \
                mma_bf16(acc[mt][nt], al[mt], bh[nt]);                          \
            }                                                                   \
    }

// ---------------- GEMM 1: qkv projection (A fp32, out window-major bf16) ----
__global__ __launch_bounds__(256) void gemm_qkv(
    const float* __restrict__ Af,
    const __nv_bfloat16* __restrict__ Bh, const __nv_bfloat16* __restrict__ Bl,
    const float* __restrict__ bias)
{
    extern __shared__ __nv_bfloat16 s[];
    __shared__ size_t wrow[128];
    const int tid = threadIdx.x, wid = tid >> 5, lane = tid & 31;
    const int g = lane >> 2, tg = lane & 3;
    const size_t m0 = (size_t)blockIdx.x * 128;
    const int n0 = blockIdx.y * 96;

    // A tile 128x96: fp32 -> bf16 hi/lo while staging
    for (int i = tid; i < 128 * 12; i += 256) {
        int row = i / 12, k8 = (i % 12) * 8;
        float4 v0 = *(const float4*)(Af + (m0 + row) * 96 + k8);
        float4 v1 = *(const float4*)(Af + (m0 + row) * 96 + k8 + 4);
        float vv[8] = {v0.x, v0.y, v0.z, v0.w, v1.x, v1.y, v1.z, v1.w};
        uint32_t hh[4], ll[4];
        #pragma unroll
        for (int e = 0; e < 4; e++) {
            float a = vv[2 * e], b = vv[2 * e + 1];
            hh[e] = pack_bf16x2(a, b);
            ll[e] = pack_bf16x2(a - bf16rt(a), b - bf16rt(b));
        }
        *(uint4*)(s + S_AH + row * ASTR + k8) = make_uint4(hh[0], hh[1], hh[2], hh[3]);
        *(uint4*)(s + S_AL + row * ASTR + k8) = make_uint4(ll[0], ll[1], ll[2], ll[3]);
    }
    for (int i = tid; i < 96 * 12; i += 256) {
        int row = i / 12, k8 = (i % 12) * 8;
        *(uint4*)(s + S_BH + row * ASTR + k8) = *(const uint4*)(Bh + (size_t)(n0 + row) * 96 + k8);
        *(uint4*)(s + S_BL + row * ASTR + k8) = *(const uint4*)(Bl + (size_t)(n0 + row) * 96 + k8);
    }
    __syncthreads();

    GEMM_MAINLOOP()

    // staged epilogue: bf16 hi/lo, then coalesced 192B-per-row stores
    __syncthreads();
    if (tid < 128) wrow[tid] = winmap(m0 + tid) * 288 + n0;
    __nv_bfloat16* stH = s;                  // [128][STG]
    __nv_bfloat16* stL = s + 128 * STG;
    #pragma unroll
    for (int mt = 0; mt < 2; mt++) {
        int rA = wm + mt * 16 + g, rB = rA + 8;
        #pragma unroll
        for (int nt = 0; nt < 6; nt++) {
            int col = wn + nt * 8 + tg * 2;
            float2 bb = *(const float2*)(bias + n0 + col);
            float v0 = acc[mt][nt][0] + bb.x, v1 = acc[mt][nt][1] + bb.y;
            float v2 = acc[mt][nt][2] + bb.x, v3 = acc[mt][nt][3] + bb.y;
            *(uint32_t*)(stH + rA * STG + col) = pack_bf16x2(v0, v1);
            *(uint32_t*)(stL + rA * STG + col) = pack_bf16x2(v0 - bf16rt(v0), v1 - bf16rt(v1));
            *(uint32_t*)(stH + rB * STG + col) = pack_bf16x2(v2, v3);
            *(uint32_t*)(stL + rB * STG + col) = pack_bf16x2(v2 - bf16rt(v2), v3 - bf16rt(v3));
        }
    }
    __syncthreads();
    for (int i = tid; i < 128 * 12; i += 256) {
        int row = i / 12, j8 = (i % 12) * 8;
        size_t d = wrow[row] + j8;
        *(uint4*)(g_qh + d) = *(const uint4*)(stH + row * STG + j8);
        *(uint4*)(g_ql + d) = *(const uint4*)(stL + row * STG + j8);
    }
}

// ---------------- GEMM 2: out projection (A window-major bf16, out spatial) -
__global__ __launch_bounds__(256) void gemm_out(
    const __nv_bfloat16* __restrict__ Ah, const __nv_bfloat16* __restrict__ Al,
    const __nv_bfloat16* __restrict__ Bh, const __nv_bfloat16* __restrict__ Bl,
    const float* __restrict__ bias, float* __restrict__ out)
{
    extern __shared__ __nv_bfloat16 s[];
    __shared__ size_t srow[128];
    const int tid = threadIdx.x, wid = tid >> 5, lane = tid & 31;
    const int g = lane >> 2, tg = lane & 3;
    const size_t m0 = (size_t)blockIdx.x * 128;

    for (int i = tid; i < 128 * 12; i += 256) {
        int row = i / 12, k8 = (i % 12) * 8;
        *(uint4*)(s + S_AH + row * ASTR + k8) = *(const uint4*)(Ah + (m0 + row) * 96 + k8);
        *(uint4*)(s + S_AL + row * ASTR + k8) = *(const uint4*)(Al + (m0 + row) * 96 + k8);
    }
    for (int i = tid; i < 96 * 12; i += 256) {
        int row = i / 12, k8 = (i % 12) * 8;
        *(uint4*)(s + S_BH + row * ASTR + k8) = *(const uint4*)(Bh + (size_t)row * 96 + k8);
        *(uint4*)(s + S_BL + row * ASTR + k8) = *(const uint4*)(Bl + (size_t)row * 96 + k8);
    }
    __syncthreads();

    GEMM_MAINLOOP()

    // staged fp32 epilogue, scatter per spatial row (384B contiguous)
    __syncthreads();
    if (tid < 128) srow[tid] = invwinmap(m0 + tid) * 96;
    float* st = (float*)s;                    // [128][100]
    #pragma unroll
    for (int mt = 0; mt < 2; mt++) {
        int rA = wm + mt * 16 + g, rB = rA + 8;
        #pragma unroll
        for (int nt = 0; nt < 6; nt++) {
            int col = wn + nt * 8 + tg * 2;
            float2 bb = *(const float2*)(bias + col);
            *(float2*)(st + rA * 100 + col) = make_float2(acc[mt][nt][0] + bb.x, acc[mt][nt][1] + bb.y);
            *(float2*)(st + rB * 100 + col) = make_float2(acc[mt][nt][2] + bb.x, acc[mt][nt][3] + bb.y);
        }
    }
    __syncthreads();
    for (int i = tid; i < 128 * 24; i += 256) {
        int row = i / 24, j4 = (i % 24) * 4;
        *(float4*)(out + srow[row] + j4) = *(const float4*)(st + row * 100 + j4);
    }
}

// ---------------- HMMA attention -------------------------------------------
// 384 threads = 12 warps; warp = (m-tile 0..3, head 0..2).  qkv bf16 hi/lo
// window-major -> coalesced gather; att output staged in smem and stored
// window-major fully coalesced.  sim/att register-resident.
#define QSTR 40
#define VSTR 56
#define SQH 0
#define SQL (3*49*QSTR)
#define SKH (2*3*49*QSTR)
#define SKL (3*3*49*QSTR)
#define SVH (4*3*49*QSTR)
#define SVL (4*3*49*QSTR + 3*32*VSTR)
#define SREL_OFF (4*3*49*QSTR + 2*3*32*VSTR)            // bf16 units (even)
#define ATTN_SMEM (SREL_OFF*2 + 507*4)                  // 70572 B

__global__ __launch_bounds__(384, 2) void attn_mma(const float* __restrict__ rel_pos)
{
    extern __shared__ __nv_bfloat16 sb[];
    __nv_bfloat16* sqh = sb + SQH;
    __nv_bfloat16* sql = sb + SQL;
    __nv_bfloat16* skh = sb + SKH;
    __nv_bfloat16* skl = sb + SKL;
    __nv_bfloat16* vth = sb + SVH;
    __nv_bfloat16* vtl = sb + SVL;
    float* srel = (float*)(sb + SREL_OFF);

    const int tid = threadIdx.x;
    const int win = blockIdx.x;

    for (int i = tid; i < 507; i += 384) srel[i] = rel_pos[i];

    // coalesced gather: 49 tokens x 36 uint4 (hi & lo)
    const __nv_bfloat16* srcH = g_qh + (size_t)win * 49 * 288;
    const __nv_bfloat16* srcL = g_ql + (size_t)win * 49 * 288;
    for (int i = tid; i < 49 * 36; i += 384) {
        int t = i / 36, r = i % 36;
        int which = r / 12, h = (r % 12) >> 2, d8 = (r & 3) * 8;
        uint4 H = *(const uint4*)(srcH + t * 288 + r * 8);
        uint4 L = *(const uint4*)(srcL + t * 288 + r * 8);
        if (which == 0) {
            *(uint4*)(sqh + (h * 49 + t) * QSTR + d8) = H;
            *(uint4*)(sql + (h * 49 + t) * QSTR + d8) = L;
        } else if (which == 1) {
            *(uint4*)(skh + (h * 49 + t) * QSTR + d8) = H;
            *(uint4*)(skl + (h * 49 + t) * QSTR + d8) = L;
        } else {
            const __nv_bfloat16* he = (const __nv_bfloat16*)&H;
            const __nv_bfloat16* le = (const __nv_bfloat16*)&L;
            #pragma unroll
            for (int e = 0; e < 8; e++) {
                vth[(h * 32 + d8 + e) * VSTR + t] = he[e];
                vtl[(h * 32 + d8 + e) * VSTR + t] = le[e];
            }
        }
    }
    __syncthreads();

    const int lane = tid & 31, warp = tid >> 5;
    const int mtile = warp & 3, h = warp >> 2;
    const int g = lane >> 2, tg = lane & 3;
    const int m0 = (mtile == 3) ? 33 : mtile * 16;
    const int r0 = m0 + g, r1 = m0 + 8 + g;
    const int n0tab[7] = {0, 8, 16, 24, 32, 40, 41};
    const float scale = 0.17677669529663687f;   // 32^-0.5

    const __nv_bfloat16* qh = sqh + h * 49 * QSTR;
    const __nv_bfloat16* ql = sql + h * 49 * QSTR;
    const __nv_bfloat16* kh = skh + h * 49 * QSTR;
    const __nv_bfloat16* kl = skl + h * 49 * QSTR;

    // ---- sim = q k^T (3-product bf16 split) ----
    float acc[7][4];
    #pragma unroll
    for (int nt = 0; nt < 7; nt++)
        #pragma unroll
        for (int e = 0; e < 4; e++) acc[nt][e] = 0.f;

    #pragma unroll
    for (int ks = 0; ks < 2; ks++) {
        const int kb = ks * 16 + 2 * tg;
        uint32_t aH[4], aL[4];
        aH[0] = *(const uint32_t*)(qh + r0 * QSTR + kb);
        aH[1] = *(const uint32_t*)(qh + r1 * QSTR + kb);
        aH[2] = *(const uint32_t*)(qh + r0 * QSTR + kb + 8);
        aH[3] = *(const uint32_t*)(qh + r1 * QSTR + kb + 8);
        aL[0] = *(const uint32_t*)(ql + r0 * QSTR + kb);
        aL[1] = *(const uint32_t*)(ql + r1 * QSTR + kb);
        aL[2] = *(const uint32_t*)(ql + r0 * QSTR + kb + 8);
        aL[3] = *(const uint32_t*)(ql + r1 * QSTR + kb + 8);
        #pragma unroll
        for (int nt = 0; nt < 7; nt++) {
            int rn = n0tab[nt] + g;
            uint32_t bH[2] = {*(const uint32_t*)(kh + rn * QSTR + kb),
                              *(const uint32_t*)(kh + rn * QSTR + kb + 8)};
            uint32_t bL[2] = {*(const uint32_t*)(kl + rn * QSTR + kb),
                              *(const uint32_t*)(kl + rn * QSTR + kb + 8)};
            mma_bf16(acc[nt], aH, bH);
            mma_bf16(acc[nt], aH, bL);
            mma_bf16(acc[nt], aL, bH);
        }
    }

    // ---- acc*scale + rel-pos bias ----
    {
        const float* relh = srel + h * 169;
        int pi0 = r0 / 7, qi0 = r0 % 7, pi1 = r1 / 7, qi1 = r1 % 7;
        #pragma unroll
        for (int nt = 0; nt < 7; nt++) {
            int j0 = n0tab[nt] + 2 * tg, j1 = j0 + 1;
            int pj0 = j0 / 7, qj0 = j0 % 7, pj1 = j1 / 7, qj1 = j1 % 7;
            acc[nt][0] = fmaf(acc[nt][0], scale, relh[(pi0 - pj0 + 6) * 13 + (qi0 - qj0 + 6)]);
            acc[nt][1] = fmaf(acc[nt][1], scale, relh[(pi0 - pj1 + 6) * 13 + (qi0 - qj1 + 6)]);
            acc[nt][2] = fmaf(acc[nt][2], scale, relh[(pi1 - pj0 + 6) * 13 + (qi1 - qj0 + 6)]);
            acc[nt][3] = fmaf(acc[nt][3], scale, relh[(pi1 - pj1 + 6) * 13 + (qi1 - qj1 + 6)]);
        }
    }

    // ---- softmax (rows r0: c0/c1, r1: c2/c3); dup cols excluded from sum ----
    float mx0 = -1e30f, mx1 = -1e30f;
    #pragma unroll
    for (int nt = 0; nt < 7; nt++) {
        mx0 = fmaxf(mx0, fmaxf(acc[nt][0], acc[nt][1]));
        mx1 = fmaxf(mx1, fmaxf(acc[nt][2], acc[nt][3]));
    }
    mx0 = fmaxf(mx0, __shfl_xor_sync(0xffffffffu, mx0, 1));
    mx0 = fmaxf(mx0, __shfl_xor_sync(0xffffffffu, mx0, 2));
    mx1 = fmaxf(mx1, __shfl_xor_sync(0xffffffffu, mx1, 1));
    mx1 = fmaxf(mx1, __shfl_xor_sync(0xffffffffu, mx1, 2));
    float s0 = 0.f, s1 = 0.f;
    #pragma unroll
    for (int nt = 0; nt < 6; nt++) {
        acc[nt][0] = __expf(acc[nt][0] - mx0); s0 += acc[nt][0];
        acc[nt][1] = __expf(acc[nt][1] - mx0); s0 += acc[nt][1];
        acc[nt][2] = __expf(acc[nt][2] - mx1); s1 += acc[nt][2];
        acc[nt][3] = __expf(acc[nt][3] - mx1); s1 += acc[nt][3];
    }
    acc[6][0] = __expf(acc[6][0] - mx0);
    acc[6][1] = __expf(acc[6][1] - mx0);
    acc[6][2] = __expf(acc[6][2] - mx1);
    acc[6][3] = __expf(acc[6][3] - mx1);
    if (tg == 3) { s0 += acc[6][1]; s1 += acc[6][3]; }   // col 48 only
    s0 += __shfl_xor_sync(0xffffffffu, s0, 1);
    s0 += __shfl_xor_sync(0xffffffffu, s0, 2);
    s1 += __shfl_xor_sync(0xffffffffu, s1, 1);
    s1 += __shfl_xor_sync(0xffffffffu, s1, 2);
    float inv0 = 1.f / s0, inv1 = 1.f / s1;
    #pragma unroll
    for (int nt = 0; nt < 7; nt++) {
        acc[nt][0] *= inv0; acc[nt][1] *= inv0;
        acc[nt][2] *= inv1; acc[nt][3] *= inv1;
    }

    // ---- out = att @ v : att repacked in-register as A frags ----
    float accv[4][4];
    #pragma unroll
    for (int dn = 0; dn < 4; dn++)
        #pragma unroll
        for (int e = 0; e < 4; e++) accv[dn][e] = 0.f;

    #pragma unroll
    for (int ks = 0; ks < 3; ks++) {
        uint32_t aH[4], aL[4];
        #pragma unroll
        for (int half = 0; half < 2; half++) {
            float* t = acc[2 * ks + half];
            float h0 = bf16rt(t[0]), h1 = bf16rt(t[1]);
            float h2 = bf16rt(t[2]), h3 = bf16rt(t[3]);
            aH[half ? 2 : 0] = pack_bf16x2(t[0], t[1]);
            aH[half ? 3 : 1] = pack_bf16x2(t[2], t[3]);
            aL[half ? 2 : 0] = pack_bf16x2(t[0] - h0, t[1] - h1);
            aL[half ? 3 : 1] = pack_bf16x2(t[2] - h2, t[3] - h3);
        }
        #pragma unroll
        for (int dn = 0; dn < 4; dn++) {
            const __nv_bfloat16* bh = vth + (h * 32 + dn * 8 + g) * VSTR + ks * 16 + 2 * tg;
            const __nv_bfloat16* bl = vtl + (h * 32 + dn * 8 + g) * VSTR + ks * 16 + 2 * tg;
            uint32_t bH[2] = {*(const uint32_t*)bh, *(const uint32_t*)(bh + 8)};
            uint32_t bL[2] = {*(const uint32_t*)bl, *(const uint32_t*)(bl + 8)};
            mma_bf16(accv[dn], aH, bH);
            mma_bf16(accv[dn], aH, bL);
            mma_bf16(accv[dn], aL, bH);
        }
    }
    // j = 48 via shfl + scalar FMA
    float a48a = __shfl_sync(0xffffffffu, acc[6][1], lane | 3);
    float a48b = __shfl_sync(0xffffffffu, acc[6][3], lane | 3);
    #pragma unroll
    for (int dn = 0; dn < 4; dn++) {
        int d0 = dn * 8 + 2 * tg;
        float v0 = __bfloat162float(vth[(h * 32 + d0) * VSTR + 48])
                 + __bfloat162float(vtl[(h * 32 + d0) * VSTR + 48]);
        float v1 = __bfloat162float(vth[(h * 32 + d0 + 1) * VSTR + 48])
                 + __bfloat162float(vtl[(h * 32 + d0 + 1) * VSTR + 48]);
        accv[dn][0] += a48a * v0; accv[dn][1] += a48a * v1;
        accv[dn][2] += a48b * v0; accv[dn][3] += a48b * v1;
    }

    // ---- staged, fully-coalesced window-major store of att hi/lo ----
    __syncthreads();                 // done with q/k/v smem
    __nv_bfloat16* stH = sqh;        // [49][STG]
    __nv_bfloat16* stL = sqh + 49 * STG;
    #pragma unroll
    for (int dn = 0; dn < 4; dn++) {
        int col = h * 32 + dn * 8 + 2 * tg;
        float e0 = bf16rt(accv[dn][0]), e1 = bf16rt(accv[dn][1]);
        float e2 = bf16rt(accv[dn][2]), e3 = bf16rt(accv[dn][3]);
        *(uint32_t*)(stH + r0 * STG + col) = pack_bf16x2(accv[dn][0], accv[dn][1]);
        *(uint32_t*)(stL + r0 * STG + col) = pack_bf16x2(accv[dn][0] - e0, accv[dn][1] - e1);
        *(uint32_t*)(stH + r1 * STG + col) = pack_bf16x2(accv[dn][2], accv[dn][3]);
        *(uint32_t*)(stL + r1 * STG + col) = pack_bf16x2(accv[dn][2] - e2, accv[dn][3] - e3);
    }
    __syncthreads();
    __nv_bfloat16* dstH = g_ah + (size_t)win * 49 * 96;
    __nv_bfloat16* dstL = g_al + (size_t)win * 49 * 96;
    for (int i = tid; i < 49 * 12; i += 384) {
        int t = i / 12, j8 = (i % 12) * 8;
        *(uint4*)(dstH + t * 96 + j8) = *(const uint4*)(stH + t * STG + j8);
        *(uint4*)(dstL + t * 96 + j8) = *(const uint4*)(stL + t * STG + j8);
    }
}

// ---------------- launch ----------------------------------------------------
extern "C" void kernel_launch(void* const* d_in, const int* in_sizes, int n_in,
                              void* d_out, int out_size)
{
    (void)in_sizes; (void)n_in; (void)out_size;
    const float* x     = (const float*)d_in[0];
    const float* w_qkv = (const float*)d_in[1];
    const float* b_qkv = (const float*)d_in[2];
    const float* rel   = (const float*)d_in[3];
    const float* w_out = (const float*)d_in[4];
    const float* b_out = (const float*)d_in[5];
    float* out = (float*)d_out;

    __nv_bfloat16 *ah, *al, *wqh, *wql, *woh, *wol;
    cudaGetSymbolAddress((void**)&ah, g_ah);   cudaGetSymbolAddress((void**)&al, g_al);
    cudaGetSymbolAddress((void**)&wqh, g_wqh); cudaGetSymbolAddress((void**)&wql, g_wql);
    cudaGetSymbolAddress((void**)&woh, g_woh); cudaGetSymbolAddress((void**)&wol, g_wol);

    cudaFuncSetAttribute(gemm_qkv, cudaFuncAttributeMaxDynamicSharedMemorySize, GEMM_SMEM);
    cudaFuncSetAttribute(gemm_out, cudaFuncAttributeMaxDynamicSharedMemorySize, GEMM_SMEM);
    cudaFuncSetAttribute(attn_mma, cudaFuncAttributeMaxDynamicSharedMemorySize, ATTN_SMEM);

    // 0) split weights (tiny)
    split_w<<<((QKV_N + 96) * 96 + 255) / 256, 256>>>(w_qkv, w_out);

    // 1) qkv = x @ w_qkv + b_qkv -> bf16 hi/lo window-major (staged stores)
    gemm_qkv<<<dim3(M_TOK / 128, 3), 256, GEMM_SMEM>>>(x, wqh, wql, b_qkv);

    // 2) windowed attention -> att hi/lo window-major (staged stores)
    attn_mma<<<4096, 384, ATTN_SMEM>>>(rel);

    // 3) out = att @ w_out + b_out -> fp32 spatial (staged scatter)
    gemm_out<<<M_TOK / 128, 256, GEMM_SMEM>>>(ah, al, woh, wol, b_out, out);
}

// round 12
// speedup vs baseline: 2.0287x; 1.1303x over previous
#include <cuda_runtime.h>
#include <cuda_bf16.h>
#include <cstdint>

#define QKV_N 288

// ---------------- scratch: weights only (allocation-free rule) -------------
__device__ __nv_bfloat16 g_wqh[QKV_N * 96], g_wql[QKV_N * 96]; // w_qkv^T [n][k]
__device__ __nv_bfloat16 g_woh[96 * 96],    g_wol[96 * 96];    // w_out^T [n][k]

__device__ __forceinline__ void mma_bf16(float* c, const uint32_t* a, const uint32_t* b) {
    asm("mma.sync.aligned.m16n8k16.row.col.f32.bf16.bf16.f32 "
        "{%0,%1,%2,%3}, {%4,%5,%6,%7}, {%8,%9}, {%0,%1,%2,%3};"
        : "+f"(c[0]), "+f"(c[1]), "+f"(c[2]), "+f"(c[3])
        : "r"(a[0]), "r"(a[1]), "r"(a[2]), "r"(a[3]), "r"(b[0]), "r"(b[1]));
}
__device__ __forceinline__ uint32_t pack_bf16x2(float lo, float hi) {
    uint32_t r;
    asm("cvt.rn.bf16x2.f32 %0, %1, %2;" : "=r"(r) : "f"(hi), "f"(lo));
    return r;
}
__device__ __forceinline__ float bf16rt(float x) {
    return __bfloat162float(__float2bfloat16(x));
}

// ---------------- prep: split weights -> bf16 hi/lo (transposed) -----------
__global__ void split_w(const float* __restrict__ wqkv, const float* __restrict__ wout) {
    int idx = blockIdx.x * 256 + threadIdx.x;
    if (idx < QKV_N * 96) {
        int n = idx / 96, k = idx % 96;
        float v = wqkv[k * QKV_N + n];
        __nv_bfloat16 h = __float2bfloat16(v);
        g_wqh[idx] = h;
        g_wql[idx] = __float2bfloat16(v - __bfloat162float(h));
    } else if (idx < QKV_N * 96 + 96 * 96) {
        int j = idx - QKV_N * 96;
        int n = j / 96, k = j % 96;
        float v = wout[k * 96 + n];
        __nv_bfloat16 h = __float2bfloat16(v);
        g_woh[j] = h;
        g_wol[j] = __float2bfloat16(v - __bfloat162float(h));
    }
}

// ---------------- fused per-window kernel -----------------------------------
// One block = one window.  384 threads = 12 warps = (m-tile 0..3) x (third 0..2)
// where "third" is the head for attention and the 32-col n-chunk for GEMMs.
// Phases: x gather -> qkv GEMM (3 weight chunks) -> attention -> out GEMM.
// All intermediates stay in smem; only x read and out written to gmem.
// smem offsets in bf16 units:
#define W_H   0                    // weight chunk hi [96][104]
#define W_L   9984                 // weight chunk lo
#define SQH_  19968                // q hi  [3][49][40]
#define SQL_  25848
#define SKH_  31728                // k hi
#define SKL_  37608
#define SVH_  43488                // v hi  [3][32][56] (transposed)
#define SVL_  48864
#define XAH_  54240                // x / att A-tile hi [49][104]
#define XAL_  59336
#define SREL_ 64432                // rel_pos, 507 floats
#define FUSED_SMEM ((64432 + 1014) * 2)   // 130,892 B
#define QSTR 40
#define VSTR 56
#define XSTR 104
#define WSTR 104

__global__ __launch_bounds__(384) void fused_win(
    const float* __restrict__ x, const float* __restrict__ b_qkv,
    const float* __restrict__ rel_pos, const float* __restrict__ b_out,
    float* __restrict__ out)
{
    extern __shared__ __nv_bfloat16 sb[];
    __shared__ int sg[49];
    float* srel = (float*)(sb + SREL_);

    const int tid = threadIdx.x, lane = tid & 31, warp = tid >> 5;
    const int g = lane >> 2, tg = lane & 3;
    const int mt = warp & 3, third = warp >> 2;          // head / n-chunk
    const int m0 = (mt == 3) ? 33 : mt * 16;
    const int r0 = m0 + g, r1 = m0 + 8 + g;
    const int win = blockIdx.x;                          // ((b*8)+hi)*8+wi
    const int wi = win & 7, hi2 = (win >> 3) & 7, bb2 = win >> 6;

    // ---- phase 0: token map, rel_pos, first weight chunk --------------------
    if (tid < 49) {
        int p = tid / 7, q = tid % 7;
        sg[tid] = (bb2 * 56 + p * 8 + hi2) * 56 + q * 8 + wi;
    }
    for (int i = tid; i < 507; i += 384) srel[i] = rel_pos[i];
    for (int i = tid; i < 96 * 12; i += 384) {
        int r = i / 12, k8 = (i % 12) * 8;
        *(uint4*)(sb + W_H + r * WSTR + k8) = *(const uint4*)(g_wqh + r * 96 + k8);
        *(uint4*)(sb + W_L + r * WSTR + k8) = *(const uint4*)(g_wql + r * 96 + k8);
    }
    __syncthreads();

    // ---- phase 1: gather x, split to bf16 hi/lo A-tile ----------------------
    for (int i = tid; i < 49 * 24; i += 384) {
        int t = i / 24, f4 = i % 24;
        float4 v = *(const float4*)(x + (size_t)sg[t] * 96 + f4 * 4);
        uint2 H, L;
        H.x = pack_bf16x2(v.x, v.y);
        H.y = pack_bf16x2(v.z, v.w);
        L.x = pack_bf16x2(v.x - bf16rt(v.x), v.y - bf16rt(v.y));
        L.y = pack_bf16x2(v.z - bf16rt(v.z), v.w - bf16rt(v.w));
        *(uint2*)(sb + XAH_ + t * XSTR + f4 * 4) = H;
        *(uint2*)(sb + XAL_ + t * XSTR + f4 * 4) = L;
    }

    // ---- phase 2: qkv projection, 3 sequential weight chunks ---------------
    for (int c = 0; c < 3; c++) {
        __syncthreads();           // c=0: A-tile+chunk0 ready; c>0: wbuf free
        if (c > 0) {
            for (int i = tid; i < 96 * 12; i += 384) {
                int r = i / 12, k8 = (i % 12) * 8;
                *(uint4*)(sb + W_H + r * WSTR + k8) = *(const uint4*)(g_wqh + (c * 96 + r) * 96 + k8);
                *(uint4*)(sb + W_L + r * WSTR + k8) = *(const uint4*)(g_wql + (c * 96 + r) * 96 + k8);
            }
            __syncthreads();
        }
        float acc[4][4];
        #pragma unroll
        for (int nt = 0; nt < 4; nt++)
            #pragma unroll
            for (int e = 0; e < 4; e++) acc[nt][e] = 0.f;
        #pragma unroll
        for (int ks = 0; ks < 6; ks++) {
            int cb = ks * 16 + 2 * tg;
            uint32_t aH[4], aL[4];
            aH[0] = *(const uint32_t*)(sb + XAH_ + r0 * XSTR + cb);
            aH[1] = *(const uint32_t*)(sb + XAH_ + r1 * XSTR + cb);
            aH[2] = *(const uint32_t*)(sb + XAH_ + r0 * XSTR + cb + 8);
            aH[3] = *(const uint32_t*)(sb + XAH_ + r1 * XSTR + cb + 8);
            aL[0] = *(const uint32_t*)(sb + XAL_ + r0 * XSTR + cb);
            aL[1] = *(const uint32_t*)(sb + XAL_ + r1 * XSTR + cb);
            aL[2] = *(const uint32_t*)(sb + XAL_ + r0 * XSTR + cb + 8);
            aL[3] = *(const uint32_t*)(sb + XAL_ + r1 * XSTR + cb + 8);
            #pragma unroll
            for (int nt = 0; nt < 4; nt++) {
                int rn = third * 32 + nt * 8 + g;
                uint32_t bH[2] = {*(const uint32_t*)(sb + W_H + rn * WSTR + cb),
                                  *(const uint32_t*)(sb + W_H + rn * WSTR + cb + 8)};
                uint32_t bL[2] = {*(const uint32_t*)(sb + W_L + rn * WSTR + cb),
                                  *(const uint32_t*)(sb + W_L + rn * WSTR + cb + 8)};
                mma_bf16(acc[nt], aH, bH);
                mma_bf16(acc[nt], aH, bL);
                mma_bf16(acc[nt], aL, bH);
            }
        }
        // writeback: +bias, split hi/lo, into attention layouts
        if (c < 2) {
            __nv_bfloat16* dH = sb + (c ? SKH_ : SQH_);
            __nv_bfloat16* dL = sb + (c ? SKL_ : SQL_);
            #pragma unroll
            for (int nt = 0; nt < 4; nt++) {
                int col = nt * 8 + 2 * tg;
                float2 bbv = *(const float2*)(b_qkv + c * 96 + third * 32 + col);
                float v0 = acc[nt][0] + bbv.x, v1 = acc[nt][1] + bbv.y;
                float v2 = acc[nt][2] + bbv.x, v3 = acc[nt][3] + bbv.y;
                *(uint32_t*)(dH + (third * 49 + r0) * QSTR + col) = pack_bf16x2(v0, v1);
                *(uint32_t*)(dL + (third * 49 + r0) * QSTR + col) =
                    pack_bf16x2(v0 - bf16rt(v0), v1 - bf16rt(v1));
                *(uint32_t*)(dH + (third * 49 + r1) * QSTR + col) = pack_bf16x2(v2, v3);
                *(uint32_t*)(dL + (third * 49 + r1) * QSTR + col) =
                    pack_bf16x2(v2 - bf16rt(v2), v3 - bf16rt(v3));
            }
        } else {
            __nv_bfloat16* vth = sb + SVH_;
            __nv_bfloat16* vtl = sb + SVL_;
            #pragma unroll
            for (int nt = 0; nt < 4; nt++) {
                int dd = nt * 8 + 2 * tg;
                float2 bbv = *(const float2*)(b_qkv + 192 + third * 32 + dd);
                float v0 = acc[nt][0] + bbv.x, v1 = acc[nt][1] + bbv.y;
                float v2 = acc[nt][2] + bbv.x, v3 = acc[nt][3] + bbv.y;
                int base0 = (third * 32 + dd) * VSTR, base1 = base0 + VSTR;
                vth[base0 + r0] = __float2bfloat16(v0);
                vtl[base0 + r0] = __float2bfloat16(v0 - bf16rt(v0));
                vth[base1 + r0] = __float2bfloat16(v1);
                vtl[base1 + r0] = __float2bfloat16(v1 - bf16rt(v1));
                vth[base0 + r1] = __float2bfloat16(v2);
                vtl[base0 + r1] = __float2bfloat16(v2 - bf16rt(v2));
                vth[base1 + r1] = __float2bfloat16(v3);
                vtl[base1 + r1] = __float2bfloat16(v3 - bf16rt(v3));
            }
        }
    }
    __syncthreads();

    // ---- prefetch w_out into wbuf (overlaps attention compute) -------------
    for (int i = tid; i < 96 * 12; i += 384) {
        int r = i / 12, k8 = (i % 12) * 8;
        *(uint4*)(sb + W_H + r * WSTR + k8) = *(const uint4*)(g_woh + r * 96 + k8);
        *(uint4*)(sb + W_L + r * WSTR + k8) = *(const uint4*)(g_wol + r * 96 + k8);
    }

    // ---- phase 3: attention (register-resident sim/att) --------------------
    {
        const int h = third;
        const int n0tab[7] = {0, 8, 16, 24, 32, 40, 41};
        const float scale = 0.17677669529663687f;   // 32^-0.5
        const __nv_bfloat16* qh = sb + SQH_ + h * 49 * QSTR;
        const __nv_bfloat16* ql = sb + SQL_ + h * 49 * QSTR;
        const __nv_bfloat16* kh = sb + SKH_ + h * 49 * QSTR;
        const __nv_bfloat16* kl = sb + SKL_ + h * 49 * QSTR;
        const __nv_bfloat16* vth = sb + SVH_;
        const __nv_bfloat16* vtl = sb + SVL_;

        float acc[7][4];
        #pragma unroll
        for (int nt = 0; nt < 7; nt++)
            #pragma unroll
            for (int e = 0; e < 4; e++) acc[nt][e] = 0.f;

        #pragma unroll
        for (int ks = 0; ks < 2; ks++) {
            const int kb = ks * 16 + 2 * tg;
            uint32_t aH[4], aL[4];
            aH[0] = *(const uint32_t*)(qh + r0 * QSTR + kb);
            aH[1] = *(const uint32_t*)(qh + r1 * QSTR + kb);
            aH[2] = *(const uint32_t*)(qh + r0 * QSTR + kb + 8);
            aH[3] = *(const uint32_t*)(qh + r1 * QSTR + kb + 8);
            aL[0] = *(const uint32_t*)(ql + r0 * QSTR + kb);
            aL[1] = *(const uint32_t*)(ql + r1 * QSTR + kb);
            aL[2] = *(const uint32_t*)(ql + r0 * QSTR + kb + 8);
            aL[3] = *(const uint32_t*)(ql + r1 * QSTR + kb + 8);
            #pragma unroll
            for (int nt = 0; nt < 7; nt++) {
                int rn = n0tab[nt] + g;
                uint32_t bH[2] = {*(const uint32_t*)(kh + rn * QSTR + kb),
                                  *(const uint32_t*)(kh + rn * QSTR + kb + 8)};
                uint32_t bL[2] = {*(const uint32_t*)(kl + rn * QSTR + kb),
                                  *(const uint32_t*)(kl + rn * QSTR + kb + 8)};
                mma_bf16(acc[nt], aH, bH);
                mma_bf16(acc[nt], aH, bL);
                mma_bf16(acc[nt], aL, bH);
            }
        }

        // scale + rel-pos bias
        {
            const float* relh = srel + h * 169;
            int pi0 = r0 / 7, qi0 = r0 % 7, pi1 = r1 / 7, qi1 = r1 % 7;
            #pragma unroll
            for (int nt = 0; nt < 7; nt++) {
                int j0 = n0tab[nt] + 2 * tg, j1 = j0 + 1;
                int pj0 = j0 / 7, qj0 = j0 % 7, pj1 = j1 / 7, qj1 = j1 % 7;
                acc[nt][0] = fmaf(acc[nt][0], scale, relh[(pi0 - pj0 + 6) * 13 + (qi0 - qj0 + 6)]);
                acc[nt][1] = fmaf(acc[nt][1], scale, relh[(pi0 - pj1 + 6) * 13 + (qi0 - qj1 + 6)]);
                acc[nt][2] = fmaf(acc[nt][2], scale, relh[(pi1 - pj0 + 6) * 13 + (qi1 - qj0 + 6)]);
                acc[nt][3] = fmaf(acc[nt][3], scale, relh[(pi1 - pj1 + 6) * 13 + (qi1 - qj1 + 6)]);
            }
        }

        // softmax (dup col 41..47 of overlap tile excluded from sums)
        float mx0 = -1e30f, mx1 = -1e30f;
        #pragma unroll
        for (int nt = 0; nt < 7; nt++) {
            mx0 = fmaxf(mx0, fmaxf(acc[nt][0], acc[nt][1]));
            mx1 = fmaxf(mx1, fmaxf(acc[nt][2], acc[nt][3]));
        }
        mx0 = fmaxf(mx0, __shfl_xor_sync(0xffffffffu, mx0, 1));
        mx0 = fmaxf(mx0, __shfl_xor_sync(0xffffffffu, mx0, 2));
        mx1 = fmaxf(mx1, __shfl_xor_sync(0xffffffffu, mx1, 1));
        mx1 = fmaxf(mx1, __shfl_xor_sync(0xffffffffu, mx1, 2));
        float s0 = 0.f, s1 = 0.f;
        #pragma unroll
        for (int nt = 0; nt < 6; nt++) {
            acc[nt][0] = __expf(acc[nt][0] - mx0); s0 += acc[nt][0];
            acc[nt][1] = __expf(acc[nt][1] - mx0); s0 += acc[nt][1];
            acc[nt][2] = __expf(acc[nt][2] - mx1); s1 += acc[nt][2];
            acc[nt][3] = __expf(acc[nt][3] - mx1); s1 += acc[nt][3];
        }
        acc[6][0] = __expf(acc[6][0] - mx0);
        acc[6][1] = __expf(acc[6][1] - mx0);
        acc[6][2] = __expf(acc[6][2] - mx1);
        acc[6][3] = __expf(acc[6][3] - mx1);
        if (tg == 3) { s0 += acc[6][1]; s1 += acc[6][3]; }   // col 48
        s0 += __shfl_xor_sync(0xffffffffu, s0, 1);
        s0 += __shfl_xor_sync(0xffffffffu, s0, 2);
        s1 += __shfl_xor_sync(0xffffffffu, s1, 1);
        s1 += __shfl_xor_sync(0xffffffffu, s1, 2);
        float inv0 = 1.f / s0, inv1 = 1.f / s1;
        #pragma unroll
        for (int nt = 0; nt < 7; nt++) {
            acc[nt][0] *= inv0; acc[nt][1] *= inv0;
            acc[nt][2] *= inv1; acc[nt][3] *= inv1;
        }

        // out = att @ v
        float accv[4][4];
        #pragma unroll
        for (int dn = 0; dn < 4; dn++)
            #pragma unroll
            for (int e = 0; e < 4; e++) accv[dn][e] = 0.f;
        #pragma unroll
        for (int ks = 0; ks < 3; ks++) {
            uint32_t aH[4], aL[4];
            #pragma unroll
            for (int half = 0; half < 2; half++) {
                float* t = acc[2 * ks + half];
                float h0 = bf16rt(t[0]), h1 = bf16rt(t[1]);
                float h2 = bf16rt(t[2]), h3 = bf16rt(t[3]);
                aH[half ? 2 : 0] = pack_bf16x2(t[0], t[1]);
                aH[half ? 3 : 1] = pack_bf16x2(t[2], t[3]);
                aL[half ? 2 : 0] = pack_bf16x2(t[0] - h0, t[1] - h1);
                aL[half ? 3 : 1] = pack_bf16x2(t[2] - h2, t[3] - h3);
            }
            #pragma unroll
            for (int dn = 0; dn < 4; dn++) {
                const __nv_bfloat16* bh = vth + (h * 32 + dn * 8 + g) * VSTR + ks * 16 + 2 * tg;
                const __nv_bfloat16* bl = vtl + (h * 32 + dn * 8 + g) * VSTR + ks * 16 + 2 * tg;
                uint32_t bH[2] = {*(const uint32_t*)bh, *(const uint32_t*)(bh + 8)};
                uint32_t bL[2] = {*(const uint32_t*)bl, *(const uint32_t*)(bl + 8)};
                mma_bf16(accv[dn], aH, bH);
                mma_bf16(accv[dn], aH, bL);
                mma_bf16(accv[dn], aL, bH);
            }
        }
        float a48a = __shfl_sync(0xffffffffu, acc[6][1], lane | 3);
        float a48b = __shfl_sync(0xffffffffu, acc[6][3], lane | 3);
        #pragma unroll
        for (int dn = 0; dn < 4; dn++) {
            int d0 = dn * 8 + 2 * tg;
            float v0 = __bfloat162float(vth[(h * 32 + d0) * VSTR + 48])
                     + __bfloat162float(vtl[(h * 32 + d0) * VSTR + 48]);
            float v1 = __bfloat162float(vth[(h * 32 + d0 + 1) * VSTR + 48])
                     + __bfloat162float(vtl[(h * 32 + d0 + 1) * VSTR + 48]);
            accv[dn][0] += a48a * v0; accv[dn][1] += a48a * v1;
            accv[dn][2] += a48b * v0; accv[dn][3] += a48b * v1;
        }

        // att output -> A-tile (x is dead), bf16 hi/lo
        #pragma unroll
        for (int dn = 0; dn < 4; dn++) {
            int col = h * 32 + dn * 8 + 2 * tg;
            float e0 = bf16rt(accv[dn][0]), e1 = bf16rt(accv[dn][1]);
            float e2 = bf16rt(accv[dn][2]), e3 = bf16rt(accv[dn][3]);
            *(uint32_t*)(sb + XAH_ + r0 * XSTR + col) = pack_bf16x2(accv[dn][0], accv[dn][1]);
            *(uint32_t*)(sb + XAL_ + r0 * XSTR + col) = pack_bf16x2(accv[dn][0] - e0, accv[dn][1] - e1);
            *(uint32_t*)(sb + XAH_ + r1 * XSTR + col) = pack_bf16x2(accv[dn][2], accv[dn][3]);
            *(uint32_t*)(sb + XAL_ + r1 * XSTR + col) = pack_bf16x2(accv[dn][2] - e2, accv[dn][3] - e3);
        }
    }
    __syncthreads();

    // ---- phase 4: out projection -------------------------------------------
    float acc2[4][4];
    #pragma unroll
    for (int nt = 0; nt < 4; nt++)
        #pragma unroll
        for (int e = 0; e < 4; e++) acc2[nt][e] = 0.f;
    #pragma unroll
    for (int ks = 0; ks < 6; ks++) {
        int cb = ks * 16 + 2 * tg;
        uint32_t aH[4], aL[4];
        aH[0] = *(const uint32_t*)(sb + XAH_ + r0 * XSTR + cb);
        aH[1] = *(const uint32_t*)(sb + XAH_ + r1 * XSTR + cb);
        aH[2] = *(const uint32_t*)(sb + XAH_ + r0 * XSTR + cb + 8);
        aH[3] = *(const uint32_t*)(sb + XAH_ + r1 * XSTR + cb + 8);
        aL[0] = *(const uint32_t*)(sb + XAL_ + r0 * XSTR + cb);
        aL[1] = *(const uint32_t*)(sb + XAL_ + r1 * XSTR + cb);
        aL[2] = *(const uint32_t*)(sb + XAL_ + r0 * XSTR + cb + 8);
        aL[3] = *(const uint32_t*)(sb + XAL_ + r1 * XSTR + cb + 8);
        #pragma unroll
        for (int nt = 0; nt < 4; nt++) {
            int rn = third * 32 + nt * 8 + g;
            uint32_t bH[2] = {*(const uint32_t*)(sb + W_H + rn * WSTR + cb),
                              *(const uint32_t*)(sb + W_H + rn * WSTR + cb + 8)};
            uint32_t bL[2] = {*(const uint32_t*)(sb + W_L + rn * WSTR + cb),
                              *(const uint32_t*)(sb + W_L + rn * WSTR + cb + 8)};
            mma_bf16(acc2[nt], aH, bH);
            mma_bf16(acc2[nt], aH, bL);
            mma_bf16(acc2[nt], aL, bH);
        }
    }
    __syncthreads();

    // ---- phase 5: staged fp32 epilogue, coalesced spatial scatter ----------
    float* st = (float*)sb;                  // reuse wbuf region, [49][100]
    #pragma unroll
    for (int nt = 0; nt < 4; nt++) {
        int col = third * 32 + nt * 8 + 2 * tg;
        float2 bo = *(const float2*)(b_out + col);
        *(float2*)(st + r0 * 100 + col) = make_float2(acc2[nt][0] + bo.x, acc2[nt][1] + bo.y);
        *(float2*)(st + r1 * 100 + col) = make_float2(acc2[nt][2] + bo.x, acc2[nt][3] + bo.y);
    }
    __syncthreads();
    for (int i = tid; i < 49 * 24; i += 384) {
        int t = i / 24, f4 = i % 24;
        *(float4*)(out + (size_t)sg[t] * 96 + f4 * 4) = *(const float4*)(st + t * 100 + f4 * 4);
    }
}

// ---------------- launch ----------------------------------------------------
extern "C" void kernel_launch(void* const* d_in, const int* in_sizes, int n_in,
                              void* d_out, int out_size)
{
    (void)in_sizes; (void)n_in; (void)out_size;
    const float* x     = (const float*)d_in[0];
    const float* w_qkv = (const float*)d_in[1];
    const float* b_qkv = (const float*)d_in[2];
    const float* rel   = (const float*)d_in[3];
    const float* w_out = (const float*)d_in[4];
    const float* b_out = (const float*)d_in[5];
    float* out = (float*)d_out;

    cudaFuncSetAttribute(fused_win, cudaFuncAttributeMaxDynamicSharedMemorySize, FUSED_SMEM);

    // 0) split weights into bf16 hi/lo (transposed [n][k])
    split_w<<<((QKV_N + 96) * 96 + 255) / 256, 256>>>(w_qkv, w_out);

    // 1) fused qkv-projection + attention + out-projection, one block/window
    fused_win<<<4096, 384, FUSED_SMEM>>>(x, b_qkv, rel, b_out, out);
}

// round 13
// speedup vs baseline: 2.5913x; 1.2773x over previous
#include <cuda_runtime.h>
#include <cuda_bf16.h>
#include <cstdint>

#define QKV_N 288

// ---------------- scratch: weights only (allocation-free rule) -------------
__device__ __nv_bfloat16 g_wqh[QKV_N * 96], g_wql[QKV_N * 96]; // w_qkv^T [n][k]
__device__ __nv_bfloat16 g_woh[96 * 96],    g_wol[96 * 96];    // w_out^T [n][k]

__device__ __forceinline__ void mma_bf16(float* c, const uint32_t* a, const uint32_t* b) {
    asm("mma.sync.aligned.m16n8k16.row.col.f32.bf16.bf16.f32 "
        "{%0,%1,%2,%3}, {%4,%5,%6,%7}, {%8,%9}, {%0,%1,%2,%3};"
        : "+f"(c[0]), "+f"(c[1]), "+f"(c[2]), "+f"(c[3])
        : "r"(a[0]), "r"(a[1]), "r"(a[2]), "r"(a[3]), "r"(b[0]), "r"(b[1]));
}
__device__ __forceinline__ uint32_t pack_bf16x2(float lo, float hi) {
    uint32_t r;
    asm("cvt.rn.bf16x2.f32 %0, %1, %2;" : "=r"(r) : "f"(hi), "f"(lo));
    return r;
}
__device__ __forceinline__ float bf16rt(float x) {
    return __bfloat162float(__float2bfloat16(x));
}

// ---------------- prep: split weights -> bf16 hi/lo (transposed) -----------
__global__ void split_w(const float* __restrict__ wqkv, const float* __restrict__ wout) {
    int idx = blockIdx.x * 256 + threadIdx.x;
    if (idx < QKV_N * 96) {
        int n = idx / 96, k = idx % 96;
        float v = wqkv[k * QKV_N + n];
        __nv_bfloat16 h = __float2bfloat16(v);
        g_wqh[idx] = h;
        g_wql[idx] = __float2bfloat16(v - __bfloat162float(h));
    } else if (idx < QKV_N * 96 + 96 * 96) {
        int j = idx - QKV_N * 96;
        int n = j / 96, k = j % 96;
        float v = wout[k * 96 + n];
        __nv_bfloat16 h = __float2bfloat16(v);
        g_woh[j] = h;
        g_wol[j] = __float2bfloat16(v - __bfloat162float(h));
    }
}

// ---------------- fused kernel: TWO windows per block -----------------------
// 768 threads = 24 warps = (window 0/1) x (m-tile 0..3) x (head/n-chunk 0..2).
// Weight chunk buffer + rel_pos shared between the two windows; per-window
// q/k/v/A-tile state.  smem = 40KB weights + 2KB rel + 2 x 89KB = ~220KB.
// smem offsets in bf16 units:
#define W_H   0                    // weight chunk hi [96][104]
#define W_L   9984                 // weight chunk lo
#define WBASE 19968                // per-window region start
#define PERWIN 44464               // per-window size (bf16 units)
#define SQH_  0                    // q hi  [3][49][40]
#define SQL_  5880
#define SKH_  11760                // k hi
#define SKL_  17640
#define SVH_  23520                // v hi [3][32][56] (transposed)
#define SVL_  28896
#define XAH_  34272                // x / att A-tile hi [49][104]
#define XAL_  39368
#define SREL_ (WBASE + 2 * PERWIN) // 108896 (even -> float-aligned)
#define FUSED_SMEM ((SREL_ + 1014) * 2)   // 219,820 B
#define QSTR 40
#define VSTR 56
#define XSTR 104
#define WSTR 104

__global__ __launch_bounds__(768) void fused_win2(
    const float* __restrict__ x, const float* __restrict__ b_qkv,
    const float* __restrict__ rel_pos, const float* __restrict__ b_out,
    float* __restrict__ out)
{
    extern __shared__ __nv_bfloat16 sb[];
    __shared__ int sg[2][49];
    float* srel = (float*)(sb + SREL_);

    const int tid = threadIdx.x, lane = tid & 31, warp = tid >> 5;
    const int w = warp / 12, wl = warp - w * 12;         // window, warp-in-window
    const int wtid = tid - w * 384;
    const int g = lane >> 2, tg = lane & 3;
    const int mt = wl & 3, third = wl >> 2;              // head / n-chunk
    const int m0 = (mt == 3) ? 33 : mt * 16;
    const int r0 = m0 + g, r1 = m0 + 8 + g;
    const int win = blockIdx.x * 2 + w;                  // ((b*8)+hi)*8+wi
    __nv_bfloat16* sw = sb + WBASE + w * PERWIN;         // per-window region

    // ---- phase 0: token maps (both windows), rel_pos, first weight chunk ---
    if (tid < 98) {
        int ww = tid / 49, t = tid - ww * 49;
        int wx = blockIdx.x * 2 + ww;
        int wwi = wx & 7, whi = (wx >> 3) & 7, wb = wx >> 6;
        int p = t / 7, q = t % 7;
        sg[ww][t] = (wb * 56 + p * 8 + whi) * 56 + q * 8 + wwi;
    }
    for (int i = tid; i < 507; i += 768) srel[i] = rel_pos[i];
    for (int i = tid; i < 96 * 12; i += 768) {
        int r = i / 12, k8 = (i % 12) * 8;
        *(uint4*)(sb + W_H + r * WSTR + k8) = *(const uint4*)(g_wqh + r * 96 + k8);
        *(uint4*)(sb + W_L + r * WSTR + k8) = *(const uint4*)(g_wql + r * 96 + k8);
    }
    __syncthreads();

    // ---- phase 1: gather x, split to bf16 hi/lo A-tile ----------------------
    for (int i = wtid; i < 49 * 24; i += 384) {
        int t = i / 24, f4 = i % 24;
        float4 v = *(const float4*)(x + (size_t)sg[w][t] * 96 + f4 * 4);
        uint2 H, L;
        H.x = pack_bf16x2(v.x, v.y);
        H.y = pack_bf16x2(v.z, v.w);
        L.x = pack_bf16x2(v.x - bf16rt(v.x), v.y - bf16rt(v.y));
        L.y = pack_bf16x2(v.z - bf16rt(v.z), v.w - bf16rt(v.w));
        *(uint2*)(sw + XAH_ + t * XSTR + f4 * 4) = H;
        *(uint2*)(sw + XAL_ + t * XSTR + f4 * 4) = L;
    }

    // ---- phase 2: qkv projection, 3 sequential weight chunks ---------------
    for (int c = 0; c < 3; c++) {
        __syncthreads();           // c=0: A-tile+chunk0 ready; c>0: wbuf free
        if (c > 0) {
            for (int i = tid; i < 96 * 12; i += 768) {
                int r = i / 12, k8 = (i % 12) * 8;
                *(uint4*)(sb + W_H + r * WSTR + k8) = *(const uint4*)(g_wqh + (c * 96 + r) * 96 + k8);
                *(uint4*)(sb + W_L + r * WSTR + k8) = *(const uint4*)(g_wql + (c * 96 + r) * 96 + k8);
            }
            __syncthreads();
        }
        float acc[4][4];
        #pragma unroll
        for (int nt = 0; nt < 4; nt++)
            #pragma unroll
            for (int e = 0; e < 4; e++) acc[nt][e] = 0.f;
        #pragma unroll
        for (int ks = 0; ks < 6; ks++) {
            int cb = ks * 16 + 2 * tg;
            uint32_t aH[4], aL[4];
            aH[0] = *(const uint32_t*)(sw + XAH_ + r0 * XSTR + cb);
            aH[1] = *(const uint32_t*)(sw + XAH_ + r1 * XSTR + cb);
            aH[2] = *(const uint32_t*)(sw + XAH_ + r0 * XSTR + cb + 8);
            aH[3] = *(const uint32_t*)(sw + XAH_ + r1 * XSTR + cb + 8);
            aL[0] = *(const uint32_t*)(sw + XAL_ + r0 * XSTR + cb);
            aL[1] = *(const uint32_t*)(sw + XAL_ + r1 * XSTR + cb);
            aL[2] = *(const uint32_t*)(sw + XAL_ + r0 * XSTR + cb + 8);
            aL[3] = *(const uint32_t*)(sw + XAL_ + r1 * XSTR + cb + 8);
            #pragma unroll
            for (int nt = 0; nt < 4; nt++) {
                int rn = third * 32 + nt * 8 + g;
                uint32_t bH[2] = {*(const uint32_t*)(sb + W_H + rn * WSTR + cb),
                                  *(const uint32_t*)(sb + W_H + rn * WSTR + cb + 8)};
                uint32_t bL[2] = {*(const uint32_t*)(sb + W_L + rn * WSTR + cb),
                                  *(const uint32_t*)(sb + W_L + rn * WSTR + cb + 8)};
                mma_bf16(acc[nt], aH, bH);
                mma_bf16(acc[nt], aH, bL);
                mma_bf16(acc[nt], aL, bH);
            }
        }
        // writeback: +bias, split hi/lo, into attention layouts
        if (c < 2) {
            __nv_bfloat16* dH = sw + (c ? SKH_ : SQH_);
            __nv_bfloat16* dL = sw + (c ? SKL_ : SQL_);
            #pragma unroll
            for (int nt = 0; nt < 4; nt++) {
                int col = nt * 8 + 2 * tg;
                float2 bbv = *(const float2*)(b_qkv + c * 96 + third * 32 + col);
                float v0 = acc[nt][0] + bbv.x, v1 = acc[nt][1] + bbv.y;
                float v2 = acc[nt][2] + bbv.x, v3 = acc[nt][3] + bbv.y;
                *(uint32_t*)(dH + (third * 49 + r0) * QSTR + col) = pack_bf16x2(v0, v1);
                *(uint32_t*)(dL + (third * 49 + r0) * QSTR + col) =
                    pack_bf16x2(v0 - bf16rt(v0), v1 - bf16rt(v1));
                *(uint32_t*)(dH + (third * 49 + r1) * QSTR + col) = pack_bf16x2(v2, v3);
                *(uint32_t*)(dL + (third * 49 + r1) * QSTR + col) =
                    pack_bf16x2(v2 - bf16rt(v2), v3 - bf16rt(v3));
            }
        } else {
            __nv_bfloat16* vth = sw + SVH_;
            __nv_bfloat16* vtl = sw + SVL_;
            #pragma unroll
            for (int nt = 0; nt < 4; nt++) {
                int dd = nt * 8 + 2 * tg;
                float2 bbv = *(const float2*)(b_qkv + 192 + third * 32 + dd);
                float v0 = acc[nt][0] + bbv.x, v1 = acc[nt][1] + bbv.y;
                float v2 = acc[nt][2] + bbv.x, v3 = acc[nt][3] + bbv.y;
                int base0 = (third * 32 + dd) * VSTR, base1 = base0 + VSTR;
                vth[base0 + r0] = __float2bfloat16(v0);
                vtl[base0 + r0] = __float2bfloat16(v0 - bf16rt(v0));
                vth[base1 + r0] = __float2bfloat16(v1);
                vtl[base1 + r0] = __float2bfloat16(v1 - bf16rt(v1));
                vth[base0 + r1] = __float2bfloat16(v2);
                vtl[base0 + r1] = __float2bfloat16(v2 - bf16rt(v2));
                vth[base1 + r1] = __float2bfloat16(v3);
                vtl[base1 + r1] = __float2bfloat16(v3 - bf16rt(v3));
            }
        }
    }
    __syncthreads();

    // ---- prefetch w_out into wbuf (overlaps attention compute) -------------
    for (int i = tid; i < 96 * 12; i += 768) {
        int r = i / 12, k8 = (i % 12) * 8;
        *(uint4*)(sb + W_H + r * WSTR + k8) = *(const uint4*)(g_woh + r * 96 + k8);
        *(uint4*)(sb + W_L + r * WSTR + k8) = *(const uint4*)(g_wol + r * 96 + k8);
    }

    // ---- phase 3: attention (register-resident sim/att) --------------------
    {
        const int h = third;
        const int n0tab[7] = {0, 8, 16, 24, 32, 40, 41};
        const float scale = 0.17677669529663687f;   // 32^-0.5
        const __nv_bfloat16* qh = sw + SQH_ + h * 49 * QSTR;
        const __nv_bfloat16* ql = sw + SQL_ + h * 49 * QSTR;
        const __nv_bfloat16* kh = sw + SKH_ + h * 49 * QSTR;
        const __nv_bfloat16* kl = sw + SKL_ + h * 49 * QSTR;
        const __nv_bfloat16* vth = sw + SVH_;
        const __nv_bfloat16* vtl = sw + SVL_;

        float acc[7][4];
        #pragma unroll
        for (int nt = 0; nt < 7; nt++)
            #pragma unroll
            for (int e = 0; e < 4; e++) acc[nt][e] = 0.f;

        #pragma unroll
        for (int ks = 0; ks < 2; ks++) {
            const int kb = ks * 16 + 2 * tg;
            uint32_t aH[4], aL[4];
            aH[0] = *(const uint32_t*)(qh + r0 * QSTR + kb);
            aH[1] = *(const uint32_t*)(qh + r1 * QSTR + kb);
            aH[2] = *(const uint32_t*)(qh + r0 * QSTR + kb + 8);
            aH[3] = *(const uint32_t*)(qh + r1 * QSTR + kb + 8);
            aL[0] = *(const uint32_t*)(ql + r0 * QSTR + kb);
            aL[1] = *(const uint32_t*)(ql + r1 * QSTR + kb);
            aL[2] = *(const uint32_t*)(ql + r0 * QSTR + kb + 8);
            aL[3] = *(const uint32_t*)(ql + r1 * QSTR + kb + 8);
            #pragma unroll
            for (int nt = 0; nt < 7; nt++) {
                int rn = n0tab[nt] + g;
                uint32_t bH[2] = {*(const uint32_t*)(kh + rn * QSTR + kb),
                                  *(const uint32_t*)(kh + rn * QSTR + kb + 8)};
                uint32_t bL[2] = {*(const uint32_t*)(kl + rn * QSTR + kb),
                                  *(const uint32_t*)(kl + rn * QSTR + kb + 8)};
                mma_bf16(acc[nt], aH, bH);
                mma_bf16(acc[nt], aH, bL);
                mma_bf16(acc[nt], aL, bH);
            }
        }

        // scale + rel-pos bias
        {
            const float* relh = srel + h * 169;
            int pi0 = r0 / 7, qi0 = r0 % 7, pi1 = r1 / 7, qi1 = r1 % 7;
            #pragma unroll
            for (int nt = 0; nt < 7; nt++) {
                int j0 = n0tab[nt] + 2 * tg, j1 = j0 + 1;
                int pj0 = j0 / 7, qj0 = j0 % 7, pj1 = j1 / 7, qj1 = j1 % 7;
                acc[nt][0] = fmaf(acc[nt][0], scale, relh[(pi0 - pj0 + 6) * 13 + (qi0 - qj0 + 6)]);
                acc[nt][1] = fmaf(acc[nt][1], scale, relh[(pi0 - pj1 + 6) * 13 + (qi0 - qj1 + 6)]);
                acc[nt][2] = fmaf(acc[nt][2], scale, relh[(pi1 - pj0 + 6) * 13 + (qi1 - qj0 + 6)]);
                acc[nt][3] = fmaf(acc[nt][3], scale, relh[(pi1 - pj1 + 6) * 13 + (qi1 - qj1 + 6)]);
            }
        }

        // softmax (dup cols of overlap tile excluded from sums)
        float mx0 = -1e30f, mx1 = -1e30f;
        #pragma unroll
        for (int nt = 0; nt < 7; nt++) {
            mx0 = fmaxf(mx0, fmaxf(acc[nt][0], acc[nt][1]));
            mx1 = fmaxf(mx1, fmaxf(acc[nt][2], acc[nt][3]));
        }
        mx0 = fmaxf(mx0, __shfl_xor_sync(0xffffffffu, mx0, 1));
        mx0 = fmaxf(mx0, __shfl_xor_sync(0xffffffffu, mx0, 2));
        mx1 = fmaxf(mx1, __shfl_xor_sync(0xffffffffu, mx1, 1));
        mx1 = fmaxf(mx1, __shfl_xor_sync(0xffffffffu, mx1, 2));
        float s0 = 0.f, s1 = 0.f;
        #pragma unroll
        for (int nt = 0; nt < 6; nt++) {
            acc[nt][0] = __expf(acc[nt][0] - mx0); s0 += acc[nt][0];
            acc[nt][1] = __expf(acc[nt][1] - mx0); s0 += acc[nt][1];
            acc[nt][2] = __expf(acc[nt][2] - mx1); s1 += acc[nt][2];
            acc[nt][3] = __expf(acc[nt][3] - mx1); s1 += acc[nt][3];
        }
        acc[6][0] = __expf(acc[6][0] - mx0);
        acc[6][1] = __expf(acc[6][1] - mx0);
        acc[6][2] = __expf(acc[6][2] - mx1);
        acc[6][3] = __expf(acc[6][3] - mx1);
        if (tg == 3) { s0 += acc[6][1]; s1 += acc[6][3]; }   // col 48
        s0 += __shfl_xor_sync(0xffffffffu, s0, 1);
        s0 += __shfl_xor_sync(0xffffffffu, s0, 2);
        s1 += __shfl_xor_sync(0xffffffffu, s1, 1);
        s1 += __shfl_xor_sync(0xffffffffu, s1, 2);
        float inv0 = 1.f / s0, inv1 = 1.f / s1;
        #pragma unroll
        for (int nt = 0; nt < 7; nt++) {
            acc[nt][0] *= inv0; acc[nt][1] *= inv0;
            acc[nt][2] *= inv1; acc[nt][3] *= inv1;
        }

        // out = att @ v
        float accv[4][4];
        #pragma unroll
        for (int dn = 0; dn < 4; dn++)
            #pragma unroll
            for (int e = 0; e < 4; e++) accv[dn][e] = 0.f;
        #pragma unroll
        for (int ks = 0; ks < 3; ks++) {
            uint32_t aH[4], aL[4];
            #pragma unroll
            for (int half = 0; half < 2; half++) {
                float* t = acc[2 * ks + half];
                float h0 = bf16rt(t[0]), h1 = bf16rt(t[1]);
                float h2 = bf16rt(t[2]), h3 = bf16rt(t[3]);
                aH[half ? 2 : 0] = pack_bf16x2(t[0], t[1]);
                aH[half ? 3 : 1] = pack_bf16x2(t[2], t[3]);
                aL[half ? 2 : 0] = pack_bf16x2(t[0] - h0, t[1] - h1);
                aL[half ? 3 : 1] = pack_bf16x2(t[2] - h2, t[3] - h3);
            }
            #pragma unroll
            for (int dn = 0; dn < 4; dn++) {
                const __nv_bfloat16* bh = vth + (h * 32 + dn * 8 + g) * VSTR + ks * 16 + 2 * tg;
                const __nv_bfloat16* bl = vtl + (h * 32 + dn * 8 + g) * VSTR + ks * 16 + 2 * tg;
                uint32_t bH[2] = {*(const uint32_t*)bh, *(const uint32_t*)(bh + 8)};
                uint32_t bL[2] = {*(const uint32_t*)bl, *(const uint32_t*)(bl + 8)};
                mma_bf16(accv[dn], aH, bH);
                mma_bf16(accv[dn], aH, bL);
                mma_bf16(accv[dn], aL, bH);
            }
        }
        float a48a = __shfl_sync(0xffffffffu, acc[6][1], lane | 3);
        float a48b = __shfl_sync(0xffffffffu, acc[6][3], lane | 3);
        #pragma unroll
        for (int dn = 0; dn < 4; dn++) {
            int d0 = dn * 8 + 2 * tg;
            float v0 = __bfloat162float(vth[(h * 32 + d0) * VSTR + 48])
                     + __bfloat162float(vtl[(h * 32 + d0) * VSTR + 48]);
            float v1 = __bfloat162float(vth[(h * 32 + d0 + 1) * VSTR + 48])
                     + __bfloat162float(vtl[(h * 32 + d0 + 1) * VSTR + 48]);
            accv[dn][0] += a48a * v0; accv[dn][1] += a48a * v1;
            accv[dn][2] += a48b * v0; accv[dn][3] += a48b * v1;
        }

        // att output -> A-tile (x is dead), bf16 hi/lo
        #pragma unroll
        for (int dn = 0; dn < 4; dn++) {
            int col = h * 32 + dn * 8 + 2 * tg;
            float e0 = bf16rt(accv[dn][0]), e1 = bf16rt(accv[dn][1]);
            float e2 = bf16rt(accv[dn][2]), e3 = bf16rt(accv[dn][3]);
            *(uint32_t*)(sw + XAH_ + r0 * XSTR + col) = pack_bf16x2(accv[dn][0], accv[dn][1]);
            *(uint32_t*)(sw + XAL_ + r0 * XSTR + col) = pack_bf16x2(accv[dn][0] - e0, accv[dn][1] - e1);
            *(uint32_t*)(sw + XAH_ + r1 * XSTR + col) = pack_bf16x2(accv[dn][2], accv[dn][3]);
            *(uint32_t*)(sw + XAL_ + r1 * XSTR + col) = pack_bf16x2(accv[dn][2] - e2, accv[dn][3] - e3);
        }
    }
    __syncthreads();

    // ---- phase 4: out projection -------------------------------------------
    float acc2[4][4];
    #pragma unroll
    for (int nt = 0; nt < 4; nt++)
        #pragma unroll
        for (int e = 0; e < 4; e++) acc2[nt][e] = 0.f;
    #pragma unroll
    for (int ks = 0; ks < 6; ks++) {
        int cb = ks * 16 + 2 * tg;
        uint32_t aH[4], aL[4];
        aH[0] = *(const uint32_t*)(sw + XAH_ + r0 * XSTR + cb);
        aH[1] = *(const uint32_t*)(sw + XAH_ + r1 * XSTR + cb);
        aH[2] = *(const uint32_t*)(sw + XAH_ + r0 * XSTR + cb + 8);
        aH[3] = *(const uint32_t*)(sw + XAH_ + r1 * XSTR + cb + 8);
        aL[0] = *(const uint32_t*)(sw + XAL_ + r0 * XSTR + cb);
        aL[1] = *(const uint32_t*)(sw + XAL_ + r1 * XSTR + cb);
        aL[2] = *(const uint32_t*)(sw + XAL_ + r0 * XSTR + cb + 8);
        aL[3] = *(const uint32_t*)(sw + XAL_ + r1 * XSTR + cb + 8);
        #pragma unroll
        for (int nt = 0; nt < 4; nt++) {
            int rn = third * 32 + nt * 8 + g;
            uint32_t bH[2] = {*(const uint32_t*)(sb + W_H + rn * WSTR + cb),
                              *(const uint32_t*)(sb + W_H + rn * WSTR + cb + 8)};
            uint32_t bL[2] = {*(const uint32_t*)(sb + W_L + rn * WSTR + cb),
                              *(const uint32_t*)(sb + W_L + rn * WSTR + cb + 8)};
            mma_bf16(acc2[nt], aH, bH);
            mma_bf16(acc2[nt], aH, bL);
            mma_bf16(acc2[nt], aL, bH);
        }
    }
    __syncthreads();

    // ---- phase 5: staged fp32 epilogue, coalesced spatial scatter ----------
    // staging reuses the (dead) weight region: window w gets floats [w*4900, +4900)
    float* st = (float*)sb + w * 4900;       // [49][100]
    #pragma unroll
    for (int nt = 0; nt < 4; nt++) {
        int col = third * 32 + nt * 8 + 2 * tg;
        float2 bo = *(const float2*)(b_out + col);
        *(float2*)(st + r0 * 100 + col) = make_float2(acc2[nt][0] + bo.x, acc2[nt][1] + bo.y);
        *(float2*)(st + r1 * 100 + col) = make_float2(acc2[nt][2] + bo.x, acc2[nt][3] + bo.y);
    }
    __syncthreads();
    for (int i = wtid; i < 49 * 24; i += 384) {
        int t = i / 24, f4 = i % 24;
        *(float4*)(out + (size_t)sg[w][t] * 96 + f4 * 4) = *(const float4*)(st + t * 100 + f4 * 4);
    }
}

// ---------------- launch ----------------------------------------------------
extern "C" void kernel_launch(void* const* d_in, const int* in_sizes, int n_in,
                              void* d_out, int out_size)
{
    (void)in_sizes; (void)n_in; (void)out_size;
    const float* x     = (const float*)d_in[0];
    const float* w_qkv = (const float*)d_in[1];
    const float* b_qkv = (const float*)d_in[2];
    const float* rel   = (const float*)d_in[3];
    const float* w_out = (const float*)d_in[4];
    const float* b_out = (const float*)d_in[5];
    float* out = (float*)d_out;

    cudaFuncSetAttribute(fused_win2, cudaFuncAttributeMaxDynamicSharedMemorySize, FUSED_SMEM);

    // 0) split weights into bf16 hi/lo (transposed [n][k])
    split_w<<<((QKV_N + 96) * 96 + 255) / 256, 256>>>(w_qkv, w_out);

    // 1) fused qkv-projection + attention + out-projection, 2 windows/block
    fused_win2<<<2048, 768, FUSED_SMEM>>>(x, b_qkv, rel, b_out, out);
}

// round 14
// speedup vs baseline: 3.4375x; 1.3266x over previous
#include <cuda_runtime.h>
#include <cuda_bf16.h>
#include <cstdint>

#define QKV_N 288

// ---------------- scratch: fragment-packed weights (allocation-free rule) --
// qkv: [c(3)][ks(6)][third(3)][nt(4)][lane(32)] -> uint4 {bHx,bHy,bLx,bLy}
// out: [ks(6)][third(3)][nt(4)][lane(32)]
__device__ uint4 g_wfq[3 * 6 * 12 * 32];   // 6912 uint4 = 110.6 KB
__device__ uint4 g_wfo[6 * 12 * 32];       // 2304 uint4 =  36.9 KB

__device__ __forceinline__ void mma_bf16(float* c, const uint32_t* a, const uint32_t* b) {
    asm("mma.sync.aligned.m16n8k16.row.col.f32.bf16.bf16.f32 "
        "{%0,%1,%2,%3}, {%4,%5,%6,%7}, {%8,%9}, {%0,%1,%2,%3};"
        : "+f"(c[0]), "+f"(c[1]), "+f"(c[2]), "+f"(c[3])
        : "r"(a[0]), "r"(a[1]), "r"(a[2]), "r"(a[3]), "r"(b[0]), "r"(b[1]));
}
__device__ __forceinline__ uint32_t pack_bf16x2(float lo, float hi) {
    uint32_t r;
    asm("cvt.rn.bf16x2.f32 %0, %1, %2;" : "=r"(r) : "f"(hi), "f"(lo));
    return r;
}
__device__ __forceinline__ float bf16rt(float x) {
    return __bfloat162float(__float2bfloat16(x));
}

// ---------------- prep: fragment-pack weights ------------------------------
// B-fragment for (row rn, cols kb,kb+1,kb+8,kb+9) of transposed weight [n][k].
__global__ void split_w(const float* __restrict__ wqkv, const float* __restrict__ wout) {
    int idx = blockIdx.x * 256 + threadIdx.x;
    if (idx >= 6912 + 2304) return;
    float f0, f1, f8, f9;
    uint4* dst;
    if (idx < 6912) {
        int lane = idx & 31, tile = idx >> 5;
        int tg = lane & 3, g = lane >> 2;
        int nt = tile % 4, third = (tile / 4) % 3, ks = (tile / 12) % 6, c = tile / 72;
        int n = c * 96 + third * 32 + nt * 8 + g;
        int kb = ks * 16 + 2 * tg;
        f0 = wqkv[(kb + 0) * QKV_N + n];
        f1 = wqkv[(kb + 1) * QKV_N + n];
        f8 = wqkv[(kb + 8) * QKV_N + n];
        f9 = wqkv[(kb + 9) * QKV_N + n];
        dst = &g_wfq[idx];
    } else {
        int j = idx - 6912;
        int lane = j & 31, tile = j >> 5;
        int tg = lane & 3, g = lane >> 2;
        int nt = tile % 4, third = (tile / 4) % 3, ks = tile / 12;
        int n = third * 32 + nt * 8 + g;
        int kb = ks * 16 + 2 * tg;
        f0 = wout[(kb + 0) * 96 + n];
        f1 = wout[(kb + 1) * 96 + n];
        f8 = wout[(kb + 8) * 96 + n];
        f9 = wout[(kb + 9) * 96 + n];
        dst = &g_wfo[j];
    }
    uint4 wb;
    wb.x = pack_bf16x2(f0, f1);                                   // hi, k/k+1
    wb.y = pack_bf16x2(f8, f9);                                   // hi, k+8/k+9
    wb.z = pack_bf16x2(f0 - bf16rt(f0), f1 - bf16rt(f1));         // lo
    wb.w = pack_bf16x2(f8 - bf16rt(f8), f9 - bf16rt(f9));
    *dst = wb;
}

// ---------------- fused per-window kernel (weights via LDG.128) -------------
// One block = one window, 384 threads = 12 warps = (m-tile 0..3) x (third 0..2).
// smem ~91KB -> 2 blocks/SM (48 warps), independent phase schedules.
// smem offsets in bf16 units:
#define SQH_  0                    // q hi  [3][49][40]
#define SQL_  5880
#define SKH_  11760                // k hi
#define SKL_  17640
#define SVH_  23520                // v hi [3][32][56] (transposed)
#define SVL_  28896
#define XAH_  34272                // x / att A-tile hi [49][104]
#define XAL_  39368
#define SREL_ 44464                // rel_pos, 507 floats
#define FUSED_SMEM ((44464 + 1014) * 2)   // 90,956 B
#define QSTR 40
#define VSTR 56
#define XSTR 104

__global__ __launch_bounds__(384, 2) void fused_win(
    const float* __restrict__ x, const float* __restrict__ b_qkv,
    const float* __restrict__ rel_pos, const float* __restrict__ b_out,
    float* __restrict__ out)
{
    extern __shared__ __nv_bfloat16 sb[];
    __shared__ int sg[49];
    float* srel = (float*)(sb + SREL_);

    const int tid = threadIdx.x, lane = tid & 31, warp = tid >> 5;
    const int g = lane >> 2, tg = lane & 3;
    const int mt = warp & 3, third = warp >> 2;          // head / n-chunk
    const int m0 = (mt == 3) ? 33 : mt * 16;
    const int r0 = m0 + g, r1 = m0 + 8 + g;
    const int win = blockIdx.x;                          // ((b*8)+hi)*8+wi
    const int wi = win & 7, hi2 = (win >> 3) & 7, bb2 = win >> 6;

    // ---- phase 0: token map + rel_pos ---------------------------------------
    if (tid < 49) {
        int p = tid / 7, q = tid % 7;
        sg[tid] = (bb2 * 56 + p * 8 + hi2) * 56 + q * 8 + wi;
    }
    for (int i = tid; i < 507; i += 384) srel[i] = rel_pos[i];
    __syncthreads();    // sg ready for gather

    // ---- phase 1: gather x, split to bf16 hi/lo A-tile ----------------------
    for (int i = tid; i < 49 * 24; i += 384) {
        int t = i / 24, f4 = i % 24;
        float4 v = *(const float4*)(x + (size_t)sg[t] * 96 + f4 * 4);
        uint2 H, L;
        H.x = pack_bf16x2(v.x, v.y);
        H.y = pack_bf16x2(v.z, v.w);
        L.x = pack_bf16x2(v.x - bf16rt(v.x), v.y - bf16rt(v.y));
        L.y = pack_bf16x2(v.z - bf16rt(v.z), v.w - bf16rt(v.w));
        *(uint2*)(sb + XAH_ + t * XSTR + f4 * 4) = H;
        *(uint2*)(sb + XAL_ + t * XSTR + f4 * 4) = L;
    }
    __syncthreads();    // A-tile ready

    // ---- phase 2: qkv projection, weights via fragment-packed LDG ----------
    for (int c = 0; c < 3; c++) {
        float acc[4][4];
        #pragma unroll
        for (int nt = 0; nt < 4; nt++)
            #pragma unroll
            for (int e = 0; e < 4; e++) acc[nt][e] = 0.f;
        #pragma unroll
        for (int ks = 0; ks < 6; ks++) {
            int cb = ks * 16 + 2 * tg;
            uint32_t aH[4], aL[4];
            aH[0] = *(const uint32_t*)(sb + XAH_ + r0 * XSTR + cb);
            aH[1] = *(const uint32_t*)(sb + XAH_ + r1 * XSTR + cb);
            aH[2] = *(const uint32_t*)(sb + XAH_ + r0 * XSTR + cb + 8);
            aH[3] = *(const uint32_t*)(sb + XAH_ + r1 * XSTR + cb + 8);
            aL[0] = *(const uint32_t*)(sb + XAL_ + r0 * XSTR + cb);
            aL[1] = *(const uint32_t*)(sb + XAL_ + r1 * XSTR + cb);
            aL[2] = *(const uint32_t*)(sb + XAL_ + r0 * XSTR + cb + 8);
            aL[3] = *(const uint32_t*)(sb + XAL_ + r1 * XSTR + cb + 8);
            const uint4* wbase = g_wfq + ((c * 6 + ks) * 12 + third * 4) * 32 + lane;
            #pragma unroll
            for (int nt = 0; nt < 4; nt++) {
                uint4 wb = wbase[nt * 32];
                uint32_t bH[2] = {wb.x, wb.y};
                uint32_t bL[2] = {wb.z, wb.w};
                mma_bf16(acc[nt], aH, bH);
                mma_bf16(acc[nt], aH, bL);
                mma_bf16(acc[nt], aL, bH);
            }
        }
        // writeback: +bias, split hi/lo, into attention layouts
        if (c < 2) {
            __nv_bfloat16* dH = sb + (c ? SKH_ : SQH_);
            __nv_bfloat16* dL = sb + (c ? SKL_ : SQL_);
            #pragma unroll
            for (int nt = 0; nt < 4; nt++) {
                int col = nt * 8 + 2 * tg;
                float2 bbv = *(const float2*)(b_qkv + c * 96 + third * 32 + col);
                float v0 = acc[nt][0] + bbv.x, v1 = acc[nt][1] + bbv.y;
                float v2 = acc[nt][2] + bbv.x, v3 = acc[nt][3] + bbv.y;
                *(uint32_t*)(dH + (third * 49 + r0) * QSTR + col) = pack_bf16x2(v0, v1);
                *(uint32_t*)(dL + (third * 49 + r0) * QSTR + col) =
                    pack_bf16x2(v0 - bf16rt(v0), v1 - bf16rt(v1));
                *(uint32_t*)(dH + (third * 49 + r1) * QSTR + col) = pack_bf16x2(v2, v3);
                *(uint32_t*)(dL + (third * 49 + r1) * QSTR + col) =
                    pack_bf16x2(v2 - bf16rt(v2), v3 - bf16rt(v3));
            }
        } else {
            __nv_bfloat16* vth = sb + SVH_;
            __nv_bfloat16* vtl = sb + SVL_;
            #pragma unroll
            for (int nt = 0; nt < 4; nt++) {
                int dd = nt * 8 + 2 * tg;
                float2 bbv = *(const float2*)(b_qkv + 192 + third * 32 + dd);
                float v0 = acc[nt][0] + bbv.x, v1 = acc[nt][1] + bbv.y;
                float v2 = acc[nt][2] + bbv.x, v3 = acc[nt][3] + bbv.y;
                int base0 = (third * 32 + dd) * VSTR, base1 = base0 + VSTR;
                vth[base0 + r0] = __float2bfloat16(v0);
                vtl[base0 + r0] = __float2bfloat16(v0 - bf16rt(v0));
                vth[base1 + r0] = __float2bfloat16(v1);
                vtl[base1 + r0] = __float2bfloat16(v1 - bf16rt(v1));
                vth[base0 + r1] = __float2bfloat16(v2);
                vtl[base0 + r1] = __float2bfloat16(v2 - bf16rt(v2));
                vth[base1 + r1] = __float2bfloat16(v3);
                vtl[base1 + r1] = __float2bfloat16(v3 - bf16rt(v3));
            }
        }
    }
    __syncthreads();    // q/k/v ready

    // ---- phase 3: attention (register-resident sim/att) --------------------
    {
        const int h = third;
        const int n0tab[7] = {0, 8, 16, 24, 32, 40, 41};
        const float scale = 0.17677669529663687f;   // 32^-0.5
        const __nv_bfloat16* qh = sb + SQH_ + h * 49 * QSTR;
        const __nv_bfloat16* ql = sb + SQL_ + h * 49 * QSTR;
        const __nv_bfloat16* kh = sb + SKH_ + h * 49 * QSTR;
        const __nv_bfloat16* kl = sb + SKL_ + h * 49 * QSTR;
        const __nv_bfloat16* vth = sb + SVH_;
        const __nv_bfloat16* vtl = sb + SVL_;

        float acc[7][4];
        #pragma unroll
        for (int nt = 0; nt < 7; nt++)
            #pragma unroll
            for (int e = 0; e < 4; e++) acc[nt][e] = 0.f;

        #pragma unroll
        for (int ks = 0; ks < 2; ks++) {
            const int kb = ks * 16 + 2 * tg;
            uint32_t aH[4], aL[4];
            aH[0] = *(const uint32_t*)(qh + r0 * QSTR + kb);
            aH[1] = *(const uint32_t*)(qh + r1 * QSTR + kb);
            aH[2] = *(const uint32_t*)(qh + r0 * QSTR + kb + 8);
            aH[3] = *(const uint32_t*)(qh + r1 * QSTR + kb + 8);
            aL[0] = *(const uint32_t*)(ql + r0 * QSTR + kb);
            aL[1] = *(const uint32_t*)(ql + r1 * QSTR + kb);
            aL[2] = *(const uint32_t*)(ql + r0 * QSTR + kb + 8);
            aL[3] = *(const uint32_t*)(ql + r1 * QSTR + kb + 8);
            #pragma unroll
            for (int nt = 0; nt < 7; nt++) {
                int rn = n0tab[nt] + g;
                uint32_t bH[2] = {*(const uint32_t*)(kh + rn * QSTR + kb),
                                  *(const uint32_t*)(kh + rn * QSTR + kb + 8)};
                uint32_t bL[2] = {*(const uint32_t*)(kl + rn * QSTR + kb),
                                  *(const uint32_t*)(kl + rn * QSTR + kb + 8)};
                mma_bf16(acc[nt], aH, bH);
                mma_bf16(acc[nt], aH, bL);
                mma_bf16(acc[nt], aL, bH);
            }
        }

        // scale + rel-pos bias
        {
            const float* relh = srel + h * 169;
            int pi0 = r0 / 7, qi0 = r0 % 7, pi1 = r1 / 7, qi1 = r1 % 7;
            #pragma unroll
            for (int nt = 0; nt < 7; nt++) {
                int j0 = n0tab[nt] + 2 * tg, j1 = j0 + 1;
                int pj0 = j0 / 7, qj0 = j0 % 7, pj1 = j1 / 7, qj1 = j1 % 7;
                acc[nt][0] = fmaf(acc[nt][0], scale, relh[(pi0 - pj0 + 6) * 13 + (qi0 - qj0 + 6)]);
                acc[nt][1] = fmaf(acc[nt][1], scale, relh[(pi0 - pj1 + 6) * 13 + (qi0 - qj1 + 6)]);
                acc[nt][2] = fmaf(acc[nt][2], scale, relh[(pi1 - pj0 + 6) * 13 + (qi1 - qj0 + 6)]);
                acc[nt][3] = fmaf(acc[nt][3], scale, relh[(pi1 - pj1 + 6) * 13 + (qi1 - qj1 + 6)]);
            }
        }

        // softmax (dup cols of overlap tile excluded from sums)
        float mx0 = -1e30f, mx1 = -1e30f;
        #pragma unroll
        for (int nt = 0; nt < 7; nt++) {
            mx0 = fmaxf(mx0, fmaxf(acc[nt][0], acc[nt][1]));
            mx1 = fmaxf(mx1, fmaxf(acc[nt][2], acc[nt][3]));
        }
        mx0 = fmaxf(mx0, __shfl_xor_sync(0xffffffffu, mx0, 1));
        mx0 = fmaxf(mx0, __shfl_xor_sync(0xffffffffu, mx0, 2));
        mx1 = fmaxf(mx1, __shfl_xor_sync(0xffffffffu, mx1, 1));
        mx1 = fmaxf(mx1, __shfl_xor_sync(0xffffffffu, mx1, 2));
        float s0 = 0.f, s1 = 0.f;
        #pragma unroll
        for (int nt = 0; nt < 6; nt++) {
            acc[nt][0] = __expf(acc[nt][0] - mx0); s0 += acc[nt][0];
            acc[nt][1] = __expf(acc[nt][1] - mx0); s0 += acc[nt][1];
            acc[nt][2] = __expf(acc[nt][2] - mx1); s1 += acc[nt][2];
            acc[nt][3] = __expf(acc[nt][3] - mx1); s1 += acc[nt][3];
        }
        acc[6][0] = __expf(acc[6][0] - mx0);
        acc[6][1] = __expf(acc[6][1] - mx0);
        acc[6][2] = __expf(acc[6][2] - mx1);
        acc[6][3] = __expf(acc[6][3] - mx1);
        if (tg == 3) { s0 += acc[6][1]; s1 += acc[6][3]; }   // col 48
        s0 += __shfl_xor_sync(0xffffffffu, s0, 1);
        s0 += __shfl_xor_sync(0xffffffffu, s0, 2);
        s1 += __shfl_xor_sync(0xffffffffu, s1, 1);
        s1 += __shfl_xor_sync(0xffffffffu, s1, 2);
        float inv0 = 1.f / s0, inv1 = 1.f / s1;
        #pragma unroll
        for (int nt = 0; nt < 7; nt++) {
            acc[nt][0] *= inv0; acc[nt][1] *= inv0;
            acc[nt][2] *= inv1; acc[nt][3] *= inv1;
        }

        // out = att @ v
        float accv[4][4];
        #pragma unroll
        for (int dn = 0; dn < 4; dn++)
            #pragma unroll
            for (int e = 0; e < 4; e++) accv[dn][e] = 0.f;
        #pragma unroll
        for (int ks = 0; ks < 3; ks++) {
            uint32_t aH[4], aL[4];
            #pragma unroll
            for (int half = 0; half < 2; half++) {
                float* t = acc[2 * ks + half];
                float h0 = bf16rt(t[0]), h1 = bf16rt(t[1]);
                float h2 = bf16rt(t[2]), h3 = bf16rt(t[3]);
                aH[half ? 2 : 0] = pack_bf16x2(t[0], t[1]);
                aH[half ? 3 : 1] = pack_bf16x2(t[2], t[3]);
                aL[half ? 2 : 0] = pack_bf16x2(t[0] - h0, t[1] - h1);
                aL[half ? 3 : 1] = pack_bf16x2(t[2] - h2, t[3] - h3);
            }
            #pragma unroll
            for (int dn = 0; dn < 4; dn++) {
                const __nv_bfloat16* bh = vth + (h * 32 + dn * 8 + g) * VSTR + ks * 16 + 2 * tg;
                const __nv_bfloat16* bl = vtl + (h * 32 + dn * 8 + g) * VSTR + ks * 16 + 2 * tg;
                uint32_t bH[2] = {*(const uint32_t*)bh, *(const uint32_t*)(bh + 8)};
                uint32_t bL[2] = {*(const uint32_t*)bl, *(const uint32_t*)(bl + 8)};
                mma_bf16(accv[dn], aH, bH);
                mma_bf16(accv[dn], aH, bL);
                mma_bf16(accv[dn], aL, bH);
            }
        }
        float a48a = __shfl_sync(0xffffffffu, acc[6][1], lane | 3);
        float a48b = __shfl_sync(0xffffffffu, acc[6][3], lane | 3);
        #pragma unroll
        for (int dn = 0; dn < 4; dn++) {
            int d0 = dn * 8 + 2 * tg;
            float v0 = __bfloat162float(vth[(h * 32 + d0) * VSTR + 48])
                     + __bfloat162float(vtl[(h * 32 + d0) * VSTR + 48]);
            float v1 = __bfloat162float(vth[(h * 32 + d0 + 1) * VSTR + 48])
                     + __bfloat162float(vtl[(h * 32 + d0 + 1) * VSTR + 48]);
            accv[dn][0] += a48a * v0; accv[dn][1] += a48a * v1;
            accv[dn][2] += a48b * v0; accv[dn][3] += a48b * v1;
        }

        // att output -> A-tile (x is dead), bf16 hi/lo (dup rows: identical)
        #pragma unroll
        for (int dn = 0; dn < 4; dn++) {
            int col = h * 32 + dn * 8 + 2 * tg;
            float e0 = bf16rt(accv[dn][0]), e1 = bf16rt(accv[dn][1]);
            float e2 = bf16rt(accv[dn][2]), e3 = bf16rt(accv[dn][3]);
            *(uint32_t*)(sb + XAH_ + r0 * XSTR + col) = pack_bf16x2(accv[dn][0], accv[dn][1]);
            *(uint32_t*)(sb + XAL_ + r0 * XSTR + col) = pack_bf16x2(accv[dn][0] - e0, accv[dn][1] - e1);
            *(uint32_t*)(sb + XAH_ + r1 * XSTR + col) = pack_bf16x2(accv[dn][2], accv[dn][3]);
            *(uint32_t*)(sb + XAL_ + r1 * XSTR + col) = pack_bf16x2(accv[dn][2] - e2, accv[dn][3] - e3);
        }
    }
    __syncthreads();    // att A-tile ready

    // ---- phase 4: out projection (weights via fragment-packed LDG) ---------
    float acc2[4][4];
    #pragma unroll
    for (int nt = 0; nt < 4; nt++)
        #pragma unroll
        for (int e = 0; e < 4; e++) acc2[nt][e] = 0.f;
    #pragma unroll
    for (int ks = 0; ks < 6; ks++) {
        int cb = ks * 16 + 2 * tg;
        uint32_t aH[4], aL[4];
        aH[0] = *(const uint32_t*)(sb + XAH_ + r0 * XSTR + cb);
        aH[1] = *(const uint32_t*)(sb + XAH_ + r1 * XSTR + cb);
        aH[2] = *(const uint32_t*)(sb + XAH_ + r0 * XSTR + cb + 8);
        aH[3] = *(const uint32_t*)(sb + XAH_ + r1 * XSTR + cb + 8);
        aL[0] = *(const uint32_t*)(sb + XAL_ + r0 * XSTR + cb);
        aL[1] = *(const uint32_t*)(sb + XAL_ + r1 * XSTR + cb);
        aL[2] = *(const uint32_t*)(sb + XAL_ + r0 * XSTR + cb + 8);
        aL[3] = *(const uint32_t*)(sb + XAL_ + r1 * XSTR + cb + 8);
        const uint4* wbase = g_wfo + (ks * 12 + third * 4) * 32 + lane;
        #pragma unroll
        for (int nt = 0; nt < 4; nt++) {
            uint4 wb = wbase[nt * 32];
            uint32_t bH[2] = {wb.x, wb.y};
            uint32_t bL[2] = {wb.z, wb.w};
            mma_bf16(acc2[nt], aH, bH);
            mma_bf16(acc2[nt], aH, bL);
            mma_bf16(acc2[nt], aL, bH);
        }
    }

    // ---- phase 5: staged fp32 epilogue (reuses dead q region) --------------
    float* st = (float*)sb;                  // [49][100] = 19.6 KB < q region
    #pragma unroll
    for (int nt = 0; nt < 4; nt++) {
        int col = third * 32 + nt * 8 + 2 * tg;
        float2 bo = *(const float2*)(b_out + col);
        *(float2*)(st + r0 * 100 + col) = make_float2(acc2[nt][0] + bo.x, acc2[nt][1] + bo.y);
        *(float2*)(st + r1 * 100 + col) = make_float2(acc2[nt][2] + bo.x, acc2[nt][3] + bo.y);
    }
    __syncthreads();    // staging visible
    for (int i = tid; i < 49 * 24; i += 384) {
        int t = i / 24, f4 = i % 24;
        *(float4*)(out + (size_t)sg[t] * 96 + f4 * 4) = *(const float4*)(st + t * 100 + f4 * 4);
    }
}

// ---------------- launch ----------------------------------------------------
extern "C" void kernel_launch(void* const* d_in, const int* in_sizes, int n_in,
                              void* d_out, int out_size)
{
    (void)in_sizes; (void)n_in; (void)out_size;
    const float* x     = (const float*)d_in[0];
    const float* w_qkv = (const float*)d_in[1];
    const float* b_qkv = (const float*)d_in[2];
    const float* rel   = (const float*)d_in[3];
    const float* w_out = (const float*)d_in[4];
    const float* b_out = (const float*)d_in[5];
    float* out = (float*)d_out;

    cudaFuncSetAttribute(fused_win, cudaFuncAttributeMaxDynamicSharedMemorySize, FUSED_SMEM);

    // 0) fragment-pack weights into bf16 hi/lo
    split_w<<<(6912 + 2304 + 255) / 256, 256>>>(w_qkv, w_out);

    // 1) fused qkv + attention + out-projection; 1 window/block, 2 blocks/SM
    fused_win<<<4096, 384, FUSED_SMEM>>>(x, b_qkv, rel, b_out, out);
}

// round 15
// speedup vs baseline: 6.0122x; 1.7490x over previous
#include <cuda_runtime.h>
#include <cuda_fp16.h>
#include <cstdint>

#define QKV_N 288

// ---------------- scratch: fragment-packed fp16 weights --------------------
// qkv: [c(3)][ks(6)][third(3)][nt(4)][lane(32)] -> uint2 {b(k,k+1), b(k+8,k+9)}
__device__ uint2 g_wfq[3 * 6 * 12 * 32];   // 55.3 KB
__device__ uint2 g_wfo[6 * 12 * 32];       // 18.4 KB

__device__ __forceinline__ void mma_f16(float* c, const uint32_t* a, const uint32_t* b) {
    asm("mma.sync.aligned.m16n8k16.row.col.f32.f16.f16.f32 "
        "{%0,%1,%2,%3}, {%4,%5,%6,%7}, {%8,%9}, {%0,%1,%2,%3};"
        : "+f"(c[0]), "+f"(c[1]), "+f"(c[2]), "+f"(c[3])
        : "r"(a[0]), "r"(a[1]), "r"(a[2]), "r"(a[3]), "r"(b[0]), "r"(b[1]));
}
__device__ __forceinline__ uint32_t pack_f16x2(float lo, float hi) {
    uint32_t r;
    asm("cvt.rn.f16x2.f32 %0, %1, %2;" : "=r"(r) : "f"(hi), "f"(lo));
    return r;
}

// ---------------- prep: fragment-pack weights to fp16 ----------------------
__global__ void split_w(const float* __restrict__ wqkv, const float* __restrict__ wout) {
    int idx = blockIdx.x * 256 + threadIdx.x;
    if (idx >= 6912 + 2304) return;
    float f0, f1, f8, f9;
    uint2* dst;
    if (idx < 6912) {
        int lane = idx & 31, tile = idx >> 5;
        int tg = lane & 3, g = lane >> 2;
        int nt = tile % 4, third = (tile / 4) % 3, ks = (tile / 12) % 6, c = tile / 72;
        int n = c * 96 + third * 32 + nt * 8 + g;
        int kb = ks * 16 + 2 * tg;
        f0 = wqkv[(kb + 0) * QKV_N + n];
        f1 = wqkv[(kb + 1) * QKV_N + n];
        f8 = wqkv[(kb + 8) * QKV_N + n];
        f9 = wqkv[(kb + 9) * QKV_N + n];
        dst = &g_wfq[idx];
    } else {
        int j = idx - 6912;
        int lane = j & 31, tile = j >> 5;
        int tg = lane & 3, g = lane >> 2;
        int nt = tile % 4, third = (tile / 4) % 3, ks = tile / 12;
        int n = third * 32 + nt * 8 + g;
        int kb = ks * 16 + 2 * tg;
        f0 = wout[(kb + 0) * 96 + n];
        f1 = wout[(kb + 1) * 96 + n];
        f8 = wout[(kb + 8) * 96 + n];
        f9 = wout[(kb + 9) * 96 + n];
        dst = &g_wfo[j];
    }
    uint2 wb;
    wb.x = pack_f16x2(f0, f1);
    wb.y = pack_f16x2(f8, f9);
    *dst = wb;
}

// ---------------- fused per-window kernel (fp16 single-product) -------------
// One block = one window, 384 threads = 12 warps = (m-tile 0..3) x (third 0..2).
// smem 46.5KB -> 3 blocks/SM.  All operands single fp16; accum fp32.
// smem offsets in fp16 units:
#define SQ_   0                    // q  [3][49][40]
#define SK_   5880                 // k
#define SV_   11760                // v  [3][32][56] (transposed)
#define XA_   17136                // x / att A-tile [49][104]
#define SREL_ 22232                // rel_pos, 507 floats (1014 units)
#define FUSED_SMEM ((22232 + 1014) * 2)   // 46,492 B
#define QSTR 40
#define VSTR 56
#define XSTR 104

__global__ __launch_bounds__(384, 3) void fused_win(
    const float* __restrict__ x, const float* __restrict__ b_qkv,
    const float* __restrict__ rel_pos, const float* __restrict__ b_out,
    float* __restrict__ out)
{
    extern __shared__ __half sb[];
    float* srel = (float*)(sb + SREL_);

    const int tid = threadIdx.x, lane = tid & 31, warp = tid >> 5;
    const int g = lane >> 2, tg = lane & 3;
    const int mt = warp & 3, third = warp >> 2;          // head / n-chunk
    const int m0 = (mt == 3) ? 33 : mt * 16;
    const int r0 = m0 + g, r1 = m0 + 8 + g;
    const int win = blockIdx.x;                          // ((b*8)+hi)*8+wi
    const int wi = win & 7, hi2 = (win >> 3) & 7, bb2 = win >> 6;

    for (int i = tid; i < 507; i += 384) srel[i] = rel_pos[i];

    // ---- phase 1: gather x (token map inline), convert to fp16 A-tile ------
    for (int i = tid; i < 49 * 24; i += 384) {
        int t = i / 24, f4 = i % 24;
        int p = t / 7, q = t % 7;
        size_t row = (size_t)(bb2 * 56 + p * 8 + hi2) * 56 + q * 8 + wi;
        float4 v = *(const float4*)(x + row * 96 + f4 * 4);
        uint2 H;
        H.x = pack_f16x2(v.x, v.y);
        H.y = pack_f16x2(v.z, v.w);
        *(uint2*)(sb + XA_ + t * XSTR + f4 * 4) = H;
    }
    __syncthreads();    // A-tile ready

    // ---- phase 2: qkv projection (weights via LDG.64 fragments) ------------
    for (int c = 0; c < 3; c++) {
        float acc[4][4];
        #pragma unroll
        for (int nt = 0; nt < 4; nt++)
            #pragma unroll
            for (int e = 0; e < 4; e++) acc[nt][e] = 0.f;
        #pragma unroll
        for (int ks = 0; ks < 6; ks++) {
            int cb = ks * 16 + 2 * tg;
            uint32_t a[4];
            a[0] = *(const uint32_t*)(sb + XA_ + r0 * XSTR + cb);
            a[1] = *(const uint32_t*)(sb + XA_ + r1 * XSTR + cb);
            a[2] = *(const uint32_t*)(sb + XA_ + r0 * XSTR + cb + 8);
            a[3] = *(const uint32_t*)(sb + XA_ + r1 * XSTR + cb + 8);
            const uint2* wbase = g_wfq + ((c * 6 + ks) * 12 + third * 4) * 32 + lane;
            #pragma unroll
            for (int nt = 0; nt < 4; nt++) {
                uint2 wb = wbase[nt * 32];
                uint32_t b[2] = {wb.x, wb.y};
                mma_f16(acc[nt], a, b);
            }
        }
        // writeback: +bias (fp32), quantize to fp16 attention layouts
        if (c < 2) {
            __half* d = sb + (c ? SK_ : SQ_);
            #pragma unroll
            for (int nt = 0; nt < 4; nt++) {
                int col = nt * 8 + 2 * tg;
                float2 bbv = *(const float2*)(b_qkv + c * 96 + third * 32 + col);
                *(uint32_t*)(d + (third * 49 + r0) * QSTR + col) =
                    pack_f16x2(acc[nt][0] + bbv.x, acc[nt][1] + bbv.y);
                *(uint32_t*)(d + (third * 49 + r1) * QSTR + col) =
                    pack_f16x2(acc[nt][2] + bbv.x, acc[nt][3] + bbv.y);
            }
        } else {
            __half* vt = sb + SV_;
            #pragma unroll
            for (int nt = 0; nt < 4; nt++) {
                int dd = nt * 8 + 2 * tg;
                float2 bbv = *(const float2*)(b_qkv + 192 + third * 32 + dd);
                int base0 = (third * 32 + dd) * VSTR, base1 = base0 + VSTR;
                vt[base0 + r0] = __float2half(acc[nt][0] + bbv.x);
                vt[base1 + r0] = __float2half(acc[nt][1] + bbv.y);
                vt[base0 + r1] = __float2half(acc[nt][2] + bbv.x);
                vt[base1 + r1] = __float2half(acc[nt][3] + bbv.y);
            }
        }
    }
    __syncthreads();    // q/k/v + rel ready

    // ---- phase 3: attention (register-resident sim/att) --------------------
    {
        const int h = third;
        const int n0tab[7] = {0, 8, 16, 24, 32, 40, 41};
        const float scale = 0.17677669529663687f;   // 32^-0.5
        const __half* qb = sb + SQ_ + h * 49 * QSTR;
        const __half* kb2 = sb + SK_ + h * 49 * QSTR;
        const __half* vt = sb + SV_;

        float acc[7][4];
        #pragma unroll
        for (int nt = 0; nt < 7; nt++)
            #pragma unroll
            for (int e = 0; e < 4; e++) acc[nt][e] = 0.f;

        #pragma unroll
        for (int ks = 0; ks < 2; ks++) {
            const int kb = ks * 16 + 2 * tg;
            uint32_t a[4];
            a[0] = *(const uint32_t*)(qb + r0 * QSTR + kb);
            a[1] = *(const uint32_t*)(qb + r1 * QSTR + kb);
            a[2] = *(const uint32_t*)(qb + r0 * QSTR + kb + 8);
            a[3] = *(const uint32_t*)(qb + r1 * QSTR + kb + 8);
            #pragma unroll
            for (int nt = 0; nt < 7; nt++) {
                int rn = n0tab[nt] + g;
                uint32_t b[2] = {*(const uint32_t*)(kb2 + rn * QSTR + kb),
                                 *(const uint32_t*)(kb2 + rn * QSTR + kb + 8)};
                mma_f16(acc[nt], a, b);
            }
        }

        // scale + rel-pos bias (fp32)
        {
            const float* relh = srel + h * 169;
            int pi0 = r0 / 7, qi0 = r0 % 7, pi1 = r1 / 7, qi1 = r1 % 7;
            #pragma unroll
            for (int nt = 0; nt < 7; nt++) {
                int j0 = n0tab[nt] + 2 * tg, j1 = j0 + 1;
                int pj0 = j0 / 7, qj0 = j0 % 7, pj1 = j1 / 7, qj1 = j1 % 7;
                acc[nt][0] = fmaf(acc[nt][0], scale, relh[(pi0 - pj0 + 6) * 13 + (qi0 - qj0 + 6)]);
                acc[nt][1] = fmaf(acc[nt][1], scale, relh[(pi0 - pj1 + 6) * 13 + (qi0 - qj1 + 6)]);
                acc[nt][2] = fmaf(acc[nt][2], scale, relh[(pi1 - pj0 + 6) * 13 + (qi1 - qj0 + 6)]);
                acc[nt][3] = fmaf(acc[nt][3], scale, relh[(pi1 - pj1 + 6) * 13 + (qi1 - qj1 + 6)]);
            }
        }

        // softmax (dup cols of overlap tile excluded from sums)
        float mx0 = -1e30f, mx1 = -1e30f;
        #pragma unroll
        for (int nt = 0; nt < 7; nt++) {
            mx0 = fmaxf(mx0, fmaxf(acc[nt][0], acc[nt][1]));
            mx1 = fmaxf(mx1, fmaxf(acc[nt][2], acc[nt][3]));
        }
        mx0 = fmaxf(mx0, __shfl_xor_sync(0xffffffffu, mx0, 1));
        mx0 = fmaxf(mx0, __shfl_xor_sync(0xffffffffu, mx0, 2));
        mx1 = fmaxf(mx1, __shfl_xor_sync(0xffffffffu, mx1, 1));
        mx1 = fmaxf(mx1, __shfl_xor_sync(0xffffffffu, mx1, 2));
        float s0 = 0.f, s1 = 0.f;
        #pragma unroll
        for (int nt = 0; nt < 6; nt++) {
            acc[nt][0] = __expf(acc[nt][0] - mx0); s0 += acc[nt][0];
            acc[nt][1] = __expf(acc[nt][1] - mx0); s0 += acc[nt][1];
            acc[nt][2] = __expf(acc[nt][2] - mx1); s1 += acc[nt][2];
            acc[nt][3] = __expf(acc[nt][3] - mx1); s1 += acc[nt][3];
        }
        acc[6][0] = __expf(acc[6][0] - mx0);
        acc[6][1] = __expf(acc[6][1] - mx0);
        acc[6][2] = __expf(acc[6][2] - mx1);
        acc[6][3] = __expf(acc[6][3] - mx1);
        if (tg == 3) { s0 += acc[6][1]; s1 += acc[6][3]; }   // col 48 only
        s0 += __shfl_xor_sync(0xffffffffu, s0, 1);
        s0 += __shfl_xor_sync(0xffffffffu, s0, 2);
        s1 += __shfl_xor_sync(0xffffffffu, s1, 1);
        s1 += __shfl_xor_sync(0xffffffffu, s1, 2);
        float inv0 = 1.f / s0, inv1 = 1.f / s1;
        #pragma unroll
        for (int nt = 0; nt < 7; nt++) {
            acc[nt][0] *= inv0; acc[nt][1] *= inv0;
            acc[nt][2] *= inv1; acc[nt][3] *= inv1;
        }

        // out = att @ v : att repacked in-register as fp16 A frags
        float accv[4][4];
        #pragma unroll
        for (int dn = 0; dn < 4; dn++)
            #pragma unroll
            for (int e = 0; e < 4; e++) accv[dn][e] = 0.f;
        #pragma unroll
        for (int ks = 0; ks < 3; ks++) {
            uint32_t a[4];
            float* t0 = acc[2 * ks];
            float* t1 = acc[2 * ks + 1];
            a[0] = pack_f16x2(t0[0], t0[1]);
            a[1] = pack_f16x2(t0[2], t0[3]);
            a[2] = pack_f16x2(t1[0], t1[1]);
            a[3] = pack_f16x2(t1[2], t1[3]);
            #pragma unroll
            for (int dn = 0; dn < 4; dn++) {
                const __half* vb = vt + (h * 32 + dn * 8 + g) * VSTR + ks * 16 + 2 * tg;
                uint32_t b[2] = {*(const uint32_t*)vb, *(const uint32_t*)(vb + 8)};
                mma_f16(accv[dn], a, b);
            }
        }
        // j = 48 via shfl + scalar fp32 FMA
        float a48a = __shfl_sync(0xffffffffu, acc[6][1], lane | 3);
        float a48b = __shfl_sync(0xffffffffu, acc[6][3], lane | 3);
        #pragma unroll
        for (int dn = 0; dn < 4; dn++) {
            int d0 = dn * 8 + 2 * tg;
            float v0 = __half2float(vt[(h * 32 + d0) * VSTR + 48]);
            float v1 = __half2float(vt[(h * 32 + d0 + 1) * VSTR + 48]);
            accv[dn][0] += a48a * v0; accv[dn][1] += a48a * v1;
            accv[dn][2] += a48b * v0; accv[dn][3] += a48b * v1;
        }

        // att output -> A-tile (x is dead), fp16 (dup rows store identical)
        #pragma unroll
        for (int dn = 0; dn < 4; dn++) {
            int col = h * 32 + dn * 8 + 2 * tg;
            *(uint32_t*)(sb + XA_ + r0 * XSTR + col) = pack_f16x2(accv[dn][0], accv[dn][1]);
            *(uint32_t*)(sb + XA_ + r1 * XSTR + col) = pack_f16x2(accv[dn][2], accv[dn][3]);
        }
    }
    __syncthreads();    // att A-tile ready

    // ---- phase 4: out projection -------------------------------------------
    float acc2[4][4];
    #pragma unroll
    for (int nt = 0; nt < 4; nt++)
        #pragma unroll
        for (int e = 0; e < 4; e++) acc2[nt][e] = 0.f;
    #pragma unroll
    for (int ks = 0; ks < 6; ks++) {
        int cb = ks * 16 + 2 * tg;
        uint32_t a[4];
        a[0] = *(const uint32_t*)(sb + XA_ + r0 * XSTR + cb);
        a[1] = *(const uint32_t*)(sb + XA_ + r1 * XSTR + cb);
        a[2] = *(const uint32_t*)(sb + XA_ + r0 * XSTR + cb + 8);
        a[3] = *(const uint32_t*)(sb + XA_ + r1 * XSTR + cb + 8);
        const uint2* wbase = g_wfo + (ks * 12 + third * 4) * 32 + lane;
        #pragma unroll
        for (int nt = 0; nt < 4; nt++) {
            uint2 wb = wbase[nt * 32];
            uint32_t b[2] = {wb.x, wb.y};
            mma_f16(acc2[nt], a, b);
        }
    }

    // ---- phase 5: staged fp32 epilogue (reuses dead q/k regions) -----------
    float* st = (float*)sb;                  // [49][100] = 19.6 KB < q+k
    #pragma unroll
    for (int nt = 0; nt < 4; nt++) {
        int col = third * 32 + nt * 8 + 2 * tg;
        float2 bo = *(const float2*)(b_out + col);
        *(float2*)(st + r0 * 100 + col) = make_float2(acc2[nt][0] + bo.x, acc2[nt][1] + bo.y);
        *(float2*)(st + r1 * 100 + col) = make_float2(acc2[nt][2] + bo.x, acc2[nt][3] + bo.y);
    }
    __syncthreads();    // staging visible
    for (int i = tid; i < 49 * 24; i += 384) {
        int t = i / 24, f4 = i % 24;
        int p = t / 7, q = t % 7;
        size_t row = (size_t)(bb2 * 56 + p * 8 + hi2) * 56 + q * 8 + wi;
        *(float4*)(out + row * 96 + f4 * 4) = *(const float4*)(st + t * 100 + f4 * 4);
    }
}

// ---------------- launch ----------------------------------------------------
extern "C" void kernel_launch(void* const* d_in, const int* in_sizes, int n_in,
                              void* d_out, int out_size)
{
    (void)in_sizes; (void)n_in; (void)out_size;
    const float* x     = (const float*)d_in[0];
    const float* w_qkv = (const float*)d_in[1];
    const float* b_qkv = (const float*)d_in[2];
    const float* rel   = (const float*)d_in[3];
    const float* w_out = (const float*)d_in[4];
    const float* b_out = (const float*)d_in[5];
    float* out = (float*)d_out;

    cudaFuncSetAttribute(fused_win, cudaFuncAttributeMaxDynamicSharedMemorySize, FUSED_SMEM);

    // 0) fragment-pack weights to fp16
    split_w<<<(6912 + 2304 + 255) / 256, 256>>>(w_qkv, w_out);

    // 1) fused qkv + attention + out-projection; 3 blocks/SM
    fused_win<<<4096, 384, FUSED_SMEM>>>(x, b_qkv, rel, b_out, out);
}

// round 16
// speedup vs baseline: 6.0421x; 1.0050x over previous
#include <cuda_runtime.h>
#include <cuda_fp16.h>
#include <cstdint>

#define QKV_N 288

// ---------------- scratch: fragment-packed fp16 weights --------------------
// qkv: [c(3)][ks(6)][third(3)][nt(4)][lane(32)] -> uint2 {b(k,k+1), b(k+8,k+9)}
__device__ uint2 g_wfq[3 * 6 * 12 * 32];   // 55.3 KB
__device__ uint2 g_wfo[6 * 12 * 32];       // 18.4 KB

__device__ __forceinline__ void mma_f16(float* c, const uint32_t* a, const uint32_t* b) {
    asm("mma.sync.aligned.m16n8k16.row.col.f32.f16.f16.f32 "
        "{%0,%1,%2,%3}, {%4,%5,%6,%7}, {%8,%9}, {%0,%1,%2,%3};"
        : "+f"(c[0]), "+f"(c[1]), "+f"(c[2]), "+f"(c[3])
        : "r"(a[0]), "r"(a[1]), "r"(a[2]), "r"(a[3]), "r"(b[0]), "r"(b[1]));
}
__device__ __forceinline__ uint32_t pack_f16x2(float lo, float hi) {
    uint32_t r;
    asm("cvt.rn.f16x2.f32 %0, %1, %2;" : "=r"(r) : "f"(hi), "f"(lo));
    return r;
}
__device__ __forceinline__ uint32_t smem_addr(const void* p) {
    return (uint32_t)__cvta_generic_to_shared(p);
}
__device__ __forceinline__ void ldsm_x4(uint32_t* r, uint32_t a) {
    asm volatile("ldmatrix.sync.aligned.m8n8.x4.shared.b16 {%0,%1,%2,%3}, [%4];"
        : "=r"(r[0]), "=r"(r[1]), "=r"(r[2]), "=r"(r[3]) : "r"(a));
}
__device__ __forceinline__ void ldsm_x2(uint32_t* r, uint32_t a) {
    asm volatile("ldmatrix.sync.aligned.m8n8.x2.shared.b16 {%0,%1}, [%2];"
        : "=r"(r[0]), "=r"(r[1]) : "r"(a));
}

// ---------------- prep: fragment-pack weights to fp16 ----------------------
__global__ void split_w(const float* __restrict__ wqkv, const float* __restrict__ wout) {
    int idx = blockIdx.x * 256 + threadIdx.x;
    if (idx >= 6912 + 2304) return;
    float f0, f1, f8, f9;
    uint2* dst;
    if (idx < 6912) {
        int lane = idx & 31, tile = idx >> 5;
        int tg = lane & 3, g = lane >> 2;
        int nt = tile % 4, third = (tile / 4) % 3, ks = (tile / 12) % 6, c = tile / 72;
        int n = c * 96 + third * 32 + nt * 8 + g;
        int kb = ks * 16 + 2 * tg;
        f0 = wqkv[(kb + 0) * QKV_N + n];
        f1 = wqkv[(kb + 1) * QKV_N + n];
        f8 = wqkv[(kb + 8) * QKV_N + n];
        f9 = wqkv[(kb + 9) * QKV_N + n];
        dst = &g_wfq[idx];
    } else {
        int j = idx - 6912;
        int lane = j & 31, tile = j >> 5;
        int tg = lane & 3, g = lane >> 2;
        int nt = tile % 4, third = (tile / 4) % 3, ks = tile / 12;
        int n = third * 32 + nt * 8 + g;
        int kb = ks * 16 + 2 * tg;
        f0 = wout[(kb + 0) * 96 + n];
        f1 = wout[(kb + 1) * 96 + n];
        f8 = wout[(kb + 8) * 96 + n];
        f9 = wout[(kb + 9) * 96 + n];
        dst = &g_wfo[j];
    }
    uint2 wb;
    wb.x = pack_f16x2(f0, f1);
    wb.y = pack_f16x2(f8, f9);
    *dst = wb;
}

// ---------------- fused per-window kernel (fp16, ldmatrix frags) ------------
// One block = one window, 384 threads = 12 warps = (m-tile 0..3) x (third 0..2).
// smem 46.5KB -> 3 blocks/SM.  All fragment loads via ldmatrix (conflict-free
// by stride arithmetic: 208B/80B/112B row strides permute all 32 banks).
// smem offsets in fp16 units:
#define SQ_   0                    // q  [3][49][40]
#define SK_   5880                 // k
#define SV_   11760                // v  [3][32][56] (transposed)
#define XA_   17136                // x / att A-tile [49][104]
#define SREL_ 22232                // rel_pos, 507 floats (1014 units)
#define FUSED_SMEM ((22232 + 1014) * 2)   // 46,492 B
#define QSTR 40
#define VSTR 56
#define XSTR 104

__global__ __launch_bounds__(384, 3) void fused_win(
    const float* __restrict__ x, const float* __restrict__ b_qkv,
    const float* __restrict__ rel_pos, const float* __restrict__ b_out,
    float* __restrict__ out)
{
    extern __shared__ __half sb[];
    float* srel = (float*)(sb + SREL_);

    const int tid = threadIdx.x, lane = tid & 31, warp = tid >> 5;
    const int g = lane >> 2, tg = lane & 3;
    const int mt = warp & 3, third = warp >> 2;          // head / n-chunk
    const int m0 = (mt == 3) ? 33 : mt * 16;
    const int r0 = m0 + g, r1 = m0 + 8 + g;
    const int win = blockIdx.x;                          // ((b*8)+hi)*8+wi
    const int wi = win & 7, hi2 = (win >> 3) & 7, bb2 = win >> 6;

    for (int i = tid; i < 507; i += 384) srel[i] = rel_pos[i];

    // ldmatrix per-lane address components (constant through the kernel)
    const int l15 = lane & 15;                 // row-within-16 selector
    const int cH  = (lane >> 4) << 3;          // +8 halfs for upper col block (A/Q)
    const int rB  = 8 * (lane >> 4) + (lane & 7);  // B x4: tile-pair row
    const int cB  = lane & 8;                  // B: +8 halfs col block

    // A-tile fragments (phases 2 & 4): rows m0+l15, col cH
    const uint32_t aAddr = smem_addr(sb + XA_) + (((m0 + l15) * XSTR + cH) << 1);

    // ---- phase 1: gather x (token map inline), convert to fp16 A-tile ------
    for (int i = tid; i < 49 * 24; i += 384) {
        int t = i / 24, f4 = i % 24;
        int p = t / 7, q = t % 7;
        size_t row = (size_t)(bb2 * 56 + p * 8 + hi2) * 56 + q * 8 + wi;
        float4 v = *(const float4*)(x + row * 96 + f4 * 4);
        uint2 H;
        H.x = pack_f16x2(v.x, v.y);
        H.y = pack_f16x2(v.z, v.w);
        *(uint2*)(sb + XA_ + t * XSTR + f4 * 4) = H;
    }
    __syncthreads();    // A-tile ready

    // ---- phase 2: qkv projection (A via ldmatrix, weights via LDG.64) ------
    for (int c = 0; c < 3; c++) {
        float acc[4][4];
        #pragma unroll
        for (int nt = 0; nt < 4; nt++)
            #pragma unroll
            for (int e = 0; e < 4; e++) acc[nt][e] = 0.f;
        #pragma unroll
        for (int ks = 0; ks < 6; ks++) {
            uint32_t a[4];
            ldsm_x4(a, aAddr + ks * 32);
            const uint2* wbase = g_wfq + ((c * 6 + ks) * 12 + third * 4) * 32 + lane;
            #pragma unroll
            for (int nt = 0; nt < 4; nt++) {
                uint2 wb = wbase[nt * 32];
                uint32_t b[2] = {wb.x, wb.y};
                mma_f16(acc[nt], a, b);
            }
        }
        // writeback: +bias (fp32), quantize to fp16 attention layouts
        if (c < 2) {
            __half* d = sb + (c ? SK_ : SQ_);
            #pragma unroll
            for (int nt = 0; nt < 4; nt++) {
                int col = nt * 8 + 2 * tg;
                float2 bbv = *(const float2*)(b_qkv + c * 96 + third * 32 + col);
                *(uint32_t*)(d + (third * 49 + r0) * QSTR + col) =
                    pack_f16x2(acc[nt][0] + bbv.x, acc[nt][1] + bbv.y);
                *(uint32_t*)(d + (third * 49 + r1) * QSTR + col) =
                    pack_f16x2(acc[nt][2] + bbv.x, acc[nt][3] + bbv.y);
            }
        } else {
            __half* vt = sb + SV_;
            #pragma unroll
            for (int nt = 0; nt < 4; nt++) {
                int dd = nt * 8 + 2 * tg;
                float2 bbv = *(const float2*)(b_qkv + 192 + third * 32 + dd);
                int base0 = (third * 32 + dd) * VSTR, base1 = base0 + VSTR;
                vt[base0 + r0] = __float2half(acc[nt][0] + bbv.x);
                vt[base1 + r0] = __float2half(acc[nt][1] + bbv.y);
                vt[base0 + r1] = __float2half(acc[nt][2] + bbv.x);
                vt[base1 + r1] = __float2half(acc[nt][3] + bbv.y);
            }
        }
    }
    __syncthreads();    // q/k/v + rel ready

    // ---- phase 3: attention (register-resident sim/att, ldmatrix frags) ----
    {
        const int h = third;
        const float scale = 0.17677669529663687f;   // 32^-0.5
        const __half* vt = sb + SV_;

        // Q A-frags: rows m0+l15 of q; K B-frags: pairs of linear n-tiles
        const uint32_t qAddr = smem_addr(sb + SQ_) +
            (((h * 49 + m0 + l15) * QSTR + cH) << 1);
        const uint32_t kAddr = smem_addr(sb + SK_) +
            (((h * 49 + rB) * QSTR + cB) << 1);
        const uint32_t k6Addr = smem_addr(sb + SK_) +
            (((h * 49 + 41 + (lane & 7)) * QSTR + cB) << 1);
        const uint32_t vAddr = smem_addr(sb + SV_) +
            (((h * 32 + rB) * VSTR + cB) << 1);

        float acc[7][4];
        #pragma unroll
        for (int nt = 0; nt < 7; nt++)
            #pragma unroll
            for (int e = 0; e < 4; e++) acc[nt][e] = 0.f;

        #pragma unroll
        for (int ks = 0; ks < 2; ks++) {
            const int off = ks * 32;
            uint32_t a[4];
            ldsm_x4(a, qAddr + off);
            #pragma unroll
            for (int p = 0; p < 3; p++) {       // n-tile pairs (0,1)(2,3)(4,5)
                uint32_t b4[4];
                ldsm_x4(b4, kAddr + p * (16 * QSTR * 2) + off);
                mma_f16(acc[2 * p],     a, b4);
                mma_f16(acc[2 * p + 1], a, b4 + 2);
            }
            uint32_t b2[2];                      // overlap tile (n0 = 41)
            ldsm_x2(b2, k6Addr + off);
            mma_f16(acc[6], a, b2);
        }

        // scale + rel-pos bias (fp32)
        {
            const int n0tab[7] = {0, 8, 16, 24, 32, 40, 41};
            const float* relh = srel + h * 169;
            int pi0 = r0 / 7, qi0 = r0 % 7, pi1 = r1 / 7, qi1 = r1 % 7;
            #pragma unroll
            for (int nt = 0; nt < 7; nt++) {
                int j0 = n0tab[nt] + 2 * tg, j1 = j0 + 1;
                int pj0 = j0 / 7, qj0 = j0 % 7, pj1 = j1 / 7, qj1 = j1 % 7;
                acc[nt][0] = fmaf(acc[nt][0], scale, relh[(pi0 - pj0 + 6) * 13 + (qi0 - qj0 + 6)]);
                acc[nt][1] = fmaf(acc[nt][1], scale, relh[(pi0 - pj1 + 6) * 13 + (qi0 - qj1 + 6)]);
                acc[nt][2] = fmaf(acc[nt][2], scale, relh[(pi1 - pj0 + 6) * 13 + (qi1 - qj0 + 6)]);
                acc[nt][3] = fmaf(acc[nt][3], scale, relh[(pi1 - pj1 + 6) * 13 + (qi1 - qj1 + 6)]);
            }
        }

        // softmax (dup cols of overlap tile excluded from sums)
        float mx0 = -1e30f, mx1 = -1e30f;
        #pragma unroll
        for (int nt = 0; nt < 7; nt++) {
            mx0 = fmaxf(mx0, fmaxf(acc[nt][0], acc[nt][1]));
            mx1 = fmaxf(mx1, fmaxf(acc[nt][2], acc[nt][3]));
        }
        mx0 = fmaxf(mx0, __shfl_xor_sync(0xffffffffu, mx0, 1));
        mx0 = fmaxf(mx0, __shfl_xor_sync(0xffffffffu, mx0, 2));
        mx1 = fmaxf(mx1, __shfl_xor_sync(0xffffffffu, mx1, 1));
        mx1 = fmaxf(mx1, __shfl_xor_sync(0xffffffffu, mx1, 2));
        float s0 = 0.f, s1 = 0.f;
        #pragma unroll
        for (int nt = 0; nt < 6; nt++) {
            acc[nt][0] = __expf(acc[nt][0] - mx0); s0 += acc[nt][0];
            acc[nt][1] = __expf(acc[nt][1] - mx0); s0 += acc[nt][1];
            acc[nt][2] = __expf(acc[nt][2] - mx1); s1 += acc[nt][2];
            acc[nt][3] = __expf(acc[nt][3] - mx1); s1 += acc[nt][3];
        }
        acc[6][0] = __expf(acc[6][0] - mx0);
        acc[6][1] = __expf(acc[6][1] - mx0);
        acc[6][2] = __expf(acc[6][2] - mx1);
        acc[6][3] = __expf(acc[6][3] - mx1);
        if (tg == 3) { s0 += acc[6][1]; s1 += acc[6][3]; }   // col 48 only
        s0 += __shfl_xor_sync(0xffffffffu, s0, 1);
        s0 += __shfl_xor_sync(0xffffffffu, s0, 2);
        s1 += __shfl_xor_sync(0xffffffffu, s1, 1);
        s1 += __shfl_xor_sync(0xffffffffu, s1, 2);
        float inv0 = 1.f / s0, inv1 = 1.f / s1;
        #pragma unroll
        for (int nt = 0; nt < 7; nt++) {
            acc[nt][0] *= inv0; acc[nt][1] *= inv0;
            acc[nt][2] *= inv1; acc[nt][3] *= inv1;
        }

        // out = att @ v : att repacked in-register as fp16 A frags
        float accv[4][4];
        #pragma unroll
        for (int dn = 0; dn < 4; dn++)
            #pragma unroll
            for (int e = 0; e < 4; e++) accv[dn][e] = 0.f;
        #pragma unroll
        for (int ks = 0; ks < 3; ks++) {
            uint32_t a[4];
            float* t0 = acc[2 * ks];
            float* t1 = acc[2 * ks + 1];
            a[0] = pack_f16x2(t0[0], t0[1]);
            a[1] = pack_f16x2(t0[2], t0[3]);
            a[2] = pack_f16x2(t1[0], t1[1]);
            a[3] = pack_f16x2(t1[2], t1[3]);
            #pragma unroll
            for (int p = 0; p < 2; p++) {       // dn pairs (0,1)(2,3)
                uint32_t b4[4];
                ldsm_x4(b4, vAddr + p * (16 * VSTR * 2) + ks * 32);
                mma_f16(accv[2 * p],     a, b4);
                mma_f16(accv[2 * p + 1], a, b4 + 2);
            }
        }
        // j = 48 via shfl + scalar fp32 FMA
        float a48a = __shfl_sync(0xffffffffu, acc[6][1], lane | 3);
        float a48b = __shfl_sync(0xffffffffu, acc[6][3], lane | 3);
        #pragma unroll
        for (int dn = 0; dn < 4; dn++) {
            int d0 = dn * 8 + 2 * tg;
            float v0 = __half2float(vt[(h * 32 + d0) * VSTR + 48]);
            float v1 = __half2float(vt[(h * 32 + d0 + 1) * VSTR + 48]);
            accv[dn][0] += a48a * v0; accv[dn][1] += a48a * v1;
            accv[dn][2] += a48b * v0; accv[dn][3] += a48b * v1;
        }

        // att output -> A-tile (x is dead), fp16 (dup rows store identical)
        #pragma unroll
        for (int dn = 0; dn < 4; dn++) {
            int col = h * 32 + dn * 8 + 2 * tg;
            *(uint32_t*)(sb + XA_ + r0 * XSTR + col) = pack_f16x2(accv[dn][0], accv[dn][1]);
            *(uint32_t*)(sb + XA_ + r1 * XSTR + col) = pack_f16x2(accv[dn][2], accv[dn][3]);
        }
    }
    __syncthreads();    // att A-tile ready

    // ---- phase 4: out projection (A via ldmatrix) --------------------------
    float acc2[4][4];
    #pragma unroll
    for (int nt = 0; nt < 4; nt++)
        #pragma unroll
        for (int e = 0; e < 4; e++) acc2[nt][e] = 0.f;
    #pragma unroll
    for (int ks = 0; ks < 6; ks++) {
        uint32_t a[4];
        ldsm_x4(a, aAddr + ks * 32);
        const uint2* wbase = g_wfo + (ks * 12 + third * 4) * 32 + lane;
        #pragma unroll
        for (int nt = 0; nt < 4; nt++) {
            uint2 wb = wbase[nt * 32];
            uint32_t b[2] = {wb.x, wb.y};
            mma_f16(acc2[nt], a, b);
        }
    }

    // ---- phase 5: staged fp32 epilogue (reuses dead q/k regions) -----------
    float* st = (float*)sb;                  // [49][100] = 19.6 KB < q+k
    __syncthreads();    // all ldmatrix reads of XA_/q/k done before overwrite
    #pragma unroll
    for (int nt = 0; nt < 4; nt++) {
        int col = third * 32 + nt * 8 + 2 * tg;
        float2 bo = *(const float2*)(b_out + col);
        *(float2*)(st + r0 * 100 + col) = make_float2(acc2[nt][0] + bo.x, acc2[nt][1] + bo.y);
        *(float2*)(st + r1 * 100 + col) = make_float2(acc2[nt][2] + bo.x, acc2[nt][3] + bo.y);
    }
    __syncthreads();    // staging visible
    for (int i = tid; i < 49 * 24; i += 384) {
        int t = i / 24, f4 = i % 24;
        int p = t / 7, q = t % 7;
        size_t row = (size_t)(bb2 * 56 + p * 8 + hi2) * 56 + q * 8 + wi;
        *(float4*)(out + row * 96 + f4 * 4) = *(const float4*)(st + t * 100 + f4 * 4);
    }
}

// ---------------- launch ----------------------------------------------------
extern "C" void kernel_launch(void* const* d_in, const int* in_sizes, int n_in,
                              void* d_out, int out_size)
{
    (void)in_sizes; (void)n_in; (void)out_size;
    const float* x     = (const float*)d_in[0];
    const float* w_qkv = (const float*)d_in[1];
    const float* b_qkv = (const float*)d_in[2];
    const float* rel   = (const float*)d_in[3];
    const float* w_out = (const float*)d_in[4];
    const float* b_out = (const float*)d_in[5];
    float* out = (float*)d_out;

    cudaFuncSetAttribute(fused_win, cudaFuncAttributeMaxDynamicSharedMemorySize, FUSED_SMEM);

    // 0) fragment-pack weights to fp16
    split_w<<<(6912 + 2304 + 255) / 256, 256>>>(w_qkv, w_out);

    // 1) fused qkv + attention + out-projection; 3 blocks/SM
    fused_win<<<4096, 384, FUSED_SMEM>>>(x, b_qkv, rel, b_out, out);
}

// round 17
// speedup vs baseline: 6.2581x; 1.0357x over previous
#include <cuda_runtime.h>
#include <cuda_fp16.h>
#include <cstdint>

#define QKV_N 288

// ---------------- scratch: fragment-packed fp16 weights --------------------
// qkv: [c(3)][ks(6)][third(3)][nt(4)][lane(32)] -> uint2 {b(k,k+1), b(k+8,k+9)}
__device__ uint2 g_wfq[3 * 6 * 12 * 32];   // 55.3 KB
__device__ uint2 g_wfo[6 * 12 * 32];       // 18.4 KB

__device__ __forceinline__ void mma_f16(float* c, const uint32_t* a, const uint32_t* b) {
    asm("mma.sync.aligned.m16n8k16.row.col.f32.f16.f16.f32 "
        "{%0,%1,%2,%3}, {%4,%5,%6,%7}, {%8,%9}, {%0,%1,%2,%3};"
        : "+f"(c[0]), "+f"(c[1]), "+f"(c[2]), "+f"(c[3])
        : "r"(a[0]), "r"(a[1]), "r"(a[2]), "r"(a[3]), "r"(b[0]), "r"(b[1]));
}
__device__ __forceinline__ uint32_t pack_f16x2(float lo, float hi) {
    uint32_t r;
    asm("cvt.rn.f16x2.f32 %0, %1, %2;" : "=r"(r) : "f"(hi), "f"(lo));
    return r;
}
__device__ __forceinline__ uint32_t smem_addr(const void* p) {
    return (uint32_t)__cvta_generic_to_shared(p);
}
__device__ __forceinline__ void ldsm_x4(uint32_t* r, uint32_t a) {
    asm volatile("ldmatrix.sync.aligned.m8n8.x4.shared.b16 {%0,%1,%2,%3}, [%4];"
        : "=r"(r[0]), "=r"(r[1]), "=r"(r[2]), "=r"(r[3]) : "r"(a));
}
__device__ __forceinline__ void ldsm_x2(uint32_t* r, uint32_t a) {
    asm volatile("ldmatrix.sync.aligned.m8n8.x2.shared.b16 {%0,%1}, [%2];"
        : "=r"(r[0]), "=r"(r[1]) : "r"(a));
}
#define BAR_SYNC(id, n) asm volatile("bar.sync %0, %1;" :: "r"(id), "r"(n) : "memory")

// ---------------- prep: fragment-pack weights to fp16 ----------------------
__global__ void split_w(const float* __restrict__ wqkv, const float* __restrict__ wout) {
    int idx = blockIdx.x * 256 + threadIdx.x;
    if (idx >= 6912 + 2304) return;
    float f0, f1, f8, f9;
    uint2* dst;
    if (idx < 6912) {
        int lane = idx & 31, tile = idx >> 5;
        int tg = lane & 3, g = lane >> 2;
        int nt = tile % 4, third = (tile / 4) % 3, ks = (tile / 12) % 6, c = tile / 72;
        int n = c * 96 + third * 32 + nt * 8 + g;
        int kb = ks * 16 + 2 * tg;
        f0 = wqkv[(kb + 0) * QKV_N + n];
        f1 = wqkv[(kb + 1) * QKV_N + n];
        f8 = wqkv[(kb + 8) * QKV_N + n];
        f9 = wqkv[(kb + 9) * QKV_N + n];
        dst = &g_wfq[idx];
    } else {
        int j = idx - 6912;
        int lane = j & 31, tile = j >> 5;
        int tg = lane & 3, g = lane >> 2;
        int nt = tile % 4, third = (tile / 4) % 3, ks = tile / 12;
        int n = third * 32 + nt * 8 + g;
        int kb = ks * 16 + 2 * tg;
        f0 = wout[(kb + 0) * 96 + n];
        f1 = wout[(kb + 1) * 96 + n];
        f8 = wout[(kb + 8) * 96 + n];
        f9 = wout[(kb + 9) * 96 + n];
        dst = &g_wfo[j];
    }
    uint2 wb;
    wb.x = pack_f16x2(f0, f1);
    wb.y = pack_f16x2(f8, f9);
    *dst = wb;
}

// ---------------- fused per-window kernel (fp16, 4 blocks/SM) ---------------
// One block = one window, 384 threads = 12 warps = (m-tile 0..3) x (third 0..2).
// smem 46.5KB -> 4 blocks/SM (launch_bounds forces regs <= 42).
// Named barriers: post-phase2 sync is per-third group (warps {4h..4h+3}
// produce AND consume head h's q/k/v); post-phase3 is per-mt group (warps
// {mt, mt+4, mt+8} produce the XA rows that phase 4's mt reads).
// smem offsets in fp16 units:
#define SQ_   0                    // q  [3][49][40]
#define SK_   5880                 // k
#define SV_   11760                // v  [3][32][56] (transposed)
#define XA_   17136                // x / att A-tile [49][104]
#define SREL_ 22232                // rel_pos, 507 floats (1014 units)
#define FUSED_SMEM ((22232 + 1014) * 2)   // 46,492 B
#define QSTR 40
#define VSTR 56
#define XSTR 104

__global__ __launch_bounds__(384, 4) void fused_win(
    const float* __restrict__ x, const float* __restrict__ b_qkv,
    const float* __restrict__ rel_pos, const float* __restrict__ b_out,
    float* __restrict__ out)
{
    extern __shared__ __half sb[];
    float* srel = (float*)(sb + SREL_);

    const int tid = threadIdx.x, lane = tid & 31, warp = tid >> 5;
    const int g = lane >> 2, tg = lane & 3;
    const int mt = warp & 3, third = warp >> 2;          // head / n-chunk
    const int m0 = (mt == 3) ? 33 : mt * 16;
    const int r0 = m0 + g, r1 = m0 + 8 + g;
    const int win = blockIdx.x;                          // ((b*8)+hi)*8+wi
    const int wi = win & 7, hi2 = (win >> 3) & 7, bb2 = win >> 6;

    for (int i = tid; i < 507; i += 384) srel[i] = rel_pos[i];

    // ldmatrix per-lane address components
    const int l15 = lane & 15;
    const int cH  = (lane >> 4) << 3;
    const int rB  = 8 * (lane >> 4) + (lane & 7);
    const int cB  = lane & 8;
    const uint32_t aAddr = smem_addr(sb + XA_) + (((m0 + l15) * XSTR + cH) << 1);

    // ---- phase 1: gather x (token map inline), convert to fp16 A-tile ------
    for (int i = tid; i < 49 * 24; i += 384) {
        int t = i / 24, f4 = i % 24;
        int p = t / 7, q = t % 7;
        size_t row = (size_t)(bb2 * 56 + p * 8 + hi2) * 56 + q * 8 + wi;
        float4 v = *(const float4*)(x + row * 96 + f4 * 4);
        uint2 H;
        H.x = pack_f16x2(v.x, v.y);
        H.y = pack_f16x2(v.z, v.w);
        *(uint2*)(sb + XA_ + t * XSTR + f4 * 4) = H;
    }
    __syncthreads();    // A-tile + srel ready (full: XA read by all groups)

    // ---- phase 2: qkv projection (A via ldmatrix, weights via LDG.64) ------
    for (int c = 0; c < 3; c++) {
        float acc[4][4];
        #pragma unroll
        for (int nt = 0; nt < 4; nt++)
            #pragma unroll
            for (int e = 0; e < 4; e++) acc[nt][e] = 0.f;
        #pragma unroll
        for (int ks = 0; ks < 6; ks++) {
            uint32_t a[4];
            ldsm_x4(a, aAddr + ks * 32);
            const uint2* wbase = g_wfq + ((c * 6 + ks) * 12 + third * 4) * 32 + lane;
            #pragma unroll
            for (int nt = 0; nt < 4; nt++) {
                uint2 wb = wbase[nt * 32];
                uint32_t b[2] = {wb.x, wb.y};
                mma_f16(acc[nt], a, b);
            }
        }
        // writeback: +bias (fp32), quantize to fp16 attention layouts
        if (c < 2) {
            __half* d = sb + (c ? SK_ : SQ_);
            #pragma unroll
            for (int nt = 0; nt < 4; nt++) {
                int col = nt * 8 + 2 * tg;
                float2 bbv = *(const float2*)(b_qkv + c * 96 + third * 32 + col);
                *(uint32_t*)(d + (third * 49 + r0) * QSTR + col) =
                    pack_f16x2(acc[nt][0] + bbv.x, acc[nt][1] + bbv.y);
                *(uint32_t*)(d + (third * 49 + r1) * QSTR + col) =
                    pack_f16x2(acc[nt][2] + bbv.x, acc[nt][3] + bbv.y);
            }
        } else {
            __half* vt = sb + SV_;
            #pragma unroll
            for (int nt = 0; nt < 4; nt++) {
                int dd = nt * 8 + 2 * tg;
                float2 bbv = *(const float2*)(b_qkv + 192 + third * 32 + dd);
                int base0 = (third * 32 + dd) * VSTR, base1 = base0 + VSTR;
                vt[base0 + r0] = __float2half(acc[nt][0] + bbv.x);
                vt[base1 + r0] = __float2half(acc[nt][1] + bbv.y);
                vt[base0 + r1] = __float2half(acc[nt][2] + bbv.x);
                vt[base1 + r1] = __float2half(acc[nt][3] + bbv.y);
            }
        }
    }
    BAR_SYNC(1 + third, 128);   // head group: its q/k/v complete

    // ---- phase 3: attention (register-resident sim/att, ldmatrix frags) ----
    {
        const int h = third;
        const float scale = 0.17677669529663687f;   // 32^-0.5
        const __half* vt = sb + SV_;

        const uint32_t qAddr = smem_addr(sb + SQ_) +
            (((h * 49 + m0 + l15) * QSTR + cH) << 1);
        const uint32_t kAddr = smem_addr(sb + SK_) +
            (((h * 49 + rB) * QSTR + cB) << 1);
        const uint32_t k6Addr = smem_addr(sb + SK_) +
            (((h * 49 + 41 + (lane & 7)) * QSTR + cB) << 1);
        const uint32_t vAddr = smem_addr(sb + SV_) +
            (((h * 32 + rB) * VSTR + cB) << 1);

        float acc[7][4];
        #pragma unroll
        for (int nt = 0; nt < 7; nt++)
            #pragma unroll
            for (int e = 0; e < 4; e++) acc[nt][e] = 0.f;

        #pragma unroll
        for (int ks = 0; ks < 2; ks++) {
            const int off = ks * 32;
            uint32_t a[4];
            ldsm_x4(a, qAddr + off);
            #pragma unroll
            for (int p = 0; p < 3; p++) {       // n-tile pairs (0,1)(2,3)(4,5)
                uint32_t b4[4];
                ldsm_x4(b4, kAddr + p * (16 * QSTR * 2) + off);
                mma_f16(acc[2 * p],     a, b4);
                mma_f16(acc[2 * p + 1], a, b4 + 2);
            }
            uint32_t b2[2];                      // overlap tile (n0 = 41)
            ldsm_x2(b2, k6Addr + off);
            mma_f16(acc[6], a, b2);
        }

        // scale + rel-pos bias (fp32)
        {
            const int n0tab[7] = {0, 8, 16, 24, 32, 40, 41};
            const float* relh = srel + h * 169;
            int pi0 = r0 / 7, qi0 = r0 % 7, pi1 = r1 / 7, qi1 = r1 % 7;
            #pragma unroll
            for (int nt = 0; nt < 7; nt++) {
                int j0 = n0tab[nt] + 2 * tg, j1 = j0 + 1;
                int pj0 = j0 / 7, qj0 = j0 % 7, pj1 = j1 / 7, qj1 = j1 % 7;
                acc[nt][0] = fmaf(acc[nt][0], scale, relh[(pi0 - pj0 + 6) * 13 + (qi0 - qj0 + 6)]);
                acc[nt][1] = fmaf(acc[nt][1], scale, relh[(pi0 - pj1 + 6) * 13 + (qi0 - qj1 + 6)]);
                acc[nt][2] = fmaf(acc[nt][2], scale, relh[(pi1 - pj0 + 6) * 13 + (qi1 - qj0 + 6)]);
                acc[nt][3] = fmaf(acc[nt][3], scale, relh[(pi1 - pj1 + 6) * 13 + (qi1 - qj1 + 6)]);
            }
        }

        // softmax (dup cols of overlap tile excluded from sums)
        float mx0 = -1e30f, mx1 = -1e30f;
        #pragma unroll
        for (int nt = 0; nt < 7; nt++) {
            mx0 = fmaxf(mx0, fmaxf(acc[nt][0], acc[nt][1]));
            mx1 = fmaxf(mx1, fmaxf(acc[nt][2], acc[nt][3]));
        }
        mx0 = fmaxf(mx0, __shfl_xor_sync(0xffffffffu, mx0, 1));
        mx0 = fmaxf(mx0, __shfl_xor_sync(0xffffffffu, mx0, 2));
        mx1 = fmaxf(mx1, __shfl_xor_sync(0xffffffffu, mx1, 1));
        mx1 = fmaxf(mx1, __shfl_xor_sync(0xffffffffu, mx1, 2));
        float s0 = 0.f, s1 = 0.f;
        #pragma unroll
        for (int nt = 0; nt < 6; nt++) {
            acc[nt][0] = __expf(acc[nt][0] - mx0); s0 += acc[nt][0];
            acc[nt][1] = __expf(acc[nt][1] - mx0); s0 += acc[nt][1];
            acc[nt][2] = __expf(acc[nt][2] - mx1); s1 += acc[nt][2];
            acc[nt][3] = __expf(acc[nt][3] - mx1); s1 += acc[nt][3];
        }
        acc[6][0] = __expf(acc[6][0] - mx0);
        acc[6][1] = __expf(acc[6][1] - mx0);
        acc[6][2] = __expf(acc[6][2] - mx1);
        acc[6][3] = __expf(acc[6][3] - mx1);
        if (tg == 3) { s0 += acc[6][1]; s1 += acc[6][3]; }   // col 48 only
        s0 += __shfl_xor_sync(0xffffffffu, s0, 1);
        s0 += __shfl_xor_sync(0xffffffffu, s0, 2);
        s1 += __shfl_xor_sync(0xffffffffu, s1, 1);
        s1 += __shfl_xor_sync(0xffffffffu, s1, 2);
        float inv0 = 1.f / s0, inv1 = 1.f / s1;
        #pragma unroll
        for (int nt = 0; nt < 7; nt++) {
            acc[nt][0] *= inv0; acc[nt][1] *= inv0;
            acc[nt][2] *= inv1; acc[nt][3] *= inv1;
        }

        // out = att @ v : att repacked in-register as fp16 A frags
        float accv[4][4];
        #pragma unroll
        for (int dn = 0; dn < 4; dn++)
            #pragma unroll
            for (int e = 0; e < 4; e++) accv[dn][e] = 0.f;
        #pragma unroll
        for (int ks = 0; ks < 3; ks++) {
            uint32_t a[4];
            float* t0 = acc[2 * ks];
            float* t1 = acc[2 * ks + 1];
            a[0] = pack_f16x2(t0[0], t0[1]);
            a[1] = pack_f16x2(t0[2], t0[3]);
            a[2] = pack_f16x2(t1[0], t1[1]);
            a[3] = pack_f16x2(t1[2], t1[3]);
            #pragma unroll
            for (int p = 0; p < 2; p++) {       // dn pairs (0,1)(2,3)
                uint32_t b4[4];
                ldsm_x4(b4, vAddr + p * (16 * VSTR * 2) + ks * 32);
                mma_f16(accv[2 * p],     a, b4);
                mma_f16(accv[2 * p + 1], a, b4 + 2);
            }
        }
        // j = 48 via shfl + scalar fp32 FMA
        float a48a = __shfl_sync(0xffffffffu, acc[6][1], lane | 3);
        float a48b = __shfl_sync(0xffffffffu, acc[6][3], lane | 3);
        #pragma unroll
        for (int dn = 0; dn < 4; dn++) {
            int d0 = dn * 8 + 2 * tg;
            float v0 = __half2float(vt[(h * 32 + d0) * VSTR + 48]);
            float v1 = __half2float(vt[(h * 32 + d0 + 1) * VSTR + 48]);
            accv[dn][0] += a48a * v0; accv[dn][1] += a48a * v1;
            accv[dn][2] += a48b * v0; accv[dn][3] += a48b * v1;
        }

        // att output -> A-tile (x is dead), fp16 (dup rows store identical)
        #pragma unroll
        for (int dn = 0; dn < 4; dn++) {
            int col = h * 32 + dn * 8 + 2 * tg;
            *(uint32_t*)(sb + XA_ + r0 * XSTR + col) = pack_f16x2(accv[dn][0], accv[dn][1]);
            *(uint32_t*)(sb + XA_ + r1 * XSTR + col) = pack_f16x2(accv[dn][2], accv[dn][3]);
        }
    }
    BAR_SYNC(5 + mt, 96);   // mt group: XA rows for this m-tile complete

    // ---- phase 4: out projection (A via ldmatrix) --------------------------
    float acc2[4][4];
    #pragma unroll
    for (int nt = 0; nt < 4; nt++)
        #pragma unroll
        for (int e = 0; e < 4; e++) acc2[nt][e] = 0.f;
    #pragma unroll
    for (int ks = 0; ks < 6; ks++) {
        uint32_t a[4];
        ldsm_x4(a, aAddr + ks * 32);
        const uint2* wbase = g_wfo + (ks * 12 + third * 4) * 32 + lane;
        #pragma unroll
        for (int nt = 0; nt < 4; nt++) {
            uint2 wb = wbase[nt * 32];
            uint32_t b[2] = {wb.x, wb.y};
            mma_f16(acc2[nt], a, b);
        }
    }

    // ---- phase 5: staged fp32 epilogue (reuses dead q/k regions) -----------
    float* st = (float*)sb;                  // [49][100] = 19.6 KB < q+k
    __syncthreads();    // FULL: staging overwrites q/k read by other groups
    #pragma unroll
    for (int nt = 0; nt < 4; nt++) {
        int col = third * 32 + nt * 8 + 2 * tg;
        float2 bo = *(const float2*)(b_out + col);
        *(float2*)(st + r0 * 100 + col) = make_float2(acc2[nt][0] + bo.x, acc2[nt][1] + bo.y);
        *(float2*)(st + r1 * 100 + col) = make_float2(acc2[nt][2] + bo.x, acc2[nt][3] + bo.y);
    }
    __syncthreads();    // staging visible
    for (int i = tid; i < 49 * 24; i += 384) {
        int t = i / 24, f4 = i % 24;
        int p = t / 7, q = t % 7;
        size_t row = (size_t)(bb2 * 56 + p * 8 + hi2) * 56 + q * 8 + wi;
        *(float4*)(out + row * 96 + f4 * 4) = *(const float4*)(st + t * 100 + f4 * 4);
    }
}

// ---------------- launch ----------------------------------------------------
extern "C" void kernel_launch(void* const* d_in, const int* in_sizes, int n_in,
                              void* d_out, int out_size)
{
    (void)in_sizes; (void)n_in; (void)out_size;
    const float* x     = (const float*)d_in[0];
    const float* w_qkv = (const float*)d_in[1];
    const float* b_qkv = (const float*)d_in[2];
    const float* rel   = (const float*)d_in[3];
    const float* w_out = (const float*)d_in[4];
    const float* b_out = (const float*)d_in[5];
    float* out = (float*)d_out;

    cudaFuncSetAttribute(fused_win, cudaFuncAttributeMaxDynamicSharedMemorySize, FUSED_SMEM);

    // 0) fragment-pack weights to fp16
    split_w<<<(6912 + 2304 + 255) / 256, 256>>>(w_qkv, w_out);

    // 1) fused qkv + attention + out-projection; 4 blocks/SM, named barriers
    fused_win<<<4096, 384, FUSED_SMEM>>>(x, b_qkv, rel, b_out, out);
}